// round 6
// baseline (speedup 1.0000x reference)
#include <cuda_runtime.h>
#include <cuda_bf16.h>
#include <cstdint>
#include <math.h>

#define NROWS 65536
#define DD    512
#define KSPLIT 32
#define KCHUNK (NROWS / KSPLIT)   // 2048
#define NS_ITERS 10
#define INV_TEMP 0.1f

// ---------------------------------------------------------------------------
// Static device scratch
// ---------------------------------------------------------------------------
__device__ float g_covp[(size_t)KSPLIT * DD * DD];   // 32 MB
__device__ float g_G[DD * DD];
__device__ float g_S[DD * DD];
__device__ float g_P[DD * DD];
__device__ float g_Pn[DD * DD];
__device__ float g_colp[DD * 512];                   // TRANSPOSED: [col][rowblock]
__device__ float g_mean[DD];
__device__ float g_mc[DD];
__device__ float g_scalars[4];
__device__ __nv_bfloat16 g_Ah[(size_t)NROWS * DD];
__device__ __nv_bfloat16 g_Al[(size_t)NROWS * DD];
__device__ __nv_bfloat16 g_Hh[(size_t)NROWS * DD];
__device__ __nv_bfloat16 g_Hl[(size_t)NROWS * DD];
__device__ __nv_bfloat16 g_Wh[DD * DD];
__device__ __nv_bfloat16 g_Wl[DD * DD];
__device__ __nv_bfloat16 g_Sh[DD * DD], g_Sl[DD * DD];
__device__ __nv_bfloat16 g_Pah[DD * DD], g_Pal[DD * DD];
__device__ __nv_bfloat16 g_Pbh[DD * DD], g_Pbl[DD * DD];
__device__ __nv_bfloat16 g_T1h[DD * DD], g_T1l[DD * DD];
__device__ __nv_bfloat16 g_T2h[DD * DD], g_T2l[DD * DD];

// ---------------------------------------------------------------------------
// PTX helpers
// ---------------------------------------------------------------------------
__device__ __forceinline__ uint32_t smem_u32(const void* p) {
    uint32_t a;
    asm("{ .reg .u64 t; cvta.to.shared.u64 t, %1; cvt.u32.u64 %0, t; }"
        : "=r"(a) : "l"(p));
    return a;
}
__device__ __forceinline__ void cpa16(uint32_t dst, const void* src) {
    asm volatile("cp.async.cg.shared.global [%0], [%1], 16;"
                 :: "r"(dst), "l"(src) : "memory");
}
#define CP_COMMIT() asm volatile("cp.async.commit_group;" ::: "memory")
#define CP_WAIT0()  asm volatile("cp.async.wait_group 0;" ::: "memory")

__device__ __forceinline__ void ldsm4(uint32_t* r, uint32_t a) {
    asm volatile("ldmatrix.sync.aligned.m8n8.x4.shared.b16 {%0,%1,%2,%3}, [%4];"
        : "=r"(r[0]), "=r"(r[1]), "=r"(r[2]), "=r"(r[3]) : "r"(a));
}
__device__ __forceinline__ void ldsm4t(uint32_t* r, uint32_t a) {
    asm volatile("ldmatrix.sync.aligned.m8n8.x4.trans.shared.b16 {%0,%1,%2,%3}, [%4];"
        : "=r"(r[0]), "=r"(r[1]), "=r"(r[2]), "=r"(r[3]) : "r"(a));
}
__device__ __forceinline__ void mma_bf16(float* d, const uint32_t* a, const uint32_t* b) {
    asm volatile("mma.sync.aligned.m16n8k16.row.col.f32.bf16.bf16.f32 "
        "{%0,%1,%2,%3}, {%4,%5,%6,%7}, {%8,%9}, {%0,%1,%2,%3};"
        : "+f"(d[0]), "+f"(d[1]), "+f"(d[2]), "+f"(d[3])
        : "r"(a[0]), "r"(a[1]), "r"(a[2]), "r"(a[3]), "r"(b[0]), "r"(b[1]));
}

__device__ __forceinline__ void split1(float v, __nv_bfloat16& h, __nv_bfloat16& l) {
    h = __float2bfloat16_rn(v);
    l = __float2bfloat16_rn(v - __bfloat162float(h));
}
__device__ __forceinline__ void store_split1(__nv_bfloat16* Xh, __nv_bfloat16* Xl,
                                             size_t off, float v) {
    split1(v, Xh[off], Xl[off]);
}
__device__ __forceinline__ void store_split2(__nv_bfloat16* Xh, __nv_bfloat16* Xl,
                                             size_t off, float a, float b) {
    __nv_bfloat16 ha, la, hb, lb;
    split1(a, ha, la);
    split1(b, hb, lb);
    *(uint32_t*)(Xh + off) =
        ((uint32_t)__bfloat16_as_ushort(hb) << 16) | __bfloat16_as_ushort(ha);
    *(uint32_t*)(Xl + off) =
        ((uint32_t)__bfloat16_as_ushort(lb) << 16) | __bfloat16_as_ushort(la);
}

__global__ void split_f32(const float* __restrict__ X,
                          __nv_bfloat16* __restrict__ Xh, __nv_bfloat16* __restrict__ Xl)
{
    const size_t i = ((size_t)blockIdx.x * blockDim.x + threadIdx.x) * 4;
    float4 v = *(const float4*)(X + i);
    __nv_bfloat16 h[4], l[4];
    split1(v.x, h[0], l[0]); split1(v.y, h[1], l[1]);
    split1(v.z, h[2], l[2]); split1(v.w, h[3], l[3]);
    *(uint64_t*)(Xh + i) = *(const uint64_t*)h;
    *(uint64_t*)(Xl + i) = *(const uint64_t*)l;
}

// ---------------------------------------------------------------------------
// Big GEMM via mma.sync (bf16 3-term emulation), 2-stage cp.async pipeline.
// MODE 0: write split(acc) to Ch/Cl + per-rowblock column sums (transposed colp)
// MODE 1: write fp32 acc*s2 - mc[col] to Cf32 AND split of it to Ch/Cl.
// ---------------------------------------------------------------------------
#define LDA 80
#define LDB 272
#define A_TILE (128 * LDA)
#define B_TILE (32 * LDB)
#define G1_STAGE (2 * A_TILE + 2 * B_TILE)   // 37888
#define G1_SMEM (2 * G1_STAGE)               // 75776

template<int MODE>
__global__ void __launch_bounds__(256)
hgemm(const __nv_bfloat16* __restrict__ Ah, const __nv_bfloat16* __restrict__ Al,
      const __nv_bfloat16* __restrict__ Bh, const __nv_bfloat16* __restrict__ Bl,
      float* __restrict__ Cf32,
      __nv_bfloat16* __restrict__ Ch, __nv_bfloat16* __restrict__ Cl,
      const float* __restrict__ scalars, const float* __restrict__ mc,
      float* __restrict__ colp)
{
    extern __shared__ __align__(16) char smem[];
    const uint32_t sb = smem_u32(smem);
    const int tid = threadIdx.x;
    const int lane = tid & 31;
    const int wid = tid >> 5;
    const int m0 = blockIdx.y * 128;
    const int n0 = blockIdx.x * 128;
    const int wm = (wid & 1) * 64;
    const int wn = (wid >> 1) * 32;

    float acc[4][4][4] = {};

    auto loadStage = [&](int c, int s) {
        const uint32_t base = sb + s * G1_STAGE;
        const int k0 = c * 32;
#pragma unroll
        for (int rep = 0; rep < 4; rep++) {
            const int idx = rep * 256 + tid;
            const int half = idx >> 9, r = (idx >> 2) & 127, ch = idx & 3;
            const __nv_bfloat16* src =
                (half ? Al : Ah) + (size_t)(m0 + r) * DD + k0 + ch * 8;
            cpa16(base + half * A_TILE + r * LDA + ch * 16, src);
        }
#pragma unroll
        for (int rep = 0; rep < 4; rep++) {
            const int idx = rep * 256 + tid;
            const int half = idx >> 9, r = (idx >> 4) & 31, ch = idx & 15;
            const __nv_bfloat16* src =
                (half ? Bl : Bh) + (size_t)(k0 + r) * DD + n0 + ch * 8;
            cpa16(base + 2 * A_TILE + half * B_TILE + r * LDB + ch * 16, src);
        }
        CP_COMMIT();
    };

    const int NC = DD / 32;
    loadStage(0, 0);

    for (int c = 0; c < NC; c++) {
        CP_WAIT0();
        __syncthreads();
        if (c + 1 < NC) loadStage(c + 1, (c + 1) & 1);
        const uint32_t st = sb + (c & 1) * G1_STAGE;

#pragma unroll
        for (int ks = 0; ks < 2; ks++) {
            uint32_t ah[4][4], al[4][4];
            const uint32_t abase = st + (lane & 15) * LDA + ks * 32 + (lane >> 4) * 16;
#pragma unroll
            for (int mt = 0; mt < 4; mt++) {
                ldsm4(ah[mt], abase + (wm + mt * 16) * LDA);
                ldsm4(al[mt], abase + A_TILE + (wm + mt * 16) * LDA);
            }
            const uint32_t brow = ks * 16 + (lane & 7) + ((lane >> 3) & 1) * 8;
            const uint32_t bbase = st + 2 * A_TILE + brow * LDB + wn * 2 + (lane >> 4) * 16;
            uint32_t bh[2][4], bl[2][4];
            ldsm4t(bh[0], bbase);
            ldsm4t(bh[1], bbase + 32);
            ldsm4t(bl[0], bbase + B_TILE);
            ldsm4t(bl[1], bbase + B_TILE + 32);

#pragma unroll
            for (int mt = 0; mt < 4; mt++)
#pragma unroll
                for (int nt = 0; nt < 4; nt++) {
                    const uint32_t* ph = &bh[nt >> 1][(nt & 1) * 2];
                    const uint32_t* pl = &bl[nt >> 1][(nt & 1) * 2];
                    mma_bf16(acc[mt][nt], ah[mt], ph);
                    mma_bf16(acc[mt][nt], ah[mt], pl);
                    mma_bf16(acc[mt][nt], al[mt], ph);
                }
        }
    }

    const float s2 = (MODE == 1) ? scalars[2] : 1.0f;
    const int g = lane >> 2, t4 = lane & 3;
#pragma unroll
    for (int mt = 0; mt < 4; mt++) {
        const int r0 = m0 + wm + mt * 16 + g;
#pragma unroll
        for (int nt = 0; nt < 4; nt++) {
            const int cc = n0 + wn + nt * 8 + 2 * t4;
            float v0 = acc[mt][nt][0], v1 = acc[mt][nt][1];
            float v2 = acc[mt][nt][2], v3 = acc[mt][nt][3];
            if (MODE == 1) {
                const float2 m2 = *(const float2*)&mc[cc];
                v0 = v0 * s2 - m2.x; v1 = v1 * s2 - m2.y;
                v2 = v2 * s2 - m2.x; v3 = v3 * s2 - m2.y;
                *(float2*)&Cf32[(size_t)r0 * DD + cc] = make_float2(v0, v1);
                *(float2*)&Cf32[(size_t)(r0 + 8) * DD + cc] = make_float2(v2, v3);
            }
            store_split2(Ch, Cl, (size_t)r0 * DD + cc, v0, v1);
            store_split2(Ch, Cl, (size_t)(r0 + 8) * DD + cc, v2, v3);
        }
    }

    if (MODE == 0) {
        // fused column sums over this block's 128 rows; colp is [col][rowblock]
        float cs[4][2];
#pragma unroll
        for (int nt = 0; nt < 4; nt++) {
            cs[nt][0] = 0.0f; cs[nt][1] = 0.0f;
#pragma unroll
            for (int mt = 0; mt < 4; mt++) {
                cs[nt][0] += acc[mt][nt][0] + acc[mt][nt][2];
                cs[nt][1] += acc[mt][nt][1] + acc[mt][nt][3];
            }
        }
#pragma unroll
        for (int off = 4; off <= 16; off <<= 1)
#pragma unroll
            for (int nt = 0; nt < 4; nt++) {
                cs[nt][0] += __shfl_xor_sync(0xffffffffu, cs[nt][0], off);
                cs[nt][1] += __shfl_xor_sync(0xffffffffu, cs[nt][1], off);
            }
        float* smcs = (float*)smem;
        __syncthreads();
        if ((wid & 1) == 0 && g == 0) {
#pragma unroll
            for (int nt = 0; nt < 4; nt++) {
                const int c0 = wn + nt * 8 + 2 * t4;
                smcs[c0] = cs[nt][0];
                smcs[c0 + 1] = cs[nt][1];
            }
        }
        __syncthreads();
        if ((wid & 1) == 1 && g == 0) {
#pragma unroll
            for (int nt = 0; nt < 4; nt++) {
                const int c0 = wn + nt * 8 + 2 * t4;
                colp[(size_t)(n0 + c0) * 512 + blockIdx.y] = smcs[c0] + cs[nt][0];
                colp[(size_t)(n0 + c0 + 1) * 512 + blockIdx.y] = smcs[c0 + 1] + cs[nt][1];
            }
        }
    }
}

// ---------------------------------------------------------------------------
// Covariance split-K (upper-triangle tiles): 2-stage pipeline
// ---------------------------------------------------------------------------
#define CV_STAGE (4 * B_TILE)      // 34816
#define CV_SMEM (2 * CV_STAGE)     // 69632

__global__ void __launch_bounds__(256)
hcov(const __nv_bfloat16* __restrict__ Hh, const __nv_bfloat16* __restrict__ Hl,
     float* __restrict__ Cp)
{
    extern __shared__ __align__(16) char smem[];
    const uint32_t sb = smem_u32(smem);
    const int tid = threadIdx.x;
    const int lane = tid & 31;
    const int wid = tid >> 5;
    const int bx = blockIdx.x;
    const int bi = (bx < 4) ? 0 : (bx < 7) ? 1 : (bx < 9) ? 2 : 3;
    const int bj = bx - ((bi == 0) ? 0 : (bi == 1) ? 3 : (bi == 2) ? 5 : 6);
    const int i0 = bi * 128;
    const int j0 = bj * 128;
    const int z  = blockIdx.z;
    const int wm = (wid & 1) * 64;
    const int wn = (wid >> 1) * 32;

    float acc[4][4][4] = {};

    auto loadStage = [&](int c, int s) {
        const uint32_t base = sb + s * CV_STAGE;
        const int nbase = z * KCHUNK + c * 32;
#pragma unroll
        for (int rep = 0; rep < 8; rep++) {
            const int idx = rep * 256 + tid;
            const int tile = idx >> 9;
            const int r = (idx >> 4) & 31, ch = idx & 15;
            const __nv_bfloat16* basep = (tile & 1) ? Hl : Hh;
            const int coff = (tile < 2) ? i0 : j0;
            const __nv_bfloat16* src = basep + (size_t)(nbase + r) * DD + coff + ch * 8;
            cpa16(base + tile * B_TILE + r * LDB + ch * 16, src);
        }
        CP_COMMIT();
    };

    const int NC = KCHUNK / 32;
    loadStage(0, 0);

    for (int c = 0; c < NC; c++) {
        CP_WAIT0();
        __syncthreads();
        if (c + 1 < NC) loadStage(c + 1, (c + 1) & 1);
        const uint32_t st = sb + (c & 1) * CV_STAGE;

#pragma unroll
        for (int ks = 0; ks < 2; ks++) {
            const uint32_t arow = ks * 16 + (lane & 7) + ((lane >> 4) & 1) * 8;
            const uint32_t abase = st + arow * LDB + wm * 2 + ((lane >> 3) & 1) * 16;
            uint32_t ah[4][4], al[4][4];
#pragma unroll
            for (int mt = 0; mt < 4; mt++) {
                ldsm4t(ah[mt], abase + mt * 32);
                ldsm4t(al[mt], abase + B_TILE + mt * 32);
            }
            const uint32_t brow = ks * 16 + (lane & 7) + ((lane >> 3) & 1) * 8;
            const uint32_t bbase = st + 2 * B_TILE + brow * LDB + wn * 2 + (lane >> 4) * 16;
            uint32_t bh[2][4], bl[2][4];
            ldsm4t(bh[0], bbase);
            ldsm4t(bh[1], bbase + 32);
            ldsm4t(bl[0], bbase + B_TILE);
            ldsm4t(bl[1], bbase + B_TILE + 32);

#pragma unroll
            for (int mt = 0; mt < 4; mt++)
#pragma unroll
                for (int nt = 0; nt < 4; nt++) {
                    const uint32_t* ph = &bh[nt >> 1][(nt & 1) * 2];
                    const uint32_t* pl = &bl[nt >> 1][(nt & 1) * 2];
                    mma_bf16(acc[mt][nt], ah[mt], ph);
                    mma_bf16(acc[mt][nt], ah[mt], pl);
                    mma_bf16(acc[mt][nt], al[mt], ph);
                }
        }
    }

    float* out = Cp + (size_t)z * DD * DD;
    const int g = lane >> 2, t4 = lane & 3;
#pragma unroll
    for (int mt = 0; mt < 4; mt++) {
        const int r0 = i0 + wm + mt * 16 + g;
#pragma unroll
        for (int nt = 0; nt < 4; nt++) {
            const int cc = j0 + wn + nt * 8 + 2 * t4;
            float2 v0 = {acc[mt][nt][0], acc[mt][nt][1]};
            float2 v1 = {acc[mt][nt][2], acc[mt][nt][3]};
            *(float2*)&out[(size_t)r0 * DD + cc] = v0;
            *(float2*)&out[(size_t)(r0 + 8) * DD + cc] = v1;
        }
    }
}

__global__ void reduce_cov_sym(const float* __restrict__ Cp, float* __restrict__ G)
{
    const int i = blockIdx.x, j = threadIdx.x;
    if (j < i) return;
    float s = 0.0f;
#pragma unroll 8
    for (int zz = 0; zz < KSPLIT; zz++)
        s += Cp[(size_t)zz * DD * DD + i * DD + j];
    G[i * DD + j] = s;
    G[j * DD + i] = s;
}

// ---------------------------------------------------------------------------
// Newton-Schulz small GEMMs (tensor cores, symmetric upper-triangle tiles)
// ---------------------------------------------------------------------------
#define NS_LDA 80
#define NS_AT  (64 * NS_LDA)
#define NS_LDB 144
#define NS_BT  (32 * NS_LDB)
#define NS_STAGE (2 * NS_AT + 2 * NS_BT)
#define NS_SMEM  (2 * NS_STAGE)

struct NsAcc { float a[2][4][4]; };

__device__ __forceinline__ void ns_tri(int bx, int& ti, int& tj) {
    int t = 0, rem = bx;
    while (rem >= 8 - t) { rem -= 8 - t; t++; }
    ti = t; tj = t + rem;
}

__device__ __forceinline__ void ns_core(
    const __nv_bfloat16* __restrict__ Ah, const __nv_bfloat16* __restrict__ Al,
    const __nv_bfloat16* __restrict__ Bh, const __nv_bfloat16* __restrict__ Bl,
    int m0, int n0, uint32_t sb, NsAcc& A)
{
    const int tid = threadIdx.x;
    const int lane = tid & 31;
    const int wid = tid >> 5;
    const int wm = (wid & 1) * 32;
    const int wn = (wid >> 1) * 32;

    auto loadStage = [&](int c, int s) {
        const uint32_t base = sb + s * NS_STAGE;
        const int k0 = c * 32;
#pragma unroll
        for (int rep = 0; rep < 8; rep++) {
            const int idx = rep * 128 + tid;
            if (idx < 512) {
                const int half = idx >> 8, r = (idx >> 2) & 63, ch = idx & 3;
                const __nv_bfloat16* src =
                    (half ? Al : Ah) + (size_t)(m0 + r) * DD + k0 + ch * 8;
                cpa16(base + half * NS_AT + r * NS_LDA + ch * 16, src);
            } else {
                const int j = idx - 512;
                const int half = j >> 8, r = (j >> 3) & 31, ch = j & 7;
                const __nv_bfloat16* src =
                    (half ? Bl : Bh) + (size_t)(k0 + r) * DD + n0 + ch * 8;
                cpa16(base + 2 * NS_AT + half * NS_BT + r * NS_LDB + ch * 16, src);
            }
        }
        CP_COMMIT();
    };

    loadStage(0, 0);

    for (int c = 0; c < DD / 32; c++) {
        CP_WAIT0();
        __syncthreads();
        if (c + 1 < DD / 32) loadStage(c + 1, (c + 1) & 1);
        const uint32_t st = sb + (c & 1) * NS_STAGE;

#pragma unroll
        for (int ks = 0; ks < 2; ks++) {
            uint32_t ah[2][4], al[2][4];
            const uint32_t abase = st + (lane & 15) * NS_LDA + ks * 32 + (lane >> 4) * 16;
#pragma unroll
            for (int mt = 0; mt < 2; mt++) {
                ldsm4(ah[mt], abase + (wm + mt * 16) * NS_LDA);
                ldsm4(al[mt], abase + NS_AT + (wm + mt * 16) * NS_LDA);
            }
            const uint32_t brow = ks * 16 + (lane & 7) + ((lane >> 3) & 1) * 8;
            const uint32_t bbase = st + 2 * NS_AT + brow * NS_LDB + wn * 2 + (lane >> 4) * 16;
            uint32_t bh[2][4], bl[2][4];
            ldsm4t(bh[0], bbase);
            ldsm4t(bh[1], bbase + 32);
            ldsm4t(bl[0], bbase + NS_BT);
            ldsm4t(bl[1], bbase + NS_BT + 32);

#pragma unroll
            for (int mt = 0; mt < 2; mt++)
#pragma unroll
                for (int nt = 0; nt < 4; nt++) {
                    const uint32_t* ph = &bh[nt >> 1][(nt & 1) * 2];
                    const uint32_t* pl = &bl[nt >> 1][(nt & 1) * 2];
                    mma_bf16(A.a[mt][nt], ah[mt], ph);
                    mma_bf16(A.a[mt][nt], ah[mt], pl);
                    mma_bf16(A.a[mt][nt], al[mt], ph);
                }
        }
    }
}

// grid (36,1,2): z=0 -> T1 = P @ S ; z=1 -> T2 = P @ P ; symmetric, mirrored
__global__ void __launch_bounds__(128)
ns_pair(const __nv_bfloat16* __restrict__ Pah, const __nv_bfloat16* __restrict__ Pal,
        const __nv_bfloat16* __restrict__ Sh,  const __nv_bfloat16* __restrict__ Sl,
        __nv_bfloat16* __restrict__ T1h, __nv_bfloat16* __restrict__ T1l,
        __nv_bfloat16* __restrict__ T2h, __nv_bfloat16* __restrict__ T2l)
{
    __shared__ __align__(16) char smem[NS_SMEM];
    const uint32_t sb = smem_u32(smem);
    int ti, tj;
    ns_tri(blockIdx.x, ti, tj);
    const int m0 = ti * 64;
    const int n0 = tj * 64;
    const int lane = threadIdx.x & 31;
    const int wid = threadIdx.x >> 5;
    const int wm = (wid & 1) * 32;
    const int wn = (wid >> 1) * 32;

    NsAcc A = {};
    const __nv_bfloat16* Bh = blockIdx.z ? Pah : Sh;
    const __nv_bfloat16* Bl = blockIdx.z ? Pal : Sl;
    ns_core(Pah, Pal, Bh, Bl, m0, n0, sb, A);

    __nv_bfloat16* Oh = blockIdx.z ? T2h : T1h;
    __nv_bfloat16* Ol = blockIdx.z ? T2l : T1l;
    const int g = lane >> 2, t4 = lane & 3;
    const bool mir = (ti != tj);
#pragma unroll
    for (int mt = 0; mt < 2; mt++) {
        const int r0 = m0 + wm + mt * 16 + g;
#pragma unroll
        for (int nt = 0; nt < 4; nt++) {
            const int cc = n0 + wn + nt * 8 + 2 * t4;
            const float v0 = A.a[mt][nt][0], v1 = A.a[mt][nt][1];
            const float v2 = A.a[mt][nt][2], v3 = A.a[mt][nt][3];
            store_split2(Oh, Ol, (size_t)r0 * DD + cc, v0, v1);
            store_split2(Oh, Ol, (size_t)(r0 + 8) * DD + cc, v2, v3);
            if (mir) {
                store_split1(Oh, Ol, (size_t)cc * DD + r0, v0);
                store_split1(Oh, Ol, (size_t)(cc + 1) * DD + r0, v1);
                store_split1(Oh, Ol, (size_t)cc * DD + r0 + 8, v2);
                store_split1(Oh, Ol, (size_t)(cc + 1) * DD + r0 + 8, v3);
            }
        }
    }
}

// grid (36): Pb = 1.5*Pold - 0.5*(T2 @ T1); symmetric, mirrored; fp32 + splits
__global__ void __launch_bounds__(128)
ns_update(const __nv_bfloat16* __restrict__ T2h, const __nv_bfloat16* __restrict__ T2l,
          const __nv_bfloat16* __restrict__ T1h, const __nv_bfloat16* __restrict__ T1l,
          const float* __restrict__ Pold, float* __restrict__ Pnew,
          __nv_bfloat16* __restrict__ Pnh, __nv_bfloat16* __restrict__ Pnl)
{
    __shared__ __align__(16) char smem[NS_SMEM];
    const uint32_t sb = smem_u32(smem);
    int ti, tj;
    ns_tri(blockIdx.x, ti, tj);
    const int m0 = ti * 64;
    const int n0 = tj * 64;
    const int lane = threadIdx.x & 31;
    const int wid = threadIdx.x >> 5;
    const int wm = (wid & 1) * 32;
    const int wn = (wid >> 1) * 32;

    NsAcc A = {};
    ns_core(T2h, T2l, T1h, T1l, m0, n0, sb, A);

    const int g = lane >> 2, t4 = lane & 3;
    const bool mir = (ti != tj);
#pragma unroll
    for (int mt = 0; mt < 2; mt++) {
        const int r0 = m0 + wm + mt * 16 + g;
#pragma unroll
        for (int nt = 0; nt < 4; nt++) {
            const int cc = n0 + wn + nt * 8 + 2 * t4;
#pragma unroll
            for (int half = 0; half < 2; half++) {
                const int r = r0 + half * 8;
                const size_t idx = (size_t)r * DD + cc;
                const float2 po = *(const float2*)&Pold[idx];
                const float v0 = 1.5f * po.x - 0.5f * A.a[mt][nt][half * 2 + 0];
                const float v1 = 1.5f * po.y - 0.5f * A.a[mt][nt][half * 2 + 1];
                *(float2*)&Pnew[idx] = make_float2(v0, v1);
                store_split2(Pnh, Pnl, idx, v0, v1);
                if (mir) {
                    Pnew[(size_t)cc * DD + r] = v0;
                    Pnew[(size_t)(cc + 1) * DD + r] = v1;
                    store_split1(Pnh, Pnl, (size_t)cc * DD + r, v0);
                    store_split1(Pnh, Pnl, (size_t)(cc + 1) * DD + r, v1);
                }
            }
        }
    }
}

// iteration 1 closed-form: P1 = 1.5 I - 0.5 S
__global__ void p1_kernel(const float* __restrict__ S, float* __restrict__ P,
                          __nv_bfloat16* __restrict__ Ph, __nv_bfloat16* __restrict__ Pl)
{
    const int i = blockIdx.x, j = threadIdx.x;
    const float v = ((i == j) ? 1.5f : 0.0f) - 0.5f * S[i * DD + j];
    P[i * DD + j] = v;
    split1(v, Ph[i * DD + j], Pl[i * DD + j]);
}

// ---------------------------------------------------------------------------
// Mean / trace / S / mc helpers
// ---------------------------------------------------------------------------
// colp is [col][rowblock] (512 contiguous floats per column) -> coalesced
__global__ void mean_finalize(const float* __restrict__ colp, float* __restrict__ mean)
{
    __shared__ float sm[128];
    const int j = blockIdx.x;
    const int t = threadIdx.x;
    const float4 v = *(const float4*)(colp + (size_t)j * 512 + t * 4);
    sm[t] = v.x + v.y + v.z + v.w;
    __syncthreads();
    for (int s = 64; s > 0; s >>= 1) {
        if (t < s) sm[t] += sm[t + s];
        __syncthreads();
    }
    if (t == 0) mean[j] = sm[0] * (1.0f / (float)NROWS);
}

__global__ void trace_kernel(const float* __restrict__ G,
                             const float* __restrict__ mean,
                             float* __restrict__ scalars)
{
    __shared__ float sm[512];
    const int i = threadIdx.x;
    const float m = mean[i];
    sm[i] = G[i * DD + i] * (1.0f / (float)NROWS) - m * m + INV_TEMP;
    __syncthreads();
    for (int s = 256; s > 0; s >>= 1) {
        if (i < s) sm[i] += sm[i + s];
        __syncthreads();
    }
    if (i == 0) {
        const float tr = sm[0];
        scalars[0] = tr;
        scalars[1] = 1.0f / tr;
        scalars[2] = rsqrtf(tr);
    }
}

__global__ void s_kernel(const float* __restrict__ G,
                         const float* __restrict__ mean,
                         const float* __restrict__ scalars,
                         float* __restrict__ S,
                         __nv_bfloat16* __restrict__ Sh, __nv_bfloat16* __restrict__ Sl)
{
    const int i = blockIdx.x, j = threadIdx.x;
    const float invtr = scalars[1];
    float v = G[i * DD + j] * (1.0f / (float)NROWS) - mean[i] * mean[j];
    if (i == j) v += INV_TEMP;
    v *= invtr;
    S[i * DD + j] = v;
    split1(v, Sh[i * DD + j], Sl[i * DD + j]);
}

__global__ void mc_kernel(const float* __restrict__ mean, const float* __restrict__ P,
                          const float* __restrict__ scalars, float* __restrict__ mc)
{
    const int j = blockIdx.x * 128 + threadIdx.x;
    float s = 0.0f;
#pragma unroll 8
    for (int k = 0; k < DD; k++)
        s += mean[k] * P[(size_t)k * DD + j];
    mc[j] = s * scalars[2];
}

// ---------------------------------------------------------------------------
// Host orchestration
// ---------------------------------------------------------------------------
static void run_layer(const float* W, float* out)
{
    float *covp, *G, *S, *P, *Pn, *colp, *mean, *mc, *scal;
    __nv_bfloat16 *Ah, *Al, *Hh, *Hl, *Wh, *Wl, *Sh, *Sl;
    __nv_bfloat16 *Pah, *Pal, *Pbh, *Pbl, *T1h, *T1l, *T2h, *T2l;
    cudaGetSymbolAddress((void**)&covp, g_covp);
    cudaGetSymbolAddress((void**)&G,    g_G);
    cudaGetSymbolAddress((void**)&S,    g_S);
    cudaGetSymbolAddress((void**)&P,    g_P);
    cudaGetSymbolAddress((void**)&Pn,   g_Pn);
    cudaGetSymbolAddress((void**)&colp, g_colp);
    cudaGetSymbolAddress((void**)&mean, g_mean);
    cudaGetSymbolAddress((void**)&mc,   g_mc);
    cudaGetSymbolAddress((void**)&scal, g_scalars);
    cudaGetSymbolAddress((void**)&Ah,   g_Ah);
    cudaGetSymbolAddress((void**)&Al,   g_Al);
    cudaGetSymbolAddress((void**)&Hh,   g_Hh);
    cudaGetSymbolAddress((void**)&Hl,   g_Hl);
    cudaGetSymbolAddress((void**)&Wh,   g_Wh);
    cudaGetSymbolAddress((void**)&Wl,   g_Wl);
    cudaGetSymbolAddress((void**)&Sh,   g_Sh);
    cudaGetSymbolAddress((void**)&Sl,   g_Sl);
    cudaGetSymbolAddress((void**)&Pah,  g_Pah);
    cudaGetSymbolAddress((void**)&Pal,  g_Pal);
    cudaGetSymbolAddress((void**)&Pbh,  g_Pbh);
    cudaGetSymbolAddress((void**)&Pbl,  g_Pbl);
    cudaGetSymbolAddress((void**)&T1h,  g_T1h);
    cudaGetSymbolAddress((void**)&T1l,  g_T1l);
    cudaGetSymbolAddress((void**)&T2h,  g_T2h);
    cudaGetSymbolAddress((void**)&T2l,  g_T2l);

    const int wBlocks = (DD * DD) / (256 * 4);

    // H = in @ W  (epilogue writes Hh/Hl + column-sum partials, transposed)
    split_f32<<<wBlocks, 256>>>(W, Wh, Wl);
    hgemm<0><<<dim3(4, 512), 256, G1_SMEM>>>(Ah, Al, Wh, Wl,
                                             nullptr, Hh, Hl, nullptr, nullptr, colp);
    mean_finalize<<<512, 128>>>(colp, mean);

    // cov (upper-triangle tiles) -> G -> trace -> S (+split)
    hcov<<<dim3(10, 1, KSPLIT), 256, CV_SMEM>>>(Hh, Hl, covp);
    reduce_cov_sym<<<512, 512>>>(covp, G);
    trace_kernel<<<1, 512>>>(G, mean, scal);
    s_kernel<<<512, 512>>>(G, mean, scal, S, Sh, Sl);

    // Newton-Schulz: iteration 1 closed-form, 9 tensor-core iterations
    p1_kernel<<<512, 512>>>(S, P, Pah, Pal);
    float* Pf = P; float* Pg = Pn;
    __nv_bfloat16 *ah = Pah, *al = Pal, *bh = Pbh, *bl = Pbl;
    for (int t = 1; t < NS_ITERS; t++) {
        ns_pair<<<dim3(36, 1, 2), 128>>>(ah, al, Sh, Sl, T1h, T1l, T2h, T2l);
        ns_update<<<dim3(36), 128>>>(T2h, T2l, T1h, T1l, Pf, Pg, bh, bl);
        { float* t0 = Pf; Pf = Pg; Pg = t0; }
        { __nv_bfloat16* t1 = ah; ah = bh; bh = t1; }
        { __nv_bfloat16* t2 = al; al = bl; bl = t2; }
    }

    // out = (H @ P) * rsqrt(tr) - mc; splits of out -> Ah/Al (next layer input)
    mc_kernel<<<4, 128>>>(mean, Pf, scal, mc);
    hgemm<1><<<dim3(4, 512), 256, G1_SMEM>>>(Hh, Hl, ah, al,
                                             out, Ah, Al, scal, mc, nullptr);
}

extern "C" void kernel_launch(void* const* d_in, const int* in_sizes, int n_in,
                              void* d_out, int out_size)
{
    (void)in_sizes; (void)n_in; (void)out_size;
    const float* x  = (const float*)d_in[0];
    const float* W0 = (const float*)d_in[1];
    const float* W1 = (const float*)d_in[2];
    const float* W2 = (const float*)d_in[3];
    float* out = (float*)d_out;

    cudaFuncSetAttribute(hgemm<0>, cudaFuncAttributeMaxDynamicSharedMemorySize, G1_SMEM);
    cudaFuncSetAttribute(hgemm<1>, cudaFuncAttributeMaxDynamicSharedMemorySize, G1_SMEM);
    cudaFuncSetAttribute(hcov,     cudaFuncAttributeMaxDynamicSharedMemorySize, CV_SMEM);

    __nv_bfloat16 *Ah, *Al;
    cudaGetSymbolAddress((void**)&Ah, g_Ah);
    cudaGetSymbolAddress((void**)&Al, g_Al);

    split_f32<<<(NROWS * DD) / (256 * 4), 256>>>(x, Ah, Al);

    run_layer(W0, out);
    run_layer(W1, out + (size_t)NROWS * DD);
    run_layer(W2, out + (size_t)2 * NROWS * DD);
}

// round 7
// speedup vs baseline: 1.0333x; 1.0333x over previous
#include <cuda_runtime.h>
#include <cuda_bf16.h>
#include <cstdint>
#include <math.h>

#define NROWS 65536
#define DD    512
#define KSPLIT 64
#define KCHUNK (NROWS / KSPLIT)   // 1024
#define NS_ITERS 10
#define INV_TEMP 0.1f

// ---------------------------------------------------------------------------
// Static device scratch
// ---------------------------------------------------------------------------
__device__ float g_covp[(size_t)KSPLIT * DD * DD];   // 64 MB
__device__ float g_G[DD * DD];
__device__ float g_S[DD * DD];
__device__ float g_P[DD * DD];
__device__ float g_Pn[DD * DD];
__device__ float g_colp[DD * 512];                   // TRANSPOSED: [col][rowblock]
__device__ float g_mean[DD];
__device__ float g_mc[DD];
__device__ float g_scalars[4];
__device__ __nv_bfloat16 g_Ah[(size_t)NROWS * DD];
__device__ __nv_bfloat16 g_Al[(size_t)NROWS * DD];
__device__ __nv_bfloat16 g_Hh[(size_t)NROWS * DD];
__device__ __nv_bfloat16 g_Hl[(size_t)NROWS * DD];
__device__ __nv_bfloat16 g_Wh[DD * DD];
__device__ __nv_bfloat16 g_Wl[DD * DD];
__device__ __nv_bfloat16 g_Sh[DD * DD], g_Sl[DD * DD];
__device__ __nv_bfloat16 g_Pah[DD * DD], g_Pal[DD * DD];
__device__ __nv_bfloat16 g_Pbh[DD * DD], g_Pbl[DD * DD];
__device__ __nv_bfloat16 g_T1h[DD * DD], g_T1l[DD * DD];
__device__ __nv_bfloat16 g_T2h[DD * DD], g_T2l[DD * DD];

// ---------------------------------------------------------------------------
// PTX helpers
// ---------------------------------------------------------------------------
__device__ __forceinline__ uint32_t smem_u32(const void* p) {
    uint32_t a;
    asm("{ .reg .u64 t; cvta.to.shared.u64 t, %1; cvt.u32.u64 %0, t; }"
        : "=r"(a) : "l"(p));
    return a;
}
__device__ __forceinline__ void cpa16(uint32_t dst, const void* src) {
    asm volatile("cp.async.cg.shared.global [%0], [%1], 16;"
                 :: "r"(dst), "l"(src) : "memory");
}
#define CP_COMMIT() asm volatile("cp.async.commit_group;" ::: "memory")
#define CP_WAIT0()  asm volatile("cp.async.wait_group 0;" ::: "memory")

__device__ __forceinline__ void ldsm4(uint32_t* r, uint32_t a) {
    asm volatile("ldmatrix.sync.aligned.m8n8.x4.shared.b16 {%0,%1,%2,%3}, [%4];"
        : "=r"(r[0]), "=r"(r[1]), "=r"(r[2]), "=r"(r[3]) : "r"(a));
}
__device__ __forceinline__ void ldsm4t(uint32_t* r, uint32_t a) {
    asm volatile("ldmatrix.sync.aligned.m8n8.x4.trans.shared.b16 {%0,%1,%2,%3}, [%4];"
        : "=r"(r[0]), "=r"(r[1]), "=r"(r[2]), "=r"(r[3]) : "r"(a));
}
__device__ __forceinline__ void mma_bf16(float* d, const uint32_t* a, const uint32_t* b) {
    asm volatile("mma.sync.aligned.m16n8k16.row.col.f32.bf16.bf16.f32 "
        "{%0,%1,%2,%3}, {%4,%5,%6,%7}, {%8,%9}, {%0,%1,%2,%3};"
        : "+f"(d[0]), "+f"(d[1]), "+f"(d[2]), "+f"(d[3])
        : "r"(a[0]), "r"(a[1]), "r"(a[2]), "r"(a[3]), "r"(b[0]), "r"(b[1]));
}

__device__ __forceinline__ void split1(float v, __nv_bfloat16& h, __nv_bfloat16& l) {
    h = __float2bfloat16_rn(v);
    l = __float2bfloat16_rn(v - __bfloat162float(h));
}
__device__ __forceinline__ void store_split1(__nv_bfloat16* Xh, __nv_bfloat16* Xl,
                                             size_t off, float v) {
    split1(v, Xh[off], Xl[off]);
}
__device__ __forceinline__ void store_split2(__nv_bfloat16* Xh, __nv_bfloat16* Xl,
                                             size_t off, float a, float b) {
    __nv_bfloat16 ha, la, hb, lb;
    split1(a, ha, la);
    split1(b, hb, lb);
    *(uint32_t*)(Xh + off) =
        ((uint32_t)__bfloat16_as_ushort(hb) << 16) | __bfloat16_as_ushort(ha);
    *(uint32_t*)(Xl + off) =
        ((uint32_t)__bfloat16_as_ushort(lb) << 16) | __bfloat16_as_ushort(la);
}

__global__ void split_f32(const float* __restrict__ X,
                          __nv_bfloat16* __restrict__ Xh, __nv_bfloat16* __restrict__ Xl)
{
    const size_t i = ((size_t)blockIdx.x * blockDim.x + threadIdx.x) * 4;
    float4 v = *(const float4*)(X + i);
    __nv_bfloat16 h[4], l[4];
    split1(v.x, h[0], l[0]); split1(v.y, h[1], l[1]);
    split1(v.z, h[2], l[2]); split1(v.w, h[3], l[3]);
    *(uint64_t*)(Xh + i) = *(const uint64_t*)h;
    *(uint64_t*)(Xl + i) = *(const uint64_t*)l;
}

// ---------------------------------------------------------------------------
// Big GEMM via mma.sync (bf16 3-term emulation), 2-stage cp.async pipeline.
// MODE 0: write split(acc) to Ch/Cl + per-rowblock column sums (transposed colp)
// MODE 1: write fp32 acc*s2 - mc[col] to Cf32 AND split of it to Ch/Cl.
// ---------------------------------------------------------------------------
#define LDA 80
#define LDB 272
#define A_TILE (128 * LDA)
#define B_TILE (32 * LDB)
#define G1_STAGE (2 * A_TILE + 2 * B_TILE)   // 37888
#define G1_SMEM (2 * G1_STAGE)               // 75776

template<int MODE>
__global__ void __launch_bounds__(256)
hgemm(const __nv_bfloat16* __restrict__ Ah, const __nv_bfloat16* __restrict__ Al,
      const __nv_bfloat16* __restrict__ Bh, const __nv_bfloat16* __restrict__ Bl,
      float* __restrict__ Cf32,
      __nv_bfloat16* __restrict__ Ch, __nv_bfloat16* __restrict__ Cl,
      const float* __restrict__ scalars, const float* __restrict__ mc,
      float* __restrict__ colp)
{
    extern __shared__ __align__(16) char smem[];
    const uint32_t sb = smem_u32(smem);
    const int tid = threadIdx.x;
    const int lane = tid & 31;
    const int wid = tid >> 5;
    const int m0 = blockIdx.y * 128;
    const int n0 = blockIdx.x * 128;
    const int wm = (wid & 1) * 64;
    const int wn = (wid >> 1) * 32;

    float acc[4][4][4] = {};

    auto loadStage = [&](int c, int s) {
        const uint32_t base = sb + s * G1_STAGE;
        const int k0 = c * 32;
#pragma unroll
        for (int rep = 0; rep < 4; rep++) {
            const int idx = rep * 256 + tid;
            const int half = idx >> 9, r = (idx >> 2) & 127, ch = idx & 3;
            const __nv_bfloat16* src =
                (half ? Al : Ah) + (size_t)(m0 + r) * DD + k0 + ch * 8;
            cpa16(base + half * A_TILE + r * LDA + ch * 16, src);
        }
#pragma unroll
        for (int rep = 0; rep < 4; rep++) {
            const int idx = rep * 256 + tid;
            const int half = idx >> 9, r = (idx >> 4) & 31, ch = idx & 15;
            const __nv_bfloat16* src =
                (half ? Bl : Bh) + (size_t)(k0 + r) * DD + n0 + ch * 8;
            cpa16(base + 2 * A_TILE + half * B_TILE + r * LDB + ch * 16, src);
        }
        CP_COMMIT();
    };

    const int NC = DD / 32;
    loadStage(0, 0);

    for (int c = 0; c < NC; c++) {
        CP_WAIT0();
        __syncthreads();
        if (c + 1 < NC) loadStage(c + 1, (c + 1) & 1);
        const uint32_t st = sb + (c & 1) * G1_STAGE;

#pragma unroll
        for (int ks = 0; ks < 2; ks++) {
            uint32_t ah[4][4], al[4][4];
            const uint32_t abase = st + (lane & 15) * LDA + ks * 32 + (lane >> 4) * 16;
#pragma unroll
            for (int mt = 0; mt < 4; mt++) {
                ldsm4(ah[mt], abase + (wm + mt * 16) * LDA);
                ldsm4(al[mt], abase + A_TILE + (wm + mt * 16) * LDA);
            }
            const uint32_t brow = ks * 16 + (lane & 7) + ((lane >> 3) & 1) * 8;
            const uint32_t bbase = st + 2 * A_TILE + brow * LDB + wn * 2 + (lane >> 4) * 16;
            uint32_t bh[2][4], bl[2][4];
            ldsm4t(bh[0], bbase);
            ldsm4t(bh[1], bbase + 32);
            ldsm4t(bl[0], bbase + B_TILE);
            ldsm4t(bl[1], bbase + B_TILE + 32);

#pragma unroll
            for (int mt = 0; mt < 4; mt++)
#pragma unroll
                for (int nt = 0; nt < 4; nt++) {
                    const uint32_t* ph = &bh[nt >> 1][(nt & 1) * 2];
                    const uint32_t* pl = &bl[nt >> 1][(nt & 1) * 2];
                    mma_bf16(acc[mt][nt], ah[mt], ph);
                    mma_bf16(acc[mt][nt], ah[mt], pl);
                    mma_bf16(acc[mt][nt], al[mt], ph);
                }
        }
    }

    const float s2 = (MODE == 1) ? scalars[2] : 1.0f;
    const int g = lane >> 2, t4 = lane & 3;
#pragma unroll
    for (int mt = 0; mt < 4; mt++) {
        const int r0 = m0 + wm + mt * 16 + g;
#pragma unroll
        for (int nt = 0; nt < 4; nt++) {
            const int cc = n0 + wn + nt * 8 + 2 * t4;
            float v0 = acc[mt][nt][0], v1 = acc[mt][nt][1];
            float v2 = acc[mt][nt][2], v3 = acc[mt][nt][3];
            if (MODE == 1) {
                const float2 m2 = *(const float2*)&mc[cc];
                v0 = v0 * s2 - m2.x; v1 = v1 * s2 - m2.y;
                v2 = v2 * s2 - m2.x; v3 = v3 * s2 - m2.y;
                *(float2*)&Cf32[(size_t)r0 * DD + cc] = make_float2(v0, v1);
                *(float2*)&Cf32[(size_t)(r0 + 8) * DD + cc] = make_float2(v2, v3);
            }
            store_split2(Ch, Cl, (size_t)r0 * DD + cc, v0, v1);
            store_split2(Ch, Cl, (size_t)(r0 + 8) * DD + cc, v2, v3);
        }
    }

    if (MODE == 0) {
        // fused column sums over this block's 128 rows; colp is [col][rowblock]
        float cs[4][2];
#pragma unroll
        for (int nt = 0; nt < 4; nt++) {
            cs[nt][0] = 0.0f; cs[nt][1] = 0.0f;
#pragma unroll
            for (int mt = 0; mt < 4; mt++) {
                cs[nt][0] += acc[mt][nt][0] + acc[mt][nt][2];
                cs[nt][1] += acc[mt][nt][1] + acc[mt][nt][3];
            }
        }
#pragma unroll
        for (int off = 4; off <= 16; off <<= 1)
#pragma unroll
            for (int nt = 0; nt < 4; nt++) {
                cs[nt][0] += __shfl_xor_sync(0xffffffffu, cs[nt][0], off);
                cs[nt][1] += __shfl_xor_sync(0xffffffffu, cs[nt][1], off);
            }
        float* smcs = (float*)smem;
        __syncthreads();
        if ((wid & 1) == 0 && g == 0) {
#pragma unroll
            for (int nt = 0; nt < 4; nt++) {
                const int c0 = wn + nt * 8 + 2 * t4;
                smcs[c0] = cs[nt][0];
                smcs[c0 + 1] = cs[nt][1];
            }
        }
        __syncthreads();
        if ((wid & 1) == 1 && g == 0) {
#pragma unroll
            for (int nt = 0; nt < 4; nt++) {
                const int c0 = wn + nt * 8 + 2 * t4;
                colp[(size_t)(n0 + c0) * 512 + blockIdx.y] = smcs[c0] + cs[nt][0];
                colp[(size_t)(n0 + c0 + 1) * 512 + blockIdx.y] = smcs[c0 + 1] + cs[nt][1];
            }
        }
    }
}

// ---------------------------------------------------------------------------
// Covariance split-K (upper-triangle tiles): 2-stage pipeline, KSPLIT=64
// ---------------------------------------------------------------------------
#define CV_STAGE (4 * B_TILE)      // 34816
#define CV_SMEM (2 * CV_STAGE)     // 69632

__global__ void __launch_bounds__(256)
hcov(const __nv_bfloat16* __restrict__ Hh, const __nv_bfloat16* __restrict__ Hl,
     float* __restrict__ Cp)
{
    extern __shared__ __align__(16) char smem[];
    const uint32_t sb = smem_u32(smem);
    const int tid = threadIdx.x;
    const int lane = tid & 31;
    const int wid = tid >> 5;
    const int bx = blockIdx.x;
    const int bi = (bx < 4) ? 0 : (bx < 7) ? 1 : (bx < 9) ? 2 : 3;
    const int bj = bx - ((bi == 0) ? 0 : (bi == 1) ? 3 : (bi == 2) ? 5 : 6);
    const int i0 = bi * 128;
    const int j0 = bj * 128;
    const int z  = blockIdx.z;
    const int wm = (wid & 1) * 64;
    const int wn = (wid >> 1) * 32;

    float acc[4][4][4] = {};

    auto loadStage = [&](int c, int s) {
        const uint32_t base = sb + s * CV_STAGE;
        const int nbase = z * KCHUNK + c * 32;
#pragma unroll
        for (int rep = 0; rep < 8; rep++) {
            const int idx = rep * 256 + tid;
            const int tile = idx >> 9;
            const int r = (idx >> 4) & 31, ch = idx & 15;
            const __nv_bfloat16* basep = (tile & 1) ? Hl : Hh;
            const int coff = (tile < 2) ? i0 : j0;
            const __nv_bfloat16* src = basep + (size_t)(nbase + r) * DD + coff + ch * 8;
            cpa16(base + tile * B_TILE + r * LDB + ch * 16, src);
        }
        CP_COMMIT();
    };

    const int NC = KCHUNK / 32;
    loadStage(0, 0);

    for (int c = 0; c < NC; c++) {
        CP_WAIT0();
        __syncthreads();
        if (c + 1 < NC) loadStage(c + 1, (c + 1) & 1);
        const uint32_t st = sb + (c & 1) * CV_STAGE;

#pragma unroll
        for (int ks = 0; ks < 2; ks++) {
            const uint32_t arow = ks * 16 + (lane & 7) + ((lane >> 4) & 1) * 8;
            const uint32_t abase = st + arow * LDB + wm * 2 + ((lane >> 3) & 1) * 16;
            uint32_t ah[4][4], al[4][4];
#pragma unroll
            for (int mt = 0; mt < 4; mt++) {
                ldsm4t(ah[mt], abase + mt * 32);
                ldsm4t(al[mt], abase + B_TILE + mt * 32);
            }
            const uint32_t brow = ks * 16 + (lane & 7) + ((lane >> 3) & 1) * 8;
            const uint32_t bbase = st + 2 * B_TILE + brow * LDB + wn * 2 + (lane >> 4) * 16;
            uint32_t bh[2][4], bl[2][4];
            ldsm4t(bh[0], bbase);
            ldsm4t(bh[1], bbase + 32);
            ldsm4t(bl[0], bbase + B_TILE);
            ldsm4t(bl[1], bbase + B_TILE + 32);

#pragma unroll
            for (int mt = 0; mt < 4; mt++)
#pragma unroll
                for (int nt = 0; nt < 4; nt++) {
                    const uint32_t* ph = &bh[nt >> 1][(nt & 1) * 2];
                    const uint32_t* pl = &bl[nt >> 1][(nt & 1) * 2];
                    mma_bf16(acc[mt][nt], ah[mt], ph);
                    mma_bf16(acc[mt][nt], ah[mt], pl);
                    mma_bf16(acc[mt][nt], al[mt], ph);
                }
        }
    }

    float* out = Cp + (size_t)z * DD * DD;
    const int g = lane >> 2, t4 = lane & 3;
#pragma unroll
    for (int mt = 0; mt < 4; mt++) {
        const int r0 = i0 + wm + mt * 16 + g;
#pragma unroll
        for (int nt = 0; nt < 4; nt++) {
            const int cc = j0 + wn + nt * 8 + 2 * t4;
            float2 v0 = {acc[mt][nt][0], acc[mt][nt][1]};
            float2 v1 = {acc[mt][nt][2], acc[mt][nt][3]};
            *(float2*)&out[(size_t)r0 * DD + cc] = v0;
            *(float2*)&out[(size_t)(r0 + 8) * DD + cc] = v1;
        }
    }
}

__global__ void reduce_cov_sym(const float* __restrict__ Cp, float* __restrict__ G)
{
    const int i = blockIdx.x, j = threadIdx.x;
    if (j < i) return;
    float s = 0.0f;
#pragma unroll 8
    for (int zz = 0; zz < KSPLIT; zz++)
        s += Cp[(size_t)zz * DD * DD + i * DD + j];
    G[i * DD + j] = s;
    G[j * DD + i] = s;
}

// ---------------------------------------------------------------------------
// Newton-Schulz small GEMMs (tensor cores, symmetric upper-triangle tiles)
// ---------------------------------------------------------------------------
#define NS_LDA 80
#define NS_AT  (64 * NS_LDA)
#define NS_LDB 144
#define NS_BT  (32 * NS_LDB)
#define NS_STAGE (2 * NS_AT + 2 * NS_BT)
#define NS_SMEM  (2 * NS_STAGE)

struct NsAcc { float a[2][4][4]; };

__device__ __forceinline__ void ns_tri(int bx, int& ti, int& tj) {
    int t = 0, rem = bx;
    while (rem >= 8 - t) { rem -= 8 - t; t++; }
    ti = t; tj = t + rem;
}

__device__ __forceinline__ void ns_core(
    const __nv_bfloat16* __restrict__ Ah, const __nv_bfloat16* __restrict__ Al,
    const __nv_bfloat16* __restrict__ Bh, const __nv_bfloat16* __restrict__ Bl,
    int m0, int n0, uint32_t sb, NsAcc& A)
{
    const int tid = threadIdx.x;
    const int lane = tid & 31;
    const int wid = tid >> 5;
    const int wm = (wid & 1) * 32;
    const int wn = (wid >> 1) * 32;

    auto loadStage = [&](int c, int s) {
        const uint32_t base = sb + s * NS_STAGE;
        const int k0 = c * 32;
#pragma unroll
        for (int rep = 0; rep < 8; rep++) {
            const int idx = rep * 128 + tid;
            if (idx < 512) {
                const int half = idx >> 8, r = (idx >> 2) & 63, ch = idx & 3;
                const __nv_bfloat16* src =
                    (half ? Al : Ah) + (size_t)(m0 + r) * DD + k0 + ch * 8;
                cpa16(base + half * NS_AT + r * NS_LDA + ch * 16, src);
            } else {
                const int j = idx - 512;
                const int half = j >> 8, r = (j >> 3) & 31, ch = j & 7;
                const __nv_bfloat16* src =
                    (half ? Bl : Bh) + (size_t)(k0 + r) * DD + n0 + ch * 8;
                cpa16(base + 2 * NS_AT + half * NS_BT + r * NS_LDB + ch * 16, src);
            }
        }
        CP_COMMIT();
    };

    loadStage(0, 0);

    for (int c = 0; c < DD / 32; c++) {
        CP_WAIT0();
        __syncthreads();
        if (c + 1 < DD / 32) loadStage(c + 1, (c + 1) & 1);
        const uint32_t st = sb + (c & 1) * NS_STAGE;

#pragma unroll
        for (int ks = 0; ks < 2; ks++) {
            uint32_t ah[2][4], al[2][4];
            const uint32_t abase = st + (lane & 15) * NS_LDA + ks * 32 + (lane >> 4) * 16;
#pragma unroll
            for (int mt = 0; mt < 2; mt++) {
                ldsm4(ah[mt], abase + (wm + mt * 16) * NS_LDA);
                ldsm4(al[mt], abase + NS_AT + (wm + mt * 16) * NS_LDA);
            }
            const uint32_t brow = ks * 16 + (lane & 7) + ((lane >> 3) & 1) * 8;
            const uint32_t bbase = st + 2 * NS_AT + brow * NS_LDB + wn * 2 + (lane >> 4) * 16;
            uint32_t bh[2][4], bl[2][4];
            ldsm4t(bh[0], bbase);
            ldsm4t(bh[1], bbase + 32);
            ldsm4t(bl[0], bbase + NS_BT);
            ldsm4t(bl[1], bbase + NS_BT + 32);

#pragma unroll
            for (int mt = 0; mt < 2; mt++)
#pragma unroll
                for (int nt = 0; nt < 4; nt++) {
                    const uint32_t* ph = &bh[nt >> 1][(nt & 1) * 2];
                    const uint32_t* pl = &bl[nt >> 1][(nt & 1) * 2];
                    mma_bf16(A.a[mt][nt], ah[mt], ph);
                    mma_bf16(A.a[mt][nt], ah[mt], pl);
                    mma_bf16(A.a[mt][nt], al[mt], ph);
                }
        }
    }
}

// grid (36,1,2): z=0 -> T1 = P @ S ; z=1 -> T2 = P @ P ; symmetric, mirrored
__global__ void __launch_bounds__(128)
ns_pair(const __nv_bfloat16* __restrict__ Pah, const __nv_bfloat16* __restrict__ Pal,
        const __nv_bfloat16* __restrict__ Sh,  const __nv_bfloat16* __restrict__ Sl,
        __nv_bfloat16* __restrict__ T1h, __nv_bfloat16* __restrict__ T1l,
        __nv_bfloat16* __restrict__ T2h, __nv_bfloat16* __restrict__ T2l)
{
    __shared__ __align__(16) char smem[NS_SMEM];
    const uint32_t sb = smem_u32(smem);
    int ti, tj;
    ns_tri(blockIdx.x, ti, tj);
    const int m0 = ti * 64;
    const int n0 = tj * 64;
    const int lane = threadIdx.x & 31;
    const int wid = threadIdx.x >> 5;
    const int wm = (wid & 1) * 32;
    const int wn = (wid >> 1) * 32;

    NsAcc A = {};
    const __nv_bfloat16* Bh = blockIdx.z ? Pah : Sh;
    const __nv_bfloat16* Bl = blockIdx.z ? Pal : Sl;
    ns_core(Pah, Pal, Bh, Bl, m0, n0, sb, A);

    __nv_bfloat16* Oh = blockIdx.z ? T2h : T1h;
    __nv_bfloat16* Ol = blockIdx.z ? T2l : T1l;
    const int g = lane >> 2, t4 = lane & 3;
    const bool mir = (ti != tj);
#pragma unroll
    for (int mt = 0; mt < 2; mt++) {
        const int r0 = m0 + wm + mt * 16 + g;
#pragma unroll
        for (int nt = 0; nt < 4; nt++) {
            const int cc = n0 + wn + nt * 8 + 2 * t4;
            const float v0 = A.a[mt][nt][0], v1 = A.a[mt][nt][1];
            const float v2 = A.a[mt][nt][2], v3 = A.a[mt][nt][3];
            store_split2(Oh, Ol, (size_t)r0 * DD + cc, v0, v1);
            store_split2(Oh, Ol, (size_t)(r0 + 8) * DD + cc, v2, v3);
            if (mir) {
                store_split1(Oh, Ol, (size_t)cc * DD + r0, v0);
                store_split1(Oh, Ol, (size_t)(cc + 1) * DD + r0, v1);
                store_split1(Oh, Ol, (size_t)cc * DD + r0 + 8, v2);
                store_split1(Oh, Ol, (size_t)(cc + 1) * DD + r0 + 8, v3);
            }
        }
    }
}

// grid (36): Pb = 1.5*Pold - 0.5*(T2 @ T1); symmetric, mirrored; fp32 + splits
__global__ void __launch_bounds__(128)
ns_update(const __nv_bfloat16* __restrict__ T2h, const __nv_bfloat16* __restrict__ T2l,
          const __nv_bfloat16* __restrict__ T1h, const __nv_bfloat16* __restrict__ T1l,
          const float* __restrict__ Pold, float* __restrict__ Pnew,
          __nv_bfloat16* __restrict__ Pnh, __nv_bfloat16* __restrict__ Pnl)
{
    __shared__ __align__(16) char smem[NS_SMEM];
    const uint32_t sb = smem_u32(smem);
    int ti, tj;
    ns_tri(blockIdx.x, ti, tj);
    const int m0 = ti * 64;
    const int n0 = tj * 64;
    const int lane = threadIdx.x & 31;
    const int wid = threadIdx.x >> 5;
    const int wm = (wid & 1) * 32;
    const int wn = (wid >> 1) * 32;

    NsAcc A = {};
    ns_core(T2h, T2l, T1h, T1l, m0, n0, sb, A);

    const int g = lane >> 2, t4 = lane & 3;
    const bool mir = (ti != tj);
#pragma unroll
    for (int mt = 0; mt < 2; mt++) {
        const int r0 = m0 + wm + mt * 16 + g;
#pragma unroll
        for (int nt = 0; nt < 4; nt++) {
            const int cc = n0 + wn + nt * 8 + 2 * t4;
#pragma unroll
            for (int half = 0; half < 2; half++) {
                const int r = r0 + half * 8;
                const size_t idx = (size_t)r * DD + cc;
                const float2 po = *(const float2*)&Pold[idx];
                const float v0 = 1.5f * po.x - 0.5f * A.a[mt][nt][half * 2 + 0];
                const float v1 = 1.5f * po.y - 0.5f * A.a[mt][nt][half * 2 + 1];
                *(float2*)&Pnew[idx] = make_float2(v0, v1);
                store_split2(Pnh, Pnl, idx, v0, v1);
                if (mir) {
                    Pnew[(size_t)cc * DD + r] = v0;
                    Pnew[(size_t)(cc + 1) * DD + r] = v1;
                    store_split1(Pnh, Pnl, (size_t)cc * DD + r, v0);
                    store_split1(Pnh, Pnl, (size_t)(cc + 1) * DD + r, v1);
                }
            }
        }
    }
}

// iteration 1 closed-form: P1 = 1.5 I - 0.5 S
__global__ void p1_kernel(const float* __restrict__ S, float* __restrict__ P,
                          __nv_bfloat16* __restrict__ Ph, __nv_bfloat16* __restrict__ Pl)
{
    const int i = blockIdx.x, j = threadIdx.x;
    const float v = ((i == j) ? 1.5f : 0.0f) - 0.5f * S[i * DD + j];
    P[i * DD + j] = v;
    split1(v, Ph[i * DD + j], Pl[i * DD + j]);
}

// ---------------------------------------------------------------------------
// Mean / trace / S / mc helpers
// ---------------------------------------------------------------------------
__global__ void mean_finalize(const float* __restrict__ colp, float* __restrict__ mean)
{
    __shared__ float sm[128];
    const int j = blockIdx.x;
    const int t = threadIdx.x;
    const float4 v = *(const float4*)(colp + (size_t)j * 512 + t * 4);
    sm[t] = v.x + v.y + v.z + v.w;
    __syncthreads();
    for (int s = 64; s > 0; s >>= 1) {
        if (t < s) sm[t] += sm[t + s];
        __syncthreads();
    }
    if (t == 0) mean[j] = sm[0] * (1.0f / (float)NROWS);
}

__global__ void trace_kernel(const float* __restrict__ G,
                             const float* __restrict__ mean,
                             float* __restrict__ scalars)
{
    __shared__ float sm[512];
    const int i = threadIdx.x;
    const float m = mean[i];
    sm[i] = G[i * DD + i] * (1.0f / (float)NROWS) - m * m + INV_TEMP;
    __syncthreads();
    for (int s = 256; s > 0; s >>= 1) {
        if (i < s) sm[i] += sm[i + s];
        __syncthreads();
    }
    if (i == 0) {
        const float tr = sm[0];
        scalars[0] = tr;
        scalars[1] = 1.0f / tr;
        scalars[2] = rsqrtf(tr);
    }
}

__global__ void s_kernel(const float* __restrict__ G,
                         const float* __restrict__ mean,
                         const float* __restrict__ scalars,
                         float* __restrict__ S,
                         __nv_bfloat16* __restrict__ Sh, __nv_bfloat16* __restrict__ Sl)
{
    const int i = blockIdx.x, j = threadIdx.x;
    const float invtr = scalars[1];
    float v = G[i * DD + j] * (1.0f / (float)NROWS) - mean[i] * mean[j];
    if (i == j) v += INV_TEMP;
    v *= invtr;
    S[i * DD + j] = v;
    split1(v, Sh[i * DD + j], Sl[i * DD + j]);
}

__global__ void mc_kernel(const float* __restrict__ mean, const float* __restrict__ P,
                          const float* __restrict__ scalars, float* __restrict__ mc)
{
    const int j = blockIdx.x * 128 + threadIdx.x;
    float s = 0.0f;
#pragma unroll 8
    for (int k = 0; k < DD; k++)
        s += mean[k] * P[(size_t)k * DD + j];
    mc[j] = s * scalars[2];
}

// ---------------------------------------------------------------------------
// Host orchestration
// ---------------------------------------------------------------------------
static void run_layer(const float* W, float* out)
{
    float *covp, *G, *S, *P, *Pn, *colp, *mean, *mc, *scal;
    __nv_bfloat16 *Ah, *Al, *Hh, *Hl, *Wh, *Wl, *Sh, *Sl;
    __nv_bfloat16 *Pah, *Pal, *Pbh, *Pbl, *T1h, *T1l, *T2h, *T2l;
    cudaGetSymbolAddress((void**)&covp, g_covp);
    cudaGetSymbolAddress((void**)&G,    g_G);
    cudaGetSymbolAddress((void**)&S,    g_S);
    cudaGetSymbolAddress((void**)&P,    g_P);
    cudaGetSymbolAddress((void**)&Pn,   g_Pn);
    cudaGetSymbolAddress((void**)&colp, g_colp);
    cudaGetSymbolAddress((void**)&mean, g_mean);
    cudaGetSymbolAddress((void**)&mc,   g_mc);
    cudaGetSymbolAddress((void**)&scal, g_scalars);
    cudaGetSymbolAddress((void**)&Ah,   g_Ah);
    cudaGetSymbolAddress((void**)&Al,   g_Al);
    cudaGetSymbolAddress((void**)&Hh,   g_Hh);
    cudaGetSymbolAddress((void**)&Hl,   g_Hl);
    cudaGetSymbolAddress((void**)&Wh,   g_Wh);
    cudaGetSymbolAddress((void**)&Wl,   g_Wl);
    cudaGetSymbolAddress((void**)&Sh,   g_Sh);
    cudaGetSymbolAddress((void**)&Sl,   g_Sl);
    cudaGetSymbolAddress((void**)&Pah,  g_Pah);
    cudaGetSymbolAddress((void**)&Pal,  g_Pal);
    cudaGetSymbolAddress((void**)&Pbh,  g_Pbh);
    cudaGetSymbolAddress((void**)&Pbl,  g_Pbl);
    cudaGetSymbolAddress((void**)&T1h,  g_T1h);
    cudaGetSymbolAddress((void**)&T1l,  g_T1l);
    cudaGetSymbolAddress((void**)&T2h,  g_T2h);
    cudaGetSymbolAddress((void**)&T2l,  g_T2l);

    const int wBlocks = (DD * DD) / (256 * 4);

    // H = in @ W  (epilogue writes Hh/Hl + column-sum partials, transposed)
    split_f32<<<wBlocks, 256>>>(W, Wh, Wl);
    hgemm<0><<<dim3(4, 512), 256, G1_SMEM>>>(Ah, Al, Wh, Wl,
                                             nullptr, Hh, Hl, nullptr, nullptr, colp);
    mean_finalize<<<512, 128>>>(colp, mean);

    // cov (upper-triangle tiles) -> G -> trace -> S (+split)
    hcov<<<dim3(10, 1, KSPLIT), 256, CV_SMEM>>>(Hh, Hl, covp);
    reduce_cov_sym<<<512, 512>>>(covp, G);
    trace_kernel<<<1, 512>>>(G, mean, scal);
    s_kernel<<<512, 512>>>(G, mean, scal, S, Sh, Sl);

    // Newton-Schulz: iteration 1 closed-form, 9 tensor-core iterations
    p1_kernel<<<512, 512>>>(S, P, Pah, Pal);
    float* Pf = P; float* Pg = Pn;
    __nv_bfloat16 *ah = Pah, *al = Pal, *bh = Pbh, *bl = Pbl;
    for (int t = 1; t < NS_ITERS; t++) {
        ns_pair<<<dim3(36, 1, 2), 128>>>(ah, al, Sh, Sl, T1h, T1l, T2h, T2l);
        ns_update<<<dim3(36), 128>>>(T2h, T2l, T1h, T1l, Pf, Pg, bh, bl);
        { float* t0 = Pf; Pf = Pg; Pg = t0; }
        { __nv_bfloat16* t1 = ah; ah = bh; bh = t1; }
        { __nv_bfloat16* t2 = al; al = bl; bl = t2; }
    }

    // out = (H @ P) * rsqrt(tr) - mc; splits of out -> Ah/Al (next layer input)
    mc_kernel<<<4, 128>>>(mean, Pf, scal, mc);
    hgemm<1><<<dim3(4, 512), 256, G1_SMEM>>>(Hh, Hl, ah, al,
                                             out, Ah, Al, scal, mc, nullptr);
}

extern "C" void kernel_launch(void* const* d_in, const int* in_sizes, int n_in,
                              void* d_out, int out_size)
{
    (void)in_sizes; (void)n_in; (void)out_size;
    const float* x  = (const float*)d_in[0];
    const float* W0 = (const float*)d_in[1];
    const float* W1 = (const float*)d_in[2];
    const float* W2 = (const float*)d_in[3];
    float* out = (float*)d_out;

    cudaFuncSetAttribute(hgemm<0>, cudaFuncAttributeMaxDynamicSharedMemorySize, G1_SMEM);
    cudaFuncSetAttribute(hgemm<1>, cudaFuncAttributeMaxDynamicSharedMemorySize, G1_SMEM);
    cudaFuncSetAttribute(hcov,     cudaFuncAttributeMaxDynamicSharedMemorySize, CV_SMEM);

    __nv_bfloat16 *Ah, *Al;
    cudaGetSymbolAddress((void**)&Ah, g_Ah);
    cudaGetSymbolAddress((void**)&Al, g_Al);

    split_f32<<<(NROWS * DD) / (256 * 4), 256>>>(x, Ah, Al);

    run_layer(W0, out);
    run_layer(W1, out + (size_t)NROWS * DD);
    run_layer(W2, out + (size_t)2 * NROWS * DD);
}

// round 8
// speedup vs baseline: 1.1213x; 1.0851x over previous
#include <cuda_runtime.h>
#include <cuda_bf16.h>
#include <cstdint>
#include <math.h>

#define NROWS 65536
#define DD    512
#define KSPLIT 64
#define KCHUNK (NROWS / KSPLIT)   // 1024
#define NS_ITERS 10
#define INV_TEMP 0.1f

// ---------------------------------------------------------------------------
// Static device scratch
// ---------------------------------------------------------------------------
__device__ float g_covp[(size_t)KSPLIT * DD * DD];   // 64 MB (layer 0 only)
__device__ float g_G[DD * DD];
__device__ float g_S[DD * DD];
__device__ float g_P[DD * DD];
__device__ float g_Pn[DD * DD];
__device__ float g_colp[DD * 512];                   // [col][rowblock]
__device__ float g_mean[DD];
__device__ float g_mc[DD];
__device__ float g_scalars[4];
__device__ __nv_bfloat16 g_Ah[(size_t)NROWS * DD];
__device__ __nv_bfloat16 g_Al[(size_t)NROWS * DD];
__device__ __nv_bfloat16 g_Hh[(size_t)NROWS * DD];
__device__ __nv_bfloat16 g_Hl[(size_t)NROWS * DD];
__device__ __nv_bfloat16 g_Wh[DD * DD];
__device__ __nv_bfloat16 g_Wl[DD * DD];
__device__ __nv_bfloat16 g_Sh[DD * DD], g_Sl[DD * DD];
__device__ __nv_bfloat16 g_Pah[DD * DD], g_Pal[DD * DD];
__device__ __nv_bfloat16 g_Pbh[DD * DD], g_Pbl[DD * DD];
__device__ __nv_bfloat16 g_T1h[DD * DD], g_T1l[DD * DD];
__device__ __nv_bfloat16 g_T2h[DD * DD], g_T2l[DD * DD];
__device__ __nv_bfloat16 g_Uh[DD * DD],  g_Ul[DD * DD];   // W^T splits
__device__ __nv_bfloat16 g_GOh[DD * DD], g_GOl[DD * DD];  // G_out splits
__device__ __nv_bfloat16 g_Gch[DD * DD], g_Gcl[DD * DD];  // Gc splits

// ---------------------------------------------------------------------------
// PTX helpers
// ---------------------------------------------------------------------------
__device__ __forceinline__ uint32_t smem_u32(const void* p) {
    uint32_t a;
    asm("{ .reg .u64 t; cvta.to.shared.u64 t, %1; cvt.u32.u64 %0, t; }"
        : "=r"(a) : "l"(p));
    return a;
}
__device__ __forceinline__ void cpa16(uint32_t dst, const void* src) {
    asm volatile("cp.async.cg.shared.global [%0], [%1], 16;"
                 :: "r"(dst), "l"(src) : "memory");
}
#define CP_COMMIT() asm volatile("cp.async.commit_group;" ::: "memory")
#define CP_WAIT0()  asm volatile("cp.async.wait_group 0;" ::: "memory")

__device__ __forceinline__ void ldsm4(uint32_t* r, uint32_t a) {
    asm volatile("ldmatrix.sync.aligned.m8n8.x4.shared.b16 {%0,%1,%2,%3}, [%4];"
        : "=r"(r[0]), "=r"(r[1]), "=r"(r[2]), "=r"(r[3]) : "r"(a));
}
__device__ __forceinline__ void ldsm4t(uint32_t* r, uint32_t a) {
    asm volatile("ldmatrix.sync.aligned.m8n8.x4.trans.shared.b16 {%0,%1,%2,%3}, [%4];"
        : "=r"(r[0]), "=r"(r[1]), "=r"(r[2]), "=r"(r[3]) : "r"(a));
}
__device__ __forceinline__ void mma_bf16(float* d, const uint32_t* a, const uint32_t* b) {
    asm volatile("mma.sync.aligned.m16n8k16.row.col.f32.bf16.bf16.f32 "
        "{%0,%1,%2,%3}, {%4,%5,%6,%7}, {%8,%9}, {%0,%1,%2,%3};"
        : "+f"(d[0]), "+f"(d[1]), "+f"(d[2]), "+f"(d[3])
        : "r"(a[0]), "r"(a[1]), "r"(a[2]), "r"(a[3]), "r"(b[0]), "r"(b[1]));
}

__device__ __forceinline__ void split1(float v, __nv_bfloat16& h, __nv_bfloat16& l) {
    h = __float2bfloat16_rn(v);
    l = __float2bfloat16_rn(v - __bfloat162float(h));
}
__device__ __forceinline__ void store_split1(__nv_bfloat16* Xh, __nv_bfloat16* Xl,
                                             size_t off, float v) {
    split1(v, Xh[off], Xl[off]);
}
__device__ __forceinline__ void store_split2(__nv_bfloat16* Xh, __nv_bfloat16* Xl,
                                             size_t off, float a, float b) {
    __nv_bfloat16 ha, la, hb, lb;
    split1(a, ha, la);
    split1(b, hb, lb);
    *(uint32_t*)(Xh + off) =
        ((uint32_t)__bfloat16_as_ushort(hb) << 16) | __bfloat16_as_ushort(ha);
    *(uint32_t*)(Xl + off) =
        ((uint32_t)__bfloat16_as_ushort(lb) << 16) | __bfloat16_as_ushort(la);
}

__global__ void split_f32(const float* __restrict__ X,
                          __nv_bfloat16* __restrict__ Xh, __nv_bfloat16* __restrict__ Xl)
{
    const size_t i = ((size_t)blockIdx.x * blockDim.x + threadIdx.x) * 4;
    float4 v = *(const float4*)(X + i);
    __nv_bfloat16 h[4], l[4];
    split1(v.x, h[0], l[0]); split1(v.y, h[1], l[1]);
    split1(v.z, h[2], l[2]); split1(v.w, h[3], l[3]);
    *(uint64_t*)(Xh + i) = *(const uint64_t*)h;
    *(uint64_t*)(Xl + i) = *(const uint64_t*)l;
}

// transpose + split: U[i][k] = W[k][i]
__global__ void tsplit(const float* __restrict__ W,
                       __nv_bfloat16* __restrict__ Uh, __nv_bfloat16* __restrict__ Ul)
{
    __shared__ float t[32][33];
    const int bx = blockIdx.x * 32;   // i
    const int by = blockIdx.y * 32;   // k
    const int tx = threadIdx.x, ty = threadIdx.y;
    t[ty][tx] = W[(size_t)(by + ty) * DD + bx + tx];
    __syncthreads();
    const float v = t[tx][ty];        // = W[by+tx][bx+ty]
    const size_t o = (size_t)(bx + ty) * DD + by + tx;
    split1(v, Uh[o], Ul[o]);
}

// Gc = G - n * m m^T  -> splits
__global__ void gc_split(const float* __restrict__ G, const float* __restrict__ mean,
                         __nv_bfloat16* __restrict__ Gch, __nv_bfloat16* __restrict__ Gcl)
{
    const int i = blockIdx.x, j = threadIdx.x;
    const float v = G[i * DD + j] - (float)NROWS * mean[i] * mean[j];
    split1(v, Gch[i * DD + j], Gcl[i * DD + j]);
}

// ---------------------------------------------------------------------------
// Big GEMM via mma.sync (bf16 3-term emulation), 2-stage cp.async pipeline.
// MODE 0: write split(acc) to Ch/Cl + per-rowblock column sums (transposed colp)
// MODE 1: write fp32 acc*s2 - mc[col] to Cf32 AND split of it to Ch/Cl.
// ---------------------------------------------------------------------------
#define LDA 80
#define LDB 272
#define A_TILE (128 * LDA)
#define B_TILE (32 * LDB)
#define G1_STAGE (2 * A_TILE + 2 * B_TILE)   // 37888
#define G1_SMEM (2 * G1_STAGE)               // 75776

template<int MODE>
__global__ void __launch_bounds__(256)
hgemm(const __nv_bfloat16* __restrict__ Ah, const __nv_bfloat16* __restrict__ Al,
      const __nv_bfloat16* __restrict__ Bh, const __nv_bfloat16* __restrict__ Bl,
      float* __restrict__ Cf32,
      __nv_bfloat16* __restrict__ Ch, __nv_bfloat16* __restrict__ Cl,
      const float* __restrict__ scalars, const float* __restrict__ mc,
      float* __restrict__ colp)
{
    extern __shared__ __align__(16) char smem[];
    const uint32_t sb = smem_u32(smem);
    const int tid = threadIdx.x;
    const int lane = tid & 31;
    const int wid = tid >> 5;
    const int m0 = blockIdx.y * 128;
    const int n0 = blockIdx.x * 128;
    const int wm = (wid & 1) * 64;
    const int wn = (wid >> 1) * 32;

    float acc[4][4][4] = {};

    auto loadStage = [&](int c, int s) {
        const uint32_t base = sb + s * G1_STAGE;
        const int k0 = c * 32;
#pragma unroll
        for (int rep = 0; rep < 4; rep++) {
            const int idx = rep * 256 + tid;
            const int half = idx >> 9, r = (idx >> 2) & 127, ch = idx & 3;
            const __nv_bfloat16* src =
                (half ? Al : Ah) + (size_t)(m0 + r) * DD + k0 + ch * 8;
            cpa16(base + half * A_TILE + r * LDA + ch * 16, src);
        }
#pragma unroll
        for (int rep = 0; rep < 4; rep++) {
            const int idx = rep * 256 + tid;
            const int half = idx >> 9, r = (idx >> 4) & 31, ch = idx & 15;
            const __nv_bfloat16* src =
                (half ? Bl : Bh) + (size_t)(k0 + r) * DD + n0 + ch * 8;
            cpa16(base + 2 * A_TILE + half * B_TILE + r * LDB + ch * 16, src);
        }
        CP_COMMIT();
    };

    const int NC = DD / 32;
    loadStage(0, 0);

    for (int c = 0; c < NC; c++) {
        CP_WAIT0();
        __syncthreads();
        if (c + 1 < NC) loadStage(c + 1, (c + 1) & 1);
        const uint32_t st = sb + (c & 1) * G1_STAGE;

#pragma unroll
        for (int ks = 0; ks < 2; ks++) {
            uint32_t ah[4][4], al[4][4];
            const uint32_t abase = st + (lane & 15) * LDA + ks * 32 + (lane >> 4) * 16;
#pragma unroll
            for (int mt = 0; mt < 4; mt++) {
                ldsm4(ah[mt], abase + (wm + mt * 16) * LDA);
                ldsm4(al[mt], abase + A_TILE + (wm + mt * 16) * LDA);
            }
            const uint32_t brow = ks * 16 + (lane & 7) + ((lane >> 3) & 1) * 8;
            const uint32_t bbase = st + 2 * A_TILE + brow * LDB + wn * 2 + (lane >> 4) * 16;
            uint32_t bh[2][4], bl[2][4];
            ldsm4t(bh[0], bbase);
            ldsm4t(bh[1], bbase + 32);
            ldsm4t(bl[0], bbase + B_TILE);
            ldsm4t(bl[1], bbase + B_TILE + 32);

#pragma unroll
            for (int mt = 0; mt < 4; mt++)
#pragma unroll
                for (int nt = 0; nt < 4; nt++) {
                    const uint32_t* ph = &bh[nt >> 1][(nt & 1) * 2];
                    const uint32_t* pl = &bl[nt >> 1][(nt & 1) * 2];
                    mma_bf16(acc[mt][nt], ah[mt], ph);
                    mma_bf16(acc[mt][nt], ah[mt], pl);
                    mma_bf16(acc[mt][nt], al[mt], ph);
                }
        }
    }

    const float s2 = (MODE == 1) ? scalars[2] : 1.0f;
    const int g = lane >> 2, t4 = lane & 3;
#pragma unroll
    for (int mt = 0; mt < 4; mt++) {
        const int r0 = m0 + wm + mt * 16 + g;
#pragma unroll
        for (int nt = 0; nt < 4; nt++) {
            const int cc = n0 + wn + nt * 8 + 2 * t4;
            float v0 = acc[mt][nt][0], v1 = acc[mt][nt][1];
            float v2 = acc[mt][nt][2], v3 = acc[mt][nt][3];
            if (MODE == 1) {
                const float2 m2 = *(const float2*)&mc[cc];
                v0 = v0 * s2 - m2.x; v1 = v1 * s2 - m2.y;
                v2 = v2 * s2 - m2.x; v3 = v3 * s2 - m2.y;
                *(float2*)&Cf32[(size_t)r0 * DD + cc] = make_float2(v0, v1);
                *(float2*)&Cf32[(size_t)(r0 + 8) * DD + cc] = make_float2(v2, v3);
            }
            store_split2(Ch, Cl, (size_t)r0 * DD + cc, v0, v1);
            store_split2(Ch, Cl, (size_t)(r0 + 8) * DD + cc, v2, v3);
        }
    }

    if (MODE == 0) {
        float cs[4][2];
#pragma unroll
        for (int nt = 0; nt < 4; nt++) {
            cs[nt][0] = 0.0f; cs[nt][1] = 0.0f;
#pragma unroll
            for (int mt = 0; mt < 4; mt++) {
                cs[nt][0] += acc[mt][nt][0] + acc[mt][nt][2];
                cs[nt][1] += acc[mt][nt][1] + acc[mt][nt][3];
            }
        }
#pragma unroll
        for (int off = 4; off <= 16; off <<= 1)
#pragma unroll
            for (int nt = 0; nt < 4; nt++) {
                cs[nt][0] += __shfl_xor_sync(0xffffffffu, cs[nt][0], off);
                cs[nt][1] += __shfl_xor_sync(0xffffffffu, cs[nt][1], off);
            }
        float* smcs = (float*)smem;
        __syncthreads();
        if ((wid & 1) == 0 && g == 0) {
#pragma unroll
            for (int nt = 0; nt < 4; nt++) {
                const int c0 = wn + nt * 8 + 2 * t4;
                smcs[c0] = cs[nt][0];
                smcs[c0 + 1] = cs[nt][1];
            }
        }
        __syncthreads();
        if ((wid & 1) == 1 && g == 0) {
#pragma unroll
            for (int nt = 0; nt < 4; nt++) {
                const int c0 = wn + nt * 8 + 2 * t4;
                colp[(size_t)(n0 + c0) * 512 + blockIdx.y] = smcs[c0] + cs[nt][0];
                colp[(size_t)(n0 + c0 + 1) * 512 + blockIdx.y] = smcs[c0 + 1] + cs[nt][1];
            }
        }
    }
}

// ---------------------------------------------------------------------------
// Covariance split-K (upper-triangle tiles, LAYER 0 ONLY)
// ---------------------------------------------------------------------------
#define CV_STAGE (4 * B_TILE)      // 34816
#define CV_SMEM (2 * CV_STAGE)     // 69632

__global__ void __launch_bounds__(256)
hcov(const __nv_bfloat16* __restrict__ Hh, const __nv_bfloat16* __restrict__ Hl,
     float* __restrict__ Cp)
{
    extern __shared__ __align__(16) char smem[];
    const uint32_t sb = smem_u32(smem);
    const int tid = threadIdx.x;
    const int lane = tid & 31;
    const int wid = tid >> 5;
    const int bx = blockIdx.x;
    const int bi = (bx < 4) ? 0 : (bx < 7) ? 1 : (bx < 9) ? 2 : 3;
    const int bj = bx - ((bi == 0) ? 0 : (bi == 1) ? 3 : (bi == 2) ? 5 : 6);
    const int i0 = bi * 128;
    const int j0 = bj * 128;
    const int z  = blockIdx.z;
    const int wm = (wid & 1) * 64;
    const int wn = (wid >> 1) * 32;

    float acc[4][4][4] = {};

    auto loadStage = [&](int c, int s) {
        const uint32_t base = sb + s * CV_STAGE;
        const int nbase = z * KCHUNK + c * 32;
#pragma unroll
        for (int rep = 0; rep < 8; rep++) {
            const int idx = rep * 256 + tid;
            const int tile = idx >> 9;
            const int r = (idx >> 4) & 31, ch = idx & 15;
            const __nv_bfloat16* basep = (tile & 1) ? Hl : Hh;
            const int coff = (tile < 2) ? i0 : j0;
            const __nv_bfloat16* src = basep + (size_t)(nbase + r) * DD + coff + ch * 8;
            cpa16(base + tile * B_TILE + r * LDB + ch * 16, src);
        }
        CP_COMMIT();
    };

    const int NC = KCHUNK / 32;
    loadStage(0, 0);

    for (int c = 0; c < NC; c++) {
        CP_WAIT0();
        __syncthreads();
        if (c + 1 < NC) loadStage(c + 1, (c + 1) & 1);
        const uint32_t st = sb + (c & 1) * CV_STAGE;

#pragma unroll
        for (int ks = 0; ks < 2; ks++) {
            const uint32_t arow = ks * 16 + (lane & 7) + ((lane >> 4) & 1) * 8;
            const uint32_t abase = st + arow * LDB + wm * 2 + ((lane >> 3) & 1) * 16;
            uint32_t ah[4][4], al[4][4];
#pragma unroll
            for (int mt = 0; mt < 4; mt++) {
                ldsm4t(ah[mt], abase + mt * 32);
                ldsm4t(al[mt], abase + B_TILE + mt * 32);
            }
            const uint32_t brow = ks * 16 + (lane & 7) + ((lane >> 3) & 1) * 8;
            const uint32_t bbase = st + 2 * B_TILE + brow * LDB + wn * 2 + (lane >> 4) * 16;
            uint32_t bh[2][4], bl[2][4];
            ldsm4t(bh[0], bbase);
            ldsm4t(bh[1], bbase + 32);
            ldsm4t(bl[0], bbase + B_TILE);
            ldsm4t(bl[1], bbase + B_TILE + 32);

#pragma unroll
            for (int mt = 0; mt < 4; mt++)
#pragma unroll
                for (int nt = 0; nt < 4; nt++) {
                    const uint32_t* ph = &bh[nt >> 1][(nt & 1) * 2];
                    const uint32_t* pl = &bl[nt >> 1][(nt & 1) * 2];
                    mma_bf16(acc[mt][nt], ah[mt], ph);
                    mma_bf16(acc[mt][nt], ah[mt], pl);
                    mma_bf16(acc[mt][nt], al[mt], ph);
                }
        }
    }

    float* out = Cp + (size_t)z * DD * DD;
    const int g = lane >> 2, t4 = lane & 3;
#pragma unroll
    for (int mt = 0; mt < 4; mt++) {
        const int r0 = i0 + wm + mt * 16 + g;
#pragma unroll
        for (int nt = 0; nt < 4; nt++) {
            const int cc = j0 + wn + nt * 8 + 2 * t4;
            float2 v0 = {acc[mt][nt][0], acc[mt][nt][1]};
            float2 v1 = {acc[mt][nt][2], acc[mt][nt][3]};
            *(float2*)&out[(size_t)r0 * DD + cc] = v0;
            *(float2*)&out[(size_t)(r0 + 8) * DD + cc] = v1;
        }
    }
}

__global__ void reduce_cov_sym(const float* __restrict__ Cp, float* __restrict__ G)
{
    const int i = blockIdx.x, j = threadIdx.x;
    if (j < i) return;
    float s = 0.0f;
#pragma unroll 8
    for (int zz = 0; zz < KSPLIT; zz++)
        s += Cp[(size_t)zz * DD * DD + i * DD + j];
    G[i * DD + j] = s;
    G[j * DD + i] = s;
}

// ---------------------------------------------------------------------------
// Small GEMM core (64x64 tiles, 128 threads)
// ---------------------------------------------------------------------------
#define NS_LDA 80
#define NS_AT  (64 * NS_LDA)
#define NS_LDB 144
#define NS_BT  (32 * NS_LDB)
#define NS_STAGE (2 * NS_AT + 2 * NS_BT)
#define NS_SMEM  (2 * NS_STAGE)

struct NsAcc { float a[2][4][4]; };

__device__ __forceinline__ void ns_tri(int bx, int& ti, int& tj) {
    int t = 0, rem = bx;
    while (rem >= 8 - t) { rem -= 8 - t; t++; }
    ti = t; tj = t + rem;
}

__device__ __forceinline__ void ns_core(
    const __nv_bfloat16* __restrict__ Ah, const __nv_bfloat16* __restrict__ Al,
    const __nv_bfloat16* __restrict__ Bh, const __nv_bfloat16* __restrict__ Bl,
    int m0, int n0, uint32_t sb, NsAcc& A)
{
    const int tid = threadIdx.x;
    const int lane = tid & 31;
    const int wid = tid >> 5;
    const int wm = (wid & 1) * 32;
    const int wn = (wid >> 1) * 32;

    auto loadStage = [&](int c, int s) {
        const uint32_t base = sb + s * NS_STAGE;
        const int k0 = c * 32;
#pragma unroll
        for (int rep = 0; rep < 8; rep++) {
            const int idx = rep * 128 + tid;
            if (idx < 512) {
                const int half = idx >> 8, r = (idx >> 2) & 63, ch = idx & 3;
                const __nv_bfloat16* src =
                    (half ? Al : Ah) + (size_t)(m0 + r) * DD + k0 + ch * 8;
                cpa16(base + half * NS_AT + r * NS_LDA + ch * 16, src);
            } else {
                const int j = idx - 512;
                const int half = j >> 8, r = (j >> 3) & 31, ch = j & 7;
                const __nv_bfloat16* src =
                    (half ? Bl : Bh) + (size_t)(k0 + r) * DD + n0 + ch * 8;
                cpa16(base + 2 * NS_AT + half * NS_BT + r * NS_LDB + ch * 16, src);
            }
        }
        CP_COMMIT();
    };

    loadStage(0, 0);

    for (int c = 0; c < DD / 32; c++) {
        CP_WAIT0();
        __syncthreads();
        if (c + 1 < DD / 32) loadStage(c + 1, (c + 1) & 1);
        const uint32_t st = sb + (c & 1) * NS_STAGE;

#pragma unroll
        for (int ks = 0; ks < 2; ks++) {
            uint32_t ah[2][4], al[2][4];
            const uint32_t abase = st + (lane & 15) * NS_LDA + ks * 32 + (lane >> 4) * 16;
#pragma unroll
            for (int mt = 0; mt < 2; mt++) {
                ldsm4(ah[mt], abase + (wm + mt * 16) * NS_LDA);
                ldsm4(al[mt], abase + NS_AT + (wm + mt * 16) * NS_LDA);
            }
            const uint32_t brow = ks * 16 + (lane & 7) + ((lane >> 3) & 1) * 8;
            const uint32_t bbase = st + 2 * NS_AT + brow * NS_LDB + wn * 2 + (lane >> 4) * 16;
            uint32_t bh[2][4], bl[2][4];
            ldsm4t(bh[0], bbase);
            ldsm4t(bh[1], bbase + 32);
            ldsm4t(bl[0], bbase + NS_BT);
            ldsm4t(bl[1], bbase + NS_BT + 32);

#pragma unroll
            for (int mt = 0; mt < 2; mt++)
#pragma unroll
                for (int nt = 0; nt < 4; nt++) {
                    const uint32_t* ph = &bh[nt >> 1][(nt & 1) * 2];
                    const uint32_t* pl = &bl[nt >> 1][(nt & 1) * 2];
                    mma_bf16(A.a[mt][nt], ah[mt], ph);
                    mma_bf16(A.a[mt][nt], ah[mt], pl);
                    mma_bf16(A.a[mt][nt], al[mt], ph);
                }
        }
    }
}

// Generic small GEMM: C = scale * (A @ B), grid (8,8).
// SCALE: 0 -> 1.0 ; 1 -> scalars[2]^2.  OF32 / OSPLIT select outputs.
template<int SCALE, int OF32, int OSPLIT>
__global__ void __launch_bounds__(128)
sg(const __nv_bfloat16* __restrict__ Ah, const __nv_bfloat16* __restrict__ Al,
   const __nv_bfloat16* __restrict__ Bh, const __nv_bfloat16* __restrict__ Bl,
   float* __restrict__ Cf32,
   __nv_bfloat16* __restrict__ Ch, __nv_bfloat16* __restrict__ Cl,
   const float* __restrict__ scalars)
{
    __shared__ __align__(16) char smem[NS_SMEM];
    const uint32_t sb = smem_u32(smem);
    const int m0 = blockIdx.y * 64;
    const int n0 = blockIdx.x * 64;
    const int lane = threadIdx.x & 31;
    const int wid = threadIdx.x >> 5;
    const int wm = (wid & 1) * 32;
    const int wn = (wid >> 1) * 32;

    NsAcc A = {};
    ns_core(Ah, Al, Bh, Bl, m0, n0, sb, A);

    const float sc = (SCALE == 1) ? scalars[2] * scalars[2] : 1.0f;
    const int g = lane >> 2, t4 = lane & 3;
#pragma unroll
    for (int mt = 0; mt < 2; mt++) {
        const int r0 = m0 + wm + mt * 16 + g;
#pragma unroll
        for (int nt = 0; nt < 4; nt++) {
            const int cc = n0 + wn + nt * 8 + 2 * t4;
#pragma unroll
            for (int half = 0; half < 2; half++) {
                const size_t idx = (size_t)(r0 + half * 8) * DD + cc;
                const float v0 = A.a[mt][nt][half * 2 + 0] * sc;
                const float v1 = A.a[mt][nt][half * 2 + 1] * sc;
                if (OF32) *(float2*)&Cf32[idx] = make_float2(v0, v1);
                if (OSPLIT) store_split2(Ch, Cl, idx, v0, v1);
            }
        }
    }
}

// grid (36,1,2): z=0 -> T1 = P @ S ; z=1 -> T2 = P @ P ; symmetric, mirrored
__global__ void __launch_bounds__(128)
ns_pair(const __nv_bfloat16* __restrict__ Pah, const __nv_bfloat16* __restrict__ Pal,
        const __nv_bfloat16* __restrict__ Sh,  const __nv_bfloat16* __restrict__ Sl,
        __nv_bfloat16* __restrict__ T1h, __nv_bfloat16* __restrict__ T1l,
        __nv_bfloat16* __restrict__ T2h, __nv_bfloat16* __restrict__ T2l)
{
    __shared__ __align__(16) char smem[NS_SMEM];
    const uint32_t sb = smem_u32(smem);
    int ti, tj;
    ns_tri(blockIdx.x, ti, tj);
    const int m0 = ti * 64;
    const int n0 = tj * 64;
    const int lane = threadIdx.x & 31;
    const int wid = threadIdx.x >> 5;
    const int wm = (wid & 1) * 32;
    const int wn = (wid >> 1) * 32;

    NsAcc A = {};
    const __nv_bfloat16* Bh = blockIdx.z ? Pah : Sh;
    const __nv_bfloat16* Bl = blockIdx.z ? Pal : Sl;
    ns_core(Pah, Pal, Bh, Bl, m0, n0, sb, A);

    __nv_bfloat16* Oh = blockIdx.z ? T2h : T1h;
    __nv_bfloat16* Ol = blockIdx.z ? T2l : T1l;
    const int g = lane >> 2, t4 = lane & 3;
    const bool mir = (ti != tj);
#pragma unroll
    for (int mt = 0; mt < 2; mt++) {
        const int r0 = m0 + wm + mt * 16 + g;
#pragma unroll
        for (int nt = 0; nt < 4; nt++) {
            const int cc = n0 + wn + nt * 8 + 2 * t4;
            const float v0 = A.a[mt][nt][0], v1 = A.a[mt][nt][1];
            const float v2 = A.a[mt][nt][2], v3 = A.a[mt][nt][3];
            store_split2(Oh, Ol, (size_t)r0 * DD + cc, v0, v1);
            store_split2(Oh, Ol, (size_t)(r0 + 8) * DD + cc, v2, v3);
            if (mir) {
                store_split1(Oh, Ol, (size_t)cc * DD + r0, v0);
                store_split1(Oh, Ol, (size_t)(cc + 1) * DD + r0, v1);
                store_split1(Oh, Ol, (size_t)cc * DD + r0 + 8, v2);
                store_split1(Oh, Ol, (size_t)(cc + 1) * DD + r0 + 8, v3);
            }
        }
    }
}

// grid (36): Pb = 1.5*Pold - 0.5*(T2 @ T1); symmetric, mirrored; fp32 + splits
__global__ void __launch_bounds__(128)
ns_update(const __nv_bfloat16* __restrict__ T2h, const __nv_bfloat16* __restrict__ T2l,
          const __nv_bfloat16* __restrict__ T1h, const __nv_bfloat16* __restrict__ T1l,
          const float* __restrict__ Pold, float* __restrict__ Pnew,
          __nv_bfloat16* __restrict__ Pnh, __nv_bfloat16* __restrict__ Pnl)
{
    __shared__ __align__(16) char smem[NS_SMEM];
    const uint32_t sb = smem_u32(smem);
    int ti, tj;
    ns_tri(blockIdx.x, ti, tj);
    const int m0 = ti * 64;
    const int n0 = tj * 64;
    const int lane = threadIdx.x & 31;
    const int wid = threadIdx.x >> 5;
    const int wm = (wid & 1) * 32;
    const int wn = (wid >> 1) * 32;

    NsAcc A = {};
    ns_core(T2h, T2l, T1h, T1l, m0, n0, sb, A);

    const int g = lane >> 2, t4 = lane & 3;
    const bool mir = (ti != tj);
#pragma unroll
    for (int mt = 0; mt < 2; mt++) {
        const int r0 = m0 + wm + mt * 16 + g;
#pragma unroll
        for (int nt = 0; nt < 4; nt++) {
            const int cc = n0 + wn + nt * 8 + 2 * t4;
#pragma unroll
            for (int half = 0; half < 2; half++) {
                const int r = r0 + half * 8;
                const size_t idx = (size_t)r * DD + cc;
                const float2 po = *(const float2*)&Pold[idx];
                const float v0 = 1.5f * po.x - 0.5f * A.a[mt][nt][half * 2 + 0];
                const float v1 = 1.5f * po.y - 0.5f * A.a[mt][nt][half * 2 + 1];
                *(float2*)&Pnew[idx] = make_float2(v0, v1);
                store_split2(Pnh, Pnl, idx, v0, v1);
                if (mir) {
                    Pnew[(size_t)cc * DD + r] = v0;
                    Pnew[(size_t)(cc + 1) * DD + r] = v1;
                    store_split1(Pnh, Pnl, (size_t)cc * DD + r, v0);
                    store_split1(Pnh, Pnl, (size_t)(cc + 1) * DD + r, v1);
                }
            }
        }
    }
}

// iteration 1 closed-form: P1 = 1.5 I - 0.5 S
__global__ void p1_kernel(const float* __restrict__ S, float* __restrict__ P,
                          __nv_bfloat16* __restrict__ Ph, __nv_bfloat16* __restrict__ Pl)
{
    const int i = blockIdx.x, j = threadIdx.x;
    const float v = ((i == j) ? 1.5f : 0.0f) - 0.5f * S[i * DD + j];
    P[i * DD + j] = v;
    split1(v, Ph[i * DD + j], Pl[i * DD + j]);
}

// ---------------------------------------------------------------------------
// Mean / trace / S / mc helpers
// ---------------------------------------------------------------------------
__global__ void mean_finalize(const float* __restrict__ colp, float* __restrict__ mean)
{
    __shared__ float sm[128];
    const int j = blockIdx.x;
    const int t = threadIdx.x;
    const float4 v = *(const float4*)(colp + (size_t)j * 512 + t * 4);
    sm[t] = v.x + v.y + v.z + v.w;
    __syncthreads();
    for (int s = 64; s > 0; s >>= 1) {
        if (t < s) sm[t] += sm[t + s];
        __syncthreads();
    }
    if (t == 0) mean[j] = sm[0] * (1.0f / (float)NROWS);
}

__global__ void trace_kernel(const float* __restrict__ G,
                             const float* __restrict__ mean,
                             float* __restrict__ scalars)
{
    __shared__ float sm[512];
    const int i = threadIdx.x;
    const float m = mean[i];
    sm[i] = G[i * DD + i] * (1.0f / (float)NROWS) - m * m + INV_TEMP;
    __syncthreads();
    for (int s = 256; s > 0; s >>= 1) {
        if (i < s) sm[i] += sm[i + s];
        __syncthreads();
    }
    if (i == 0) {
        const float tr = sm[0];
        scalars[0] = tr;
        scalars[1] = 1.0f / tr;
        scalars[2] = rsqrtf(tr);
    }
}

__global__ void s_kernel(const float* __restrict__ G,
                         const float* __restrict__ mean,
                         const float* __restrict__ scalars,
                         float* __restrict__ S,
                         __nv_bfloat16* __restrict__ Sh, __nv_bfloat16* __restrict__ Sl)
{
    const int i = blockIdx.x, j = threadIdx.x;
    const float invtr = scalars[1];
    float v = G[i * DD + j] * (1.0f / (float)NROWS) - mean[i] * mean[j];
    if (i == j) v += INV_TEMP;
    v *= invtr;
    S[i * DD + j] = v;
    split1(v, Sh[i * DD + j], Sl[i * DD + j]);
}

__global__ void mc_kernel(const float* __restrict__ mean, const float* __restrict__ P,
                          const float* __restrict__ scalars, float* __restrict__ mc)
{
    const int j = blockIdx.x * 128 + threadIdx.x;
    float s = 0.0f;
#pragma unroll 8
    for (int k = 0; k < DD; k++)
        s += mean[k] * P[(size_t)k * DD + j];
    mc[j] = s * scalars[2];
}

// ---------------------------------------------------------------------------
// Host orchestration
// ---------------------------------------------------------------------------
static void run_layer(const float* W, float* out, int layer)
{
    float *covp, *G, *S, *P, *Pn, *colp, *mean, *mc, *scal;
    __nv_bfloat16 *Ah, *Al, *Hh, *Hl, *Wh, *Wl, *Sh, *Sl;
    __nv_bfloat16 *Pah, *Pal, *Pbh, *Pbl, *T1h, *T1l, *T2h, *T2l;
    __nv_bfloat16 *Uh, *Ul, *GOh, *GOl, *Gch, *Gcl;
    cudaGetSymbolAddress((void**)&covp, g_covp);
    cudaGetSymbolAddress((void**)&G,    g_G);
    cudaGetSymbolAddress((void**)&S,    g_S);
    cudaGetSymbolAddress((void**)&P,    g_P);
    cudaGetSymbolAddress((void**)&Pn,   g_Pn);
    cudaGetSymbolAddress((void**)&colp, g_colp);
    cudaGetSymbolAddress((void**)&mean, g_mean);
    cudaGetSymbolAddress((void**)&mc,   g_mc);
    cudaGetSymbolAddress((void**)&scal, g_scalars);
    cudaGetSymbolAddress((void**)&Ah,   g_Ah);
    cudaGetSymbolAddress((void**)&Al,   g_Al);
    cudaGetSymbolAddress((void**)&Hh,   g_Hh);
    cudaGetSymbolAddress((void**)&Hl,   g_Hl);
    cudaGetSymbolAddress((void**)&Wh,   g_Wh);
    cudaGetSymbolAddress((void**)&Wl,   g_Wl);
    cudaGetSymbolAddress((void**)&Sh,   g_Sh);
    cudaGetSymbolAddress((void**)&Sl,   g_Sl);
    cudaGetSymbolAddress((void**)&Pah,  g_Pah);
    cudaGetSymbolAddress((void**)&Pal,  g_Pal);
    cudaGetSymbolAddress((void**)&Pbh,  g_Pbh);
    cudaGetSymbolAddress((void**)&Pbl,  g_Pbl);
    cudaGetSymbolAddress((void**)&T1h,  g_T1h);
    cudaGetSymbolAddress((void**)&T1l,  g_T1l);
    cudaGetSymbolAddress((void**)&T2h,  g_T2h);
    cudaGetSymbolAddress((void**)&T2l,  g_T2l);
    cudaGetSymbolAddress((void**)&Uh,   g_Uh);
    cudaGetSymbolAddress((void**)&Ul,   g_Ul);
    cudaGetSymbolAddress((void**)&GOh,  g_GOh);
    cudaGetSymbolAddress((void**)&GOl,  g_GOl);
    cudaGetSymbolAddress((void**)&Gch,  g_Gch);
    cudaGetSymbolAddress((void**)&Gcl,  g_Gcl);

    const int wBlocks = (DD * DD) / (256 * 4);

    // H = in @ W  (epilogue writes Hh/Hl + column-sum partials)
    split_f32<<<wBlocks, 256>>>(W, Wh, Wl);
    hgemm<0><<<dim3(4, 512), 256, G1_SMEM>>>(Ah, Al, Wh, Wl,
                                             nullptr, Hh, Hl, nullptr, nullptr, colp);
    mean_finalize<<<512, 128>>>(colp, mean);

    // Gram of H
    if (layer == 0) {
        hcov<<<dim3(10, 1, KSPLIT), 256, CV_SMEM>>>(Hh, Hl, covp);
        reduce_cov_sym<<<512, 512>>>(covp, G);
    } else {
        // G = W^T @ Gout_prev @ W  (Gout_prev in GOh/GOl from previous layer)
        tsplit<<<dim3(16, 16), dim3(32, 32)>>>(W, Uh, Ul);
        sg<0, 0, 1><<<dim3(8, 8), 128>>>(Uh, Ul, GOh, GOl,
                                         nullptr, T1h, T1l, scal);   // tmp = W^T @ Gout
        sg<0, 1, 0><<<dim3(8, 8), 128>>>(T1h, T1l, Wh, Wl,
                                         G, nullptr, nullptr, scal); // G = tmp @ W
    }
    trace_kernel<<<1, 512>>>(G, mean, scal);
    s_kernel<<<512, 512>>>(G, mean, scal, S, Sh, Sl);

    // Newton-Schulz: iteration 1 closed-form, 9 tensor-core iterations
    p1_kernel<<<512, 512>>>(S, P, Pah, Pal);
    float* Pf = P; float* Pg = Pn;
    __nv_bfloat16 *ah = Pah, *al = Pal, *bh = Pbh, *bl = Pbl;
    for (int t = 1; t < NS_ITERS; t++) {
        ns_pair<<<dim3(36, 1, 2), 128>>>(ah, al, Sh, Sl, T1h, T1l, T2h, T2l);
        ns_update<<<dim3(36), 128>>>(T2h, T2l, T1h, T1l, Pf, Pg, bh, bl);
        { float* t0 = Pf; Pf = Pg; Pg = t0; }
        { __nv_bfloat16* t1 = ah; ah = bh; bh = t1; }
        { __nv_bfloat16* t2 = al; al = bl; bl = t2; }
    }

    // Gout = s2^2 * P @ (G - n m m^T) @ P  (for next layer's Gram chain)
    if (layer < 2) {
        gc_split<<<512, 512>>>(G, mean, Gch, Gcl);
        sg<0, 0, 1><<<dim3(8, 8), 128>>>(ah, al, Gch, Gcl,
                                         nullptr, T1h, T1l, scal);   // t2 = P @ Gc
        sg<1, 0, 1><<<dim3(8, 8), 128>>>(T1h, T1l, ah, al,
                                         nullptr, GOh, GOl, scal);   // Gout = s2^2 (t2 @ P)
    }

    // out = (H @ P) * rsqrt(tr) - mc; splits of out -> Ah/Al (next layer input)
    mc_kernel<<<4, 128>>>(mean, Pf, scal, mc);
    hgemm<1><<<dim3(4, 512), 256, G1_SMEM>>>(Hh, Hl, ah, al,
                                             out, Ah, Al, scal, mc, nullptr);
}

extern "C" void kernel_launch(void* const* d_in, const int* in_sizes, int n_in,
                              void* d_out, int out_size)
{
    (void)in_sizes; (void)n_in; (void)out_size;
    const float* x  = (const float*)d_in[0];
    const float* W0 = (const float*)d_in[1];
    const float* W1 = (const float*)d_in[2];
    const float* W2 = (const float*)d_in[3];
    float* out = (float*)d_out;

    cudaFuncSetAttribute(hgemm<0>, cudaFuncAttributeMaxDynamicSharedMemorySize, G1_SMEM);
    cudaFuncSetAttribute(hgemm<1>, cudaFuncAttributeMaxDynamicSharedMemorySize, G1_SMEM);
    cudaFuncSetAttribute(hcov,     cudaFuncAttributeMaxDynamicSharedMemorySize, CV_SMEM);

    __nv_bfloat16 *Ah, *Al;
    cudaGetSymbolAddress((void**)&Ah, g_Ah);
    cudaGetSymbolAddress((void**)&Al, g_Al);

    split_f32<<<(NROWS * DD) / (256 * 4), 256>>>(x, Ah, Al);

    run_layer(W0, out, 0);
    run_layer(W1, out + (size_t)NROWS * DD, 1);
    run_layer(W2, out + (size_t)2 * NROWS * DD, 2);
}

// round 9
// speedup vs baseline: 1.4962x; 1.3344x over previous
#include <cuda_runtime.h>
#include <cuda_bf16.h>
#include <cstdint>
#include <math.h>

#define NROWS 65536
#define DD    512
#define KSPLIT 64
#define KCHUNK (NROWS / KSPLIT)   // 1024
#define NS_ITERS 10
#define INV_TEMP 0.1f

// ---------------------------------------------------------------------------
// Static device scratch
// ---------------------------------------------------------------------------
__device__ float g_covp[(size_t)KSPLIT * DD * DD];   // 64 MB (input Gram only)
__device__ float g_G[DD * DD];
__device__ float g_S[DD * DD];
__device__ float g_P[DD * DD];
__device__ float g_Pn[DD * DD];
__device__ float g_colp[DD * 512];                   // [col][rowblock]
__device__ float g_mean[DD];                          // mean of layer input
__device__ float g_mH[DD];                            // mean of H (analytic)
__device__ float g_mc[DD];
__device__ float g_scalars[4];
__device__ __nv_bfloat16 g_Ah[(size_t)NROWS * DD];   // ping
__device__ __nv_bfloat16 g_Al[(size_t)NROWS * DD];
__device__ __nv_bfloat16 g_Hh[(size_t)NROWS * DD];   // pong
__device__ __nv_bfloat16 g_Hl[(size_t)NROWS * DD];
__device__ __nv_bfloat16 g_Wh[DD * DD];
__device__ __nv_bfloat16 g_Wl[DD * DD];
__device__ __nv_bfloat16 g_Sh[DD * DD], g_Sl[DD * DD];
__device__ __nv_bfloat16 g_Pah[DD * DD], g_Pal[DD * DD];
__device__ __nv_bfloat16 g_Pbh[DD * DD], g_Pbl[DD * DD];
__device__ __nv_bfloat16 g_T1h[DD * DD], g_T1l[DD * DD];
__device__ __nv_bfloat16 g_T2h[DD * DD], g_T2l[DD * DD];
__device__ __nv_bfloat16 g_Uh[DD * DD],  g_Ul[DD * DD];   // W^T splits / Weff splits
__device__ __nv_bfloat16 g_GOh[DD * DD], g_GOl[DD * DD];  // input-Gram splits
__device__ __nv_bfloat16 g_Gch[DD * DD], g_Gcl[DD * DD];

// ---------------------------------------------------------------------------
// PTX helpers
// ---------------------------------------------------------------------------
__device__ __forceinline__ uint32_t smem_u32(const void* p) {
    uint32_t a;
    asm("{ .reg .u64 t; cvta.to.shared.u64 t, %1; cvt.u32.u64 %0, t; }"
        : "=r"(a) : "l"(p));
    return a;
}
__device__ __forceinline__ void cpa16(uint32_t dst, const void* src) {
    asm volatile("cp.async.cg.shared.global [%0], [%1], 16;"
                 :: "r"(dst), "l"(src) : "memory");
}
#define CP_COMMIT() asm volatile("cp.async.commit_group;" ::: "memory")
#define CP_WAIT0()  asm volatile("cp.async.wait_group 0;" ::: "memory")

__device__ __forceinline__ void ldsm4(uint32_t* r, uint32_t a) {
    asm volatile("ldmatrix.sync.aligned.m8n8.x4.shared.b16 {%0,%1,%2,%3}, [%4];"
        : "=r"(r[0]), "=r"(r[1]), "=r"(r[2]), "=r"(r[3]) : "r"(a));
}
__device__ __forceinline__ void ldsm4t(uint32_t* r, uint32_t a) {
    asm volatile("ldmatrix.sync.aligned.m8n8.x4.trans.shared.b16 {%0,%1,%2,%3}, [%4];"
        : "=r"(r[0]), "=r"(r[1]), "=r"(r[2]), "=r"(r[3]) : "r"(a));
}
__device__ __forceinline__ void mma_bf16(float* d, const uint32_t* a, const uint32_t* b) {
    asm volatile("mma.sync.aligned.m16n8k16.row.col.f32.bf16.bf16.f32 "
        "{%0,%1,%2,%3}, {%4,%5,%6,%7}, {%8,%9}, {%0,%1,%2,%3};"
        : "+f"(d[0]), "+f"(d[1]), "+f"(d[2]), "+f"(d[3])
        : "r"(a[0]), "r"(a[1]), "r"(a[2]), "r"(a[3]), "r"(b[0]), "r"(b[1]));
}

__device__ __forceinline__ void split1(float v, __nv_bfloat16& h, __nv_bfloat16& l) {
    h = __float2bfloat16_rn(v);
    l = __float2bfloat16_rn(v - __bfloat162float(h));
}
__device__ __forceinline__ void store_split1(__nv_bfloat16* Xh, __nv_bfloat16* Xl,
                                             size_t off, float v) {
    split1(v, Xh[off], Xl[off]);
}
__device__ __forceinline__ void store_split2(__nv_bfloat16* Xh, __nv_bfloat16* Xl,
                                             size_t off, float a, float b) {
    __nv_bfloat16 ha, la, hb, lb;
    split1(a, ha, la);
    split1(b, hb, lb);
    *(uint32_t*)(Xh + off) =
        ((uint32_t)__bfloat16_as_ushort(hb) << 16) | __bfloat16_as_ushort(ha);
    *(uint32_t*)(Xl + off) =
        ((uint32_t)__bfloat16_as_ushort(lb) << 16) | __bfloat16_as_ushort(la);
}

__global__ void split_f32(const float* __restrict__ X,
                          __nv_bfloat16* __restrict__ Xh, __nv_bfloat16* __restrict__ Xl)
{
    const size_t i = ((size_t)blockIdx.x * blockDim.x + threadIdx.x) * 4;
    float4 v = *(const float4*)(X + i);
    __nv_bfloat16 h[4], l[4];
    split1(v.x, h[0], l[0]); split1(v.y, h[1], l[1]);
    split1(v.z, h[2], l[2]); split1(v.w, h[3], l[3]);
    *(uint64_t*)(Xh + i) = *(const uint64_t*)h;
    *(uint64_t*)(Xl + i) = *(const uint64_t*)l;
}

// transpose + split: U[i][k] = W[k][i]
__global__ void tsplit(const float* __restrict__ W,
                       __nv_bfloat16* __restrict__ Uh, __nv_bfloat16* __restrict__ Ul)
{
    __shared__ float t[32][33];
    const int bx = blockIdx.x * 32;
    const int by = blockIdx.y * 32;
    const int tx = threadIdx.x, ty = threadIdx.y;
    t[ty][tx] = W[(size_t)(by + ty) * DD + bx + tx];
    __syncthreads();
    const float v = t[tx][ty];
    const size_t o = (size_t)(bx + ty) * DD + by + tx;
    split1(v, Uh[o], Ul[o]);
}

// plain split of a 512x512 fp32 matrix
__global__ void gsplit(const float* __restrict__ G,
                       __nv_bfloat16* __restrict__ Gh, __nv_bfloat16* __restrict__ Gl)
{
    const int i = blockIdx.x, j = threadIdx.x;
    split1(G[i * DD + j], Gh[i * DD + j], Gl[i * DD + j]);
}

// Gc = G - n * mH mH^T  -> splits
__global__ void gc_split(const float* __restrict__ G, const float* __restrict__ mH,
                         __nv_bfloat16* __restrict__ Gch, __nv_bfloat16* __restrict__ Gcl)
{
    const int i = blockIdx.x, j = threadIdx.x;
    const float v = G[i * DD + j] - (float)NROWS * mH[i] * mH[j];
    split1(v, Gch[i * DD + j], Gcl[i * DD + j]);
}

// column-sum partials of fp32 X [NROWS][DD] -> colp[col][rowblock]
__global__ void colsum_x(const float* __restrict__ X, float* __restrict__ colp)
{
    const int c0 = blockIdx.x * 128;
    const int r0 = blockIdx.y * 128;
    const int t = threadIdx.x;
    float s = 0.0f;
    for (int r = 0; r < 128; r++)
        s += X[(size_t)(r0 + r) * DD + c0 + t];
    colp[(size_t)(c0 + t) * 512 + blockIdx.y] = s;
}

// ---------------------------------------------------------------------------
// Big output GEMM: out = in @ Weff - mc  (bf16 3-term emulation)
// LAST=0: also write splits of out (next layer input) + fused column sums
// ---------------------------------------------------------------------------
#define LDA 80
#define LDB 272
#define A_TILE (128 * LDA)
#define B_TILE (32 * LDB)
#define G1_STAGE (2 * A_TILE + 2 * B_TILE)   // 37888
#define G1_SMEM (2 * G1_STAGE)               // 75776

template<int LAST>
__global__ void __launch_bounds__(256)
hgemm_out(const __nv_bfloat16* __restrict__ Ah, const __nv_bfloat16* __restrict__ Al,
          const __nv_bfloat16* __restrict__ Bh, const __nv_bfloat16* __restrict__ Bl,
          float* __restrict__ Cf32,
          __nv_bfloat16* __restrict__ Ch, __nv_bfloat16* __restrict__ Cl,
          const float* __restrict__ mc, float* __restrict__ colp)
{
    extern __shared__ __align__(16) char smem[];
    const uint32_t sb = smem_u32(smem);
    const int tid = threadIdx.x;
    const int lane = tid & 31;
    const int wid = tid >> 5;
    const int m0 = blockIdx.y * 128;
    const int n0 = blockIdx.x * 128;
    const int wm = (wid & 1) * 64;
    const int wn = (wid >> 1) * 32;

    float acc[4][4][4] = {};

    auto loadStage = [&](int c, int s) {
        const uint32_t base = sb + s * G1_STAGE;
        const int k0 = c * 32;
#pragma unroll
        for (int rep = 0; rep < 4; rep++) {
            const int idx = rep * 256 + tid;
            const int half = idx >> 9, r = (idx >> 2) & 127, ch = idx & 3;
            const __nv_bfloat16* src =
                (half ? Al : Ah) + (size_t)(m0 + r) * DD + k0 + ch * 8;
            cpa16(base + half * A_TILE + r * LDA + ch * 16, src);
        }
#pragma unroll
        for (int rep = 0; rep < 4; rep++) {
            const int idx = rep * 256 + tid;
            const int half = idx >> 9, r = (idx >> 4) & 31, ch = idx & 15;
            const __nv_bfloat16* src =
                (half ? Bl : Bh) + (size_t)(k0 + r) * DD + n0 + ch * 8;
            cpa16(base + 2 * A_TILE + half * B_TILE + r * LDB + ch * 16, src);
        }
        CP_COMMIT();
    };

    const int NC = DD / 32;
    loadStage(0, 0);

    for (int c = 0; c < NC; c++) {
        CP_WAIT0();
        __syncthreads();
        if (c + 1 < NC) loadStage(c + 1, (c + 1) & 1);
        const uint32_t st = sb + (c & 1) * G1_STAGE;

#pragma unroll
        for (int ks = 0; ks < 2; ks++) {
            uint32_t ah[4][4], al[4][4];
            const uint32_t abase = st + (lane & 15) * LDA + ks * 32 + (lane >> 4) * 16;
#pragma unroll
            for (int mt = 0; mt < 4; mt++) {
                ldsm4(ah[mt], abase + (wm + mt * 16) * LDA);
                ldsm4(al[mt], abase + A_TILE + (wm + mt * 16) * LDA);
            }
            const uint32_t brow = ks * 16 + (lane & 7) + ((lane >> 3) & 1) * 8;
            const uint32_t bbase = st + 2 * A_TILE + brow * LDB + wn * 2 + (lane >> 4) * 16;
            uint32_t bh[2][4], bl[2][4];
            ldsm4t(bh[0], bbase);
            ldsm4t(bh[1], bbase + 32);
            ldsm4t(bl[0], bbase + B_TILE);
            ldsm4t(bl[1], bbase + B_TILE + 32);

#pragma unroll
            for (int mt = 0; mt < 4; mt++)
#pragma unroll
                for (int nt = 0; nt < 4; nt++) {
                    const uint32_t* ph = &bh[nt >> 1][(nt & 1) * 2];
                    const uint32_t* pl = &bl[nt >> 1][(nt & 1) * 2];
                    mma_bf16(acc[mt][nt], ah[mt], ph);
                    mma_bf16(acc[mt][nt], ah[mt], pl);
                    mma_bf16(acc[mt][nt], al[mt], ph);
                }
        }
    }

    const int g = lane >> 2, t4 = lane & 3;
    // subtract mc in place, then store fp32 (+ splits)
#pragma unroll
    for (int mt = 0; mt < 4; mt++) {
        const int r0 = m0 + wm + mt * 16 + g;
#pragma unroll
        for (int nt = 0; nt < 4; nt++) {
            const int cc = n0 + wn + nt * 8 + 2 * t4;
            const float2 m2 = *(const float2*)&mc[cc];
            acc[mt][nt][0] -= m2.x;
            acc[mt][nt][1] -= m2.y;
            acc[mt][nt][2] -= m2.x;
            acc[mt][nt][3] -= m2.y;
            *(float2*)&Cf32[(size_t)r0 * DD + cc] =
                make_float2(acc[mt][nt][0], acc[mt][nt][1]);
            *(float2*)&Cf32[(size_t)(r0 + 8) * DD + cc] =
                make_float2(acc[mt][nt][2], acc[mt][nt][3]);
            if (!LAST) {
                store_split2(Ch, Cl, (size_t)r0 * DD + cc,
                             acc[mt][nt][0], acc[mt][nt][1]);
                store_split2(Ch, Cl, (size_t)(r0 + 8) * DD + cc,
                             acc[mt][nt][2], acc[mt][nt][3]);
            }
        }
    }

    if (!LAST) {
        float cs[4][2];
#pragma unroll
        for (int nt = 0; nt < 4; nt++) {
            cs[nt][0] = 0.0f; cs[nt][1] = 0.0f;
#pragma unroll
            for (int mt = 0; mt < 4; mt++) {
                cs[nt][0] += acc[mt][nt][0] + acc[mt][nt][2];
                cs[nt][1] += acc[mt][nt][1] + acc[mt][nt][3];
            }
        }
#pragma unroll
        for (int off = 4; off <= 16; off <<= 1)
#pragma unroll
            for (int nt = 0; nt < 4; nt++) {
                cs[nt][0] += __shfl_xor_sync(0xffffffffu, cs[nt][0], off);
                cs[nt][1] += __shfl_xor_sync(0xffffffffu, cs[nt][1], off);
            }
        float* smcs = (float*)smem;
        __syncthreads();
        if ((wid & 1) == 0 && g == 0) {
#pragma unroll
            for (int nt = 0; nt < 4; nt++) {
                const int c0 = wn + nt * 8 + 2 * t4;
                smcs[c0] = cs[nt][0];
                smcs[c0 + 1] = cs[nt][1];
            }
        }
        __syncthreads();
        if ((wid & 1) == 1 && g == 0) {
#pragma unroll
            for (int nt = 0; nt < 4; nt++) {
                const int c0 = wn + nt * 8 + 2 * t4;
                colp[(size_t)(n0 + c0) * 512 + blockIdx.y] = smcs[c0] + cs[nt][0];
                colp[(size_t)(n0 + c0 + 1) * 512 + blockIdx.y] = smcs[c0 + 1] + cs[nt][1];
            }
        }
    }
}

// ---------------------------------------------------------------------------
// Input Gram split-K (upper-triangle tiles) — run ONCE on x
// ---------------------------------------------------------------------------
#define CV_STAGE (4 * B_TILE)      // 34816
#define CV_SMEM (2 * CV_STAGE)     // 69632

__global__ void __launch_bounds__(256)
hcov(const __nv_bfloat16* __restrict__ Hh, const __nv_bfloat16* __restrict__ Hl,
     float* __restrict__ Cp)
{
    extern __shared__ __align__(16) char smem[];
    const uint32_t sb = smem_u32(smem);
    const int tid = threadIdx.x;
    const int lane = tid & 31;
    const int wid = tid >> 5;
    const int bx = blockIdx.x;
    const int bi = (bx < 4) ? 0 : (bx < 7) ? 1 : (bx < 9) ? 2 : 3;
    const int bj = bx - ((bi == 0) ? 0 : (bi == 1) ? 3 : (bi == 2) ? 5 : 6);
    const int i0 = bi * 128;
    const int j0 = bj * 128;
    const int z  = blockIdx.z;
    const int wm = (wid & 1) * 64;
    const int wn = (wid >> 1) * 32;

    float acc[4][4][4] = {};

    auto loadStage = [&](int c, int s) {
        const uint32_t base = sb + s * CV_STAGE;
        const int nbase = z * KCHUNK + c * 32;
#pragma unroll
        for (int rep = 0; rep < 8; rep++) {
            const int idx = rep * 256 + tid;
            const int tile = idx >> 9;
            const int r = (idx >> 4) & 31, ch = idx & 15;
            const __nv_bfloat16* basep = (tile & 1) ? Hl : Hh;
            const int coff = (tile < 2) ? i0 : j0;
            const __nv_bfloat16* src = basep + (size_t)(nbase + r) * DD + coff + ch * 8;
            cpa16(base + tile * B_TILE + r * LDB + ch * 16, src);
        }
        CP_COMMIT();
    };

    const int NC = KCHUNK / 32;
    loadStage(0, 0);

    for (int c = 0; c < NC; c++) {
        CP_WAIT0();
        __syncthreads();
        if (c + 1 < NC) loadStage(c + 1, (c + 1) & 1);
        const uint32_t st = sb + (c & 1) * CV_STAGE;

#pragma unroll
        for (int ks = 0; ks < 2; ks++) {
            const uint32_t arow = ks * 16 + (lane & 7) + ((lane >> 4) & 1) * 8;
            const uint32_t abase = st + arow * LDB + wm * 2 + ((lane >> 3) & 1) * 16;
            uint32_t ah[4][4], al[4][4];
#pragma unroll
            for (int mt = 0; mt < 4; mt++) {
                ldsm4t(ah[mt], abase + mt * 32);
                ldsm4t(al[mt], abase + B_TILE + mt * 32);
            }
            const uint32_t brow = ks * 16 + (lane & 7) + ((lane >> 3) & 1) * 8;
            const uint32_t bbase = st + 2 * B_TILE + brow * LDB + wn * 2 + (lane >> 4) * 16;
            uint32_t bh[2][4], bl[2][4];
            ldsm4t(bh[0], bbase);
            ldsm4t(bh[1], bbase + 32);
            ldsm4t(bl[0], bbase + B_TILE);
            ldsm4t(bl[1], bbase + B_TILE + 32);

#pragma unroll
            for (int mt = 0; mt < 4; mt++)
#pragma unroll
                for (int nt = 0; nt < 4; nt++) {
                    const uint32_t* ph = &bh[nt >> 1][(nt & 1) * 2];
                    const uint32_t* pl = &bl[nt >> 1][(nt & 1) * 2];
                    mma_bf16(acc[mt][nt], ah[mt], ph);
                    mma_bf16(acc[mt][nt], ah[mt], pl);
                    mma_bf16(acc[mt][nt], al[mt], ph);
                }
        }
    }

    float* out = Cp + (size_t)z * DD * DD;
    const int g = lane >> 2, t4 = lane & 3;
#pragma unroll
    for (int mt = 0; mt < 4; mt++) {
        const int r0 = i0 + wm + mt * 16 + g;
#pragma unroll
        for (int nt = 0; nt < 4; nt++) {
            const int cc = j0 + wn + nt * 8 + 2 * t4;
            float2 v0 = {acc[mt][nt][0], acc[mt][nt][1]};
            float2 v1 = {acc[mt][nt][2], acc[mt][nt][3]};
            *(float2*)&out[(size_t)r0 * DD + cc] = v0;
            *(float2*)&out[(size_t)(r0 + 8) * DD + cc] = v1;
        }
    }
}

__global__ void reduce_cov_sym(const float* __restrict__ Cp, float* __restrict__ G)
{
    const int i = blockIdx.x, j = threadIdx.x;
    if (j < i) return;
    float s = 0.0f;
#pragma unroll 8
    for (int zz = 0; zz < KSPLIT; zz++)
        s += Cp[(size_t)zz * DD * DD + i * DD + j];
    G[i * DD + j] = s;
    G[j * DD + i] = s;
}

// ---------------------------------------------------------------------------
// Small GEMM core (64x64 tiles, 128 threads)
// ---------------------------------------------------------------------------
#define NS_LDA 80
#define NS_AT  (64 * NS_LDA)
#define NS_LDB 144
#define NS_BT  (32 * NS_LDB)
#define NS_STAGE (2 * NS_AT + 2 * NS_BT)
#define NS_SMEM  (2 * NS_STAGE)

struct NsAcc { float a[2][4][4]; };

__device__ __forceinline__ void ns_tri(int bx, int& ti, int& tj) {
    int t = 0, rem = bx;
    while (rem >= 8 - t) { rem -= 8 - t; t++; }
    ti = t; tj = t + rem;
}

__device__ __forceinline__ void ns_core(
    const __nv_bfloat16* __restrict__ Ah, const __nv_bfloat16* __restrict__ Al,
    const __nv_bfloat16* __restrict__ Bh, const __nv_bfloat16* __restrict__ Bl,
    int m0, int n0, uint32_t sb, NsAcc& A)
{
    const int tid = threadIdx.x;
    const int lane = tid & 31;
    const int wid = tid >> 5;
    const int wm = (wid & 1) * 32;
    const int wn = (wid >> 1) * 32;

    auto loadStage = [&](int c, int s) {
        const uint32_t base = sb + s * NS_STAGE;
        const int k0 = c * 32;
#pragma unroll
        for (int rep = 0; rep < 8; rep++) {
            const int idx = rep * 128 + tid;
            if (idx < 512) {
                const int half = idx >> 8, r = (idx >> 2) & 63, ch = idx & 3;
                const __nv_bfloat16* src =
                    (half ? Al : Ah) + (size_t)(m0 + r) * DD + k0 + ch * 8;
                cpa16(base + half * NS_AT + r * NS_LDA + ch * 16, src);
            } else {
                const int j = idx - 512;
                const int half = j >> 8, r = (j >> 3) & 31, ch = j & 7;
                const __nv_bfloat16* src =
                    (half ? Bl : Bh) + (size_t)(k0 + r) * DD + n0 + ch * 8;
                cpa16(base + 2 * NS_AT + half * NS_BT + r * NS_LDB + ch * 16, src);
            }
        }
        CP_COMMIT();
    };

    loadStage(0, 0);

    for (int c = 0; c < DD / 32; c++) {
        CP_WAIT0();
        __syncthreads();
        if (c + 1 < DD / 32) loadStage(c + 1, (c + 1) & 1);
        const uint32_t st = sb + (c & 1) * NS_STAGE;

#pragma unroll
        for (int ks = 0; ks < 2; ks++) {
            uint32_t ah[2][4], al[2][4];
            const uint32_t abase = st + (lane & 15) * NS_LDA + ks * 32 + (lane >> 4) * 16;
#pragma unroll
            for (int mt = 0; mt < 2; mt++) {
                ldsm4(ah[mt], abase + (wm + mt * 16) * NS_LDA);
                ldsm4(al[mt], abase + NS_AT + (wm + mt * 16) * NS_LDA);
            }
            const uint32_t brow = ks * 16 + (lane & 7) + ((lane >> 3) & 1) * 8;
            const uint32_t bbase = st + 2 * NS_AT + brow * NS_LDB + wn * 2 + (lane >> 4) * 16;
            uint32_t bh[2][4], bl[2][4];
            ldsm4t(bh[0], bbase);
            ldsm4t(bh[1], bbase + 32);
            ldsm4t(bl[0], bbase + NS_BT);
            ldsm4t(bl[1], bbase + NS_BT + 32);

#pragma unroll
            for (int mt = 0; mt < 2; mt++)
#pragma unroll
                for (int nt = 0; nt < 4; nt++) {
                    const uint32_t* ph = &bh[nt >> 1][(nt & 1) * 2];
                    const uint32_t* pl = &bl[nt >> 1][(nt & 1) * 2];
                    mma_bf16(A.a[mt][nt], ah[mt], ph);
                    mma_bf16(A.a[mt][nt], ah[mt], pl);
                    mma_bf16(A.a[mt][nt], al[mt], ph);
                }
        }
    }
}

// Generic small GEMM: C = scale * (A @ B), grid (8,8).
// SCALE: 0 -> 1.0 ; 1 -> scalars[2]^2 ; 2 -> scalars[2]
template<int SCALE, int OF32, int OSPLIT>
__global__ void __launch_bounds__(128)
sg(const __nv_bfloat16* __restrict__ Ah, const __nv_bfloat16* __restrict__ Al,
   const __nv_bfloat16* __restrict__ Bh, const __nv_bfloat16* __restrict__ Bl,
   float* __restrict__ Cf32,
   __nv_bfloat16* __restrict__ Ch, __nv_bfloat16* __restrict__ Cl,
   const float* __restrict__ scalars)
{
    __shared__ __align__(16) char smem[NS_SMEM];
    const uint32_t sb = smem_u32(smem);
    const int m0 = blockIdx.y * 64;
    const int n0 = blockIdx.x * 64;
    const int lane = threadIdx.x & 31;
    const int wid = threadIdx.x >> 5;
    const int wm = (wid & 1) * 32;
    const int wn = (wid >> 1) * 32;

    NsAcc A = {};
    ns_core(Ah, Al, Bh, Bl, m0, n0, sb, A);

    float sc = 1.0f;
    if (SCALE == 1) sc = scalars[2] * scalars[2];
    if (SCALE == 2) sc = scalars[2];
    const int g = lane >> 2, t4 = lane & 3;
#pragma unroll
    for (int mt = 0; mt < 2; mt++) {
        const int r0 = m0 + wm + mt * 16 + g;
#pragma unroll
        for (int nt = 0; nt < 4; nt++) {
            const int cc = n0 + wn + nt * 8 + 2 * t4;
#pragma unroll
            for (int half = 0; half < 2; half++) {
                const size_t idx = (size_t)(r0 + half * 8) * DD + cc;
                const float v0 = A.a[mt][nt][half * 2 + 0] * sc;
                const float v1 = A.a[mt][nt][half * 2 + 1] * sc;
                if (OF32) *(float2*)&Cf32[idx] = make_float2(v0, v1);
                if (OSPLIT) store_split2(Ch, Cl, idx, v0, v1);
            }
        }
    }
}

// grid (36,1,2): z=0 -> T1 = P @ S ; z=1 -> T2 = P @ P ; symmetric, mirrored
__global__ void __launch_bounds__(128)
ns_pair(const __nv_bfloat16* __restrict__ Pah, const __nv_bfloat16* __restrict__ Pal,
        const __nv_bfloat16* __restrict__ Sh,  const __nv_bfloat16* __restrict__ Sl,
        __nv_bfloat16* __restrict__ T1h, __nv_bfloat16* __restrict__ T1l,
        __nv_bfloat16* __restrict__ T2h, __nv_bfloat16* __restrict__ T2l)
{
    __shared__ __align__(16) char smem[NS_SMEM];
    const uint32_t sb = smem_u32(smem);
    int ti, tj;
    ns_tri(blockIdx.x, ti, tj);
    const int m0 = ti * 64;
    const int n0 = tj * 64;
    const int lane = threadIdx.x & 31;
    const int wid = threadIdx.x >> 5;
    const int wm = (wid & 1) * 32;
    const int wn = (wid >> 1) * 32;

    NsAcc A = {};
    const __nv_bfloat16* Bh = blockIdx.z ? Pah : Sh;
    const __nv_bfloat16* Bl = blockIdx.z ? Pal : Sl;
    ns_core(Pah, Pal, Bh, Bl, m0, n0, sb, A);

    __nv_bfloat16* Oh = blockIdx.z ? T2h : T1h;
    __nv_bfloat16* Ol = blockIdx.z ? T2l : T1l;
    const int g = lane >> 2, t4 = lane & 3;
    const bool mir = (ti != tj);
#pragma unroll
    for (int mt = 0; mt < 2; mt++) {
        const int r0 = m0 + wm + mt * 16 + g;
#pragma unroll
        for (int nt = 0; nt < 4; nt++) {
            const int cc = n0 + wn + nt * 8 + 2 * t4;
            const float v0 = A.a[mt][nt][0], v1 = A.a[mt][nt][1];
            const float v2 = A.a[mt][nt][2], v3 = A.a[mt][nt][3];
            store_split2(Oh, Ol, (size_t)r0 * DD + cc, v0, v1);
            store_split2(Oh, Ol, (size_t)(r0 + 8) * DD + cc, v2, v3);
            if (mir) {
                store_split1(Oh, Ol, (size_t)cc * DD + r0, v0);
                store_split1(Oh, Ol, (size_t)(cc + 1) * DD + r0, v1);
                store_split1(Oh, Ol, (size_t)cc * DD + r0 + 8, v2);
                store_split1(Oh, Ol, (size_t)(cc + 1) * DD + r0 + 8, v3);
            }
        }
    }
}

// grid (36): Pb = 1.5*Pold - 0.5*(T2 @ T1); symmetric, mirrored; fp32 + splits
__global__ void __launch_bounds__(128)
ns_update(const __nv_bfloat16* __restrict__ T2h, const __nv_bfloat16* __restrict__ T2l,
          const __nv_bfloat16* __restrict__ T1h, const __nv_bfloat16* __restrict__ T1l,
          const float* __restrict__ Pold, float* __restrict__ Pnew,
          __nv_bfloat16* __restrict__ Pnh, __nv_bfloat16* __restrict__ Pnl)
{
    __shared__ __align__(16) char smem[NS_SMEM];
    const uint32_t sb = smem_u32(smem);
    int ti, tj;
    ns_tri(blockIdx.x, ti, tj);
    const int m0 = ti * 64;
    const int n0 = tj * 64;
    const int lane = threadIdx.x & 31;
    const int wid = threadIdx.x >> 5;
    const int wm = (wid & 1) * 32;
    const int wn = (wid >> 1) * 32;

    NsAcc A = {};
    ns_core(T2h, T2l, T1h, T1l, m0, n0, sb, A);

    const int g = lane >> 2, t4 = lane & 3;
    const bool mir = (ti != tj);
#pragma unroll
    for (int mt = 0; mt < 2; mt++) {
        const int r0 = m0 + wm + mt * 16 + g;
#pragma unroll
        for (int nt = 0; nt < 4; nt++) {
            const int cc = n0 + wn + nt * 8 + 2 * t4;
#pragma unroll
            for (int half = 0; half < 2; half++) {
                const int r = r0 + half * 8;
                const size_t idx = (size_t)r * DD + cc;
                const float2 po = *(const float2*)&Pold[idx];
                const float v0 = 1.5f * po.x - 0.5f * A.a[mt][nt][half * 2 + 0];
                const float v1 = 1.5f * po.y - 0.5f * A.a[mt][nt][half * 2 + 1];
                *(float2*)&Pnew[idx] = make_float2(v0, v1);
                store_split2(Pnh, Pnl, idx, v0, v1);
                if (mir) {
                    Pnew[(size_t)cc * DD + r] = v0;
                    Pnew[(size_t)(cc + 1) * DD + r] = v1;
                    store_split1(Pnh, Pnl, (size_t)cc * DD + r, v0);
                    store_split1(Pnh, Pnl, (size_t)(cc + 1) * DD + r, v1);
                }
            }
        }
    }
}

// iteration 1 closed-form: P1 = 1.5 I - 0.5 S
__global__ void p1_kernel(const float* __restrict__ S, float* __restrict__ P,
                          __nv_bfloat16* __restrict__ Ph, __nv_bfloat16* __restrict__ Pl)
{
    const int i = blockIdx.x, j = threadIdx.x;
    const float v = ((i == j) ? 1.5f : 0.0f) - 0.5f * S[i * DD + j];
    P[i * DD + j] = v;
    split1(v, Ph[i * DD + j], Pl[i * DD + j]);
}

// ---------------------------------------------------------------------------
// Mean / trace / S / vector helpers
// ---------------------------------------------------------------------------
__global__ void mean_finalize(const float* __restrict__ colp, float* __restrict__ mean)
{
    __shared__ float sm[128];
    const int j = blockIdx.x;
    const int t = threadIdx.x;
    const float4 v = *(const float4*)(colp + (size_t)j * 512 + t * 4);
    sm[t] = v.x + v.y + v.z + v.w;
    __syncthreads();
    for (int s = 64; s > 0; s >>= 1) {
        if (t < s) sm[t] += sm[t + s];
        __syncthreads();
    }
    if (t == 0) mean[j] = sm[0] * (1.0f / (float)NROWS);
}

__global__ void trace_kernel(const float* __restrict__ G,
                             const float* __restrict__ mH,
                             float* __restrict__ scalars)
{
    __shared__ float sm[512];
    const int i = threadIdx.x;
    const float m = mH[i];
    sm[i] = G[i * DD + i] * (1.0f / (float)NROWS) - m * m + INV_TEMP;
    __syncthreads();
    for (int s = 256; s > 0; s >>= 1) {
        if (i < s) sm[i] += sm[i + s];
        __syncthreads();
    }
    if (i == 0) {
        const float tr = sm[0];
        scalars[0] = tr;
        scalars[1] = 1.0f / tr;
        scalars[2] = rsqrtf(tr);
    }
}

__global__ void s_kernel(const float* __restrict__ G,
                         const float* __restrict__ mH,
                         const float* __restrict__ scalars,
                         float* __restrict__ S,
                         __nv_bfloat16* __restrict__ Sh, __nv_bfloat16* __restrict__ Sl)
{
    const int i = blockIdx.x, j = threadIdx.x;
    const float invtr = scalars[1];
    float v = G[i * DD + j] * (1.0f / (float)NROWS) - mH[i] * mH[j];
    if (i == j) v += INV_TEMP;
    v *= invtr;
    S[i * DD + j] = v;
    split1(v, Sh[i * DD + j], Sl[i * DD + j]);
}

// mH = mean_prev @ W
__global__ void meanW(const float* __restrict__ mp, const float* __restrict__ W,
                      float* __restrict__ mH)
{
    const int j = blockIdx.x * 128 + threadIdx.x;
    float s = 0.0f;
#pragma unroll 8
    for (int k = 0; k < DD; k++)
        s += mp[k] * W[(size_t)k * DD + j];
    mH[j] = s;
}

// mc = s2 * mH @ P
__global__ void mc_kernel(const float* __restrict__ mH, const float* __restrict__ P,
                          const float* __restrict__ scalars, float* __restrict__ mc)
{
    const int j = blockIdx.x * 128 + threadIdx.x;
    float s = 0.0f;
#pragma unroll 8
    for (int k = 0; k < DD; k++)
        s += mH[k] * P[(size_t)k * DD + j];
    mc[j] = s * scalars[2];
}

// ---------------------------------------------------------------------------
// Host orchestration
// ---------------------------------------------------------------------------
static void run_layer(const float* W, float* out,
                      __nv_bfloat16* inh, __nv_bfloat16* inl,
                      __nv_bfloat16* outh, __nv_bfloat16* outl, int last)
{
    float *G, *S, *P, *Pn, *colp, *mean, *mH, *mc, *scal;
    __nv_bfloat16 *Wh, *Wl, *Sh, *Sl;
    __nv_bfloat16 *Pah, *Pal, *Pbh, *Pbl, *T1h, *T1l, *T2h, *T2l;
    __nv_bfloat16 *Uh, *Ul, *GOh, *GOl, *Gch, *Gcl;
    cudaGetSymbolAddress((void**)&G,    g_G);
    cudaGetSymbolAddress((void**)&S,    g_S);
    cudaGetSymbolAddress((void**)&P,    g_P);
    cudaGetSymbolAddress((void**)&Pn,   g_Pn);
    cudaGetSymbolAddress((void**)&colp, g_colp);
    cudaGetSymbolAddress((void**)&mean, g_mean);
    cudaGetSymbolAddress((void**)&mH,   g_mH);
    cudaGetSymbolAddress((void**)&mc,   g_mc);
    cudaGetSymbolAddress((void**)&scal, g_scalars);
    cudaGetSymbolAddress((void**)&Wh,   g_Wh);
    cudaGetSymbolAddress((void**)&Wl,   g_Wl);
    cudaGetSymbolAddress((void**)&Sh,   g_Sh);
    cudaGetSymbolAddress((void**)&Sl,   g_Sl);
    cudaGetSymbolAddress((void**)&Pah,  g_Pah);
    cudaGetSymbolAddress((void**)&Pal,  g_Pal);
    cudaGetSymbolAddress((void**)&Pbh,  g_Pbh);
    cudaGetSymbolAddress((void**)&Pbl,  g_Pbl);
    cudaGetSymbolAddress((void**)&T1h,  g_T1h);
    cudaGetSymbolAddress((void**)&T1l,  g_T1l);
    cudaGetSymbolAddress((void**)&T2h,  g_T2h);
    cudaGetSymbolAddress((void**)&T2l,  g_T2l);
    cudaGetSymbolAddress((void**)&Uh,   g_Uh);
    cudaGetSymbolAddress((void**)&Ul,   g_Ul);
    cudaGetSymbolAddress((void**)&GOh,  g_GOh);
    cudaGetSymbolAddress((void**)&GOl,  g_GOl);
    cudaGetSymbolAddress((void**)&Gch,  g_Gch);
    cudaGetSymbolAddress((void**)&Gcl,  g_Gcl);

    const int wBlocks = (DD * DD) / (256 * 4);

    // W splits + mean_H = mean_prev @ W
    split_f32<<<wBlocks, 256>>>(W, Wh, Wl);
    meanW<<<4, 128>>>(mean, W, mH);

    // G_H = W^T @ G_in @ W  (G_in splits in GOh/GOl)
    tsplit<<<dim3(16, 16), dim3(32, 32)>>>(W, Uh, Ul);
    sg<0, 0, 1><<<dim3(8, 8), 128>>>(Uh, Ul, GOh, GOl, nullptr, T1h, T1l, scal);
    sg<0, 1, 0><<<dim3(8, 8), 128>>>(T1h, T1l, Wh, Wl, G, nullptr, nullptr, scal);

    trace_kernel<<<1, 512>>>(G, mH, scal);
    s_kernel<<<512, 512>>>(G, mH, scal, S, Sh, Sl);

    // Newton-Schulz
    p1_kernel<<<512, 512>>>(S, P, Pah, Pal);
    float* Pf = P; float* Pg = Pn;
    __nv_bfloat16 *ah = Pah, *al = Pal, *bh = Pbh, *bl = Pbl;
    for (int t = 1; t < NS_ITERS; t++) {
        ns_pair<<<dim3(36, 1, 2), 128>>>(ah, al, Sh, Sl, T1h, T1l, T2h, T2l);
        ns_update<<<dim3(36), 128>>>(T2h, T2l, T1h, T1l, Pf, Pg, bh, bl);
        { float* t0 = Pf; Pf = Pg; Pg = t0; }
        { __nv_bfloat16* t1 = ah; ah = bh; bh = t1; }
        { __nv_bfloat16* t2 = al; al = bl; bl = t2; }
    }

    // G_out = s2^2 * P @ (G_H - n mH mH^T) @ P  (input Gram for next layer)
    if (!last) {
        gc_split<<<512, 512>>>(G, mH, Gch, Gcl);
        sg<0, 0, 1><<<dim3(8, 8), 128>>>(ah, al, Gch, Gcl, nullptr, T1h, T1l, scal);
        sg<1, 0, 1><<<dim3(8, 8), 128>>>(T1h, T1l, ah, al, nullptr, GOh, GOl, scal);
    }

    // Weff = s2 * W @ P  (into Uh/Ul; W^T splits dead by now); mc = s2 mH @ P
    sg<2, 0, 1><<<dim3(8, 8), 128>>>(Wh, Wl, ah, al, nullptr, Uh, Ul, scal);
    mc_kernel<<<4, 128>>>(mH, Pf, scal, mc);

    // out = in @ Weff - mc  (single big GEMM; epilogue: splits + colsum)
    if (last) {
        hgemm_out<1><<<dim3(4, 512), 256, G1_SMEM>>>(inh, inl, Uh, Ul,
                                                     out, outh, outl, mc, colp);
    } else {
        hgemm_out<0><<<dim3(4, 512), 256, G1_SMEM>>>(inh, inl, Uh, Ul,
                                                     out, outh, outl, mc, colp);
        mean_finalize<<<512, 128>>>(colp, mean);   // mean_prev for next layer
    }
}

extern "C" void kernel_launch(void* const* d_in, const int* in_sizes, int n_in,
                              void* d_out, int out_size)
{
    (void)in_sizes; (void)n_in; (void)out_size;
    const float* x  = (const float*)d_in[0];
    const float* W0 = (const float*)d_in[1];
    const float* W1 = (const float*)d_in[2];
    const float* W2 = (const float*)d_in[3];
    float* out = (float*)d_out;

    cudaFuncSetAttribute(hgemm_out<0>, cudaFuncAttributeMaxDynamicSharedMemorySize, G1_SMEM);
    cudaFuncSetAttribute(hgemm_out<1>, cudaFuncAttributeMaxDynamicSharedMemorySize, G1_SMEM);
    cudaFuncSetAttribute(hcov,         cudaFuncAttributeMaxDynamicSharedMemorySize, CV_SMEM);

    float *covp, *G, *colp, *mean;
    __nv_bfloat16 *Ah, *Al, *Hh, *Hl, *GOh, *GOl;
    cudaGetSymbolAddress((void**)&covp, g_covp);
    cudaGetSymbolAddress((void**)&G,    g_G);
    cudaGetSymbolAddress((void**)&colp, g_colp);
    cudaGetSymbolAddress((void**)&mean, g_mean);
    cudaGetSymbolAddress((void**)&Ah,   g_Ah);
    cudaGetSymbolAddress((void**)&Al,   g_Al);
    cudaGetSymbolAddress((void**)&Hh,   g_Hh);
    cudaGetSymbolAddress((void**)&Hl,   g_Hl);
    cudaGetSymbolAddress((void**)&GOh,  g_GOh);
    cudaGetSymbolAddress((void**)&GOl,  g_GOl);

    // input preprocessing: splits, mean, Gram (the only big Gram in the run)
    split_f32<<<(NROWS * DD) / (256 * 4), 256>>>(x, Ah, Al);
    colsum_x<<<dim3(4, 512), 128>>>(x, colp);
    mean_finalize<<<512, 128>>>(colp, mean);
    hcov<<<dim3(10, 1, KSPLIT), 256, CV_SMEM>>>(Ah, Al, covp);
    reduce_cov_sym<<<512, 512>>>(covp, G);
    gsplit<<<512, 512>>>(G, GOh, GOl);

    float* o0 = out;
    float* o1 = out + (size_t)NROWS * DD;
    float* o2 = out + (size_t)2 * NROWS * DD;

    run_layer(W0, o0, Ah, Al, Hh, Hl, 0);
    run_layer(W1, o1, Hh, Hl, Ah, Al, 0);
    run_layer(W2, o2, Ah, Al, Hh, Hl, 1);
}

// round 10
// speedup vs baseline: 1.7500x; 1.1696x over previous
#include <cuda_runtime.h>
#include <cuda_bf16.h>
#include <cstdint>
#include <math.h>

#define NROWS 65536
#define DD    512
#define KSPLIT 64
#define KCHUNK (NROWS / KSPLIT)   // 1024
#define NS_ITERS 10
#define INV_TEMP 0.1f

// ---------------------------------------------------------------------------
// Static device scratch
// ---------------------------------------------------------------------------
__device__ float g_covp[(size_t)KSPLIT * DD * DD];   // 64 MB (input Gram only)
__device__ float g_G[DD * DD];
__device__ float g_P[DD * DD];
__device__ float g_Pn[DD * DD];
__device__ float g_colp[DD * 512];                   // [col][rowblock] (x only)
__device__ float g_mean[DD];                          // mean of x
__device__ float g_mH[DD];                            // mean of H0 (analytic)
__device__ float g_mc[DD];
__device__ float g_scalars[4];
__device__ __nv_bfloat16 g_Ah[(size_t)NROWS * DD];   // ping
__device__ __nv_bfloat16 g_Al[(size_t)NROWS * DD];
__device__ __nv_bfloat16 g_Hh[(size_t)NROWS * DD];   // pong
__device__ __nv_bfloat16 g_Hl[(size_t)NROWS * DD];
__device__ __nv_bfloat16 g_Wh[DD * DD];
__device__ __nv_bfloat16 g_Wl[DD * DD];
__device__ __nv_bfloat16 g_Sh[DD * DD], g_Sl[DD * DD];
__device__ __nv_bfloat16 g_Pah[DD * DD], g_Pal[DD * DD];
__device__ __nv_bfloat16 g_Pbh[DD * DD], g_Pbl[DD * DD];
__device__ __nv_bfloat16 g_T1h[DD * DD], g_T1l[DD * DD];
__device__ __nv_bfloat16 g_T2h[DD * DD], g_T2l[DD * DD];
__device__ __nv_bfloat16 g_Uh[DD * DD],  g_Ul[DD * DD];
__device__ __nv_bfloat16 g_GOh[DD * DD], g_GOl[DD * DD];
__device__ __nv_bfloat16 g_Gch[DD * DD], g_Gcl[DD * DD];

// ---------------------------------------------------------------------------
// PTX helpers
// ---------------------------------------------------------------------------
__device__ __forceinline__ uint32_t smem_u32(const void* p) {
    uint32_t a;
    asm("{ .reg .u64 t; cvta.to.shared.u64 t, %1; cvt.u32.u64 %0, t; }"
        : "=r"(a) : "l"(p));
    return a;
}
__device__ __forceinline__ void cpa16(uint32_t dst, const void* src) {
    asm volatile("cp.async.cg.shared.global [%0], [%1], 16;"
                 :: "r"(dst), "l"(src) : "memory");
}
#define CP_COMMIT() asm volatile("cp.async.commit_group;" ::: "memory")
#define CP_WAIT0()  asm volatile("cp.async.wait_group 0;" ::: "memory")

__device__ __forceinline__ void ldsm4(uint32_t* r, uint32_t a) {
    asm volatile("ldmatrix.sync.aligned.m8n8.x4.shared.b16 {%0,%1,%2,%3}, [%4];"
        : "=r"(r[0]), "=r"(r[1]), "=r"(r[2]), "=r"(r[3]) : "r"(a));
}
__device__ __forceinline__ void ldsm4t(uint32_t* r, uint32_t a) {
    asm volatile("ldmatrix.sync.aligned.m8n8.x4.trans.shared.b16 {%0,%1,%2,%3}, [%4];"
        : "=r"(r[0]), "=r"(r[1]), "=r"(r[2]), "=r"(r[3]) : "r"(a));
}
__device__ __forceinline__ void mma_bf16(float* d, const uint32_t* a, const uint32_t* b) {
    asm volatile("mma.sync.aligned.m16n8k16.row.col.f32.bf16.bf16.f32 "
        "{%0,%1,%2,%3}, {%4,%5,%6,%7}, {%8,%9}, {%0,%1,%2,%3};"
        : "+f"(d[0]), "+f"(d[1]), "+f"(d[2]), "+f"(d[3])
        : "r"(a[0]), "r"(a[1]), "r"(a[2]), "r"(a[3]), "r"(b[0]), "r"(b[1]));
}

__device__ __forceinline__ void split1(float v, __nv_bfloat16& h, __nv_bfloat16& l) {
    h = __float2bfloat16_rn(v);
    l = __float2bfloat16_rn(v - __bfloat162float(h));
}
__device__ __forceinline__ void store_split1(__nv_bfloat16* Xh, __nv_bfloat16* Xl,
                                             size_t off, float v) {
    split1(v, Xh[off], Xl[off]);
}
__device__ __forceinline__ void store_split2(__nv_bfloat16* Xh, __nv_bfloat16* Xl,
                                             size_t off, float a, float b) {
    __nv_bfloat16 ha, la, hb, lb;
    split1(a, ha, la);
    split1(b, hb, lb);
    *(uint32_t*)(Xh + off) =
        ((uint32_t)__bfloat16_as_ushort(hb) << 16) | __bfloat16_as_ushort(ha);
    *(uint32_t*)(Xl + off) =
        ((uint32_t)__bfloat16_as_ushort(lb) << 16) | __bfloat16_as_ushort(la);
}

__global__ void split_f32(const float* __restrict__ X,
                          __nv_bfloat16* __restrict__ Xh, __nv_bfloat16* __restrict__ Xl)
{
    const size_t i = ((size_t)blockIdx.x * blockDim.x + threadIdx.x) * 4;
    float4 v = *(const float4*)(X + i);
    __nv_bfloat16 h[4], l[4];
    split1(v.x, h[0], l[0]); split1(v.y, h[1], l[1]);
    split1(v.z, h[2], l[2]); split1(v.w, h[3], l[3]);
    *(uint64_t*)(Xh + i) = *(const uint64_t*)h;
    *(uint64_t*)(Xl + i) = *(const uint64_t*)l;
}

// transpose + split: U[i][k] = W[k][i]
__global__ void tsplit(const float* __restrict__ W,
                       __nv_bfloat16* __restrict__ Uh, __nv_bfloat16* __restrict__ Ul)
{
    __shared__ float t[32][33];
    const int bx = blockIdx.x * 32;
    const int by = blockIdx.y * 32;
    const int tx = threadIdx.x, ty = threadIdx.y;
    t[ty][tx] = W[(size_t)(by + ty) * DD + bx + tx];
    __syncthreads();
    const float v = t[tx][ty];
    const size_t o = (size_t)(bx + ty) * DD + by + tx;
    split1(v, Uh[o], Ul[o]);
}

// plain split of a 512x512 fp32 matrix
__global__ void gsplit(const float* __restrict__ G,
                       __nv_bfloat16* __restrict__ Gh, __nv_bfloat16* __restrict__ Gl)
{
    const int i = blockIdx.x, j = threadIdx.x;
    split1(G[i * DD + j], Gh[i * DD + j], Gl[i * DD + j]);
}

// Gc = G - n * mH mH^T (mH may be null -> Gc = G) -> splits
__global__ void gc_split(const float* __restrict__ G, const float* __restrict__ mH,
                         __nv_bfloat16* __restrict__ Gch, __nv_bfloat16* __restrict__ Gcl)
{
    const int i = blockIdx.x, j = threadIdx.x;
    float v = G[i * DD + j];
    if (mH) v -= (float)NROWS * mH[i] * mH[j];
    split1(v, Gch[i * DD + j], Gcl[i * DD + j]);
}

// column-sum partials of fp32 X [NROWS][DD] -> colp[col][rowblock]
__global__ void colsum_x(const float* __restrict__ X, float* __restrict__ colp)
{
    const int c0 = blockIdx.x * 128;
    const int r0 = blockIdx.y * 128;
    const int t = threadIdx.x;
    float s = 0.0f;
    for (int r = 0; r < 128; r++)
        s += X[(size_t)(r0 + r) * DD + c0 + t];
    colp[(size_t)(c0 + t) * 512 + blockIdx.y] = s;
}

// ---------------------------------------------------------------------------
// Big output GEMM: out = in @ Weff (- mc)  (bf16 3-term emulation)
// MC: subtract mc[col].  LAST=0: also write splits of out.
// ---------------------------------------------------------------------------
#define LDA 80
#define LDB 272
#define A_TILE (128 * LDA)
#define B_TILE (32 * LDB)
#define G1_STAGE (2 * A_TILE + 2 * B_TILE)   // 37888
#define G1_SMEM (2 * G1_STAGE)               // 75776

template<int MC, int LAST>
__global__ void __launch_bounds__(256)
hgemm_out(const __nv_bfloat16* __restrict__ Ah, const __nv_bfloat16* __restrict__ Al,
          const __nv_bfloat16* __restrict__ Bh, const __nv_bfloat16* __restrict__ Bl,
          float* __restrict__ Cf32,
          __nv_bfloat16* __restrict__ Ch, __nv_bfloat16* __restrict__ Cl,
          const float* __restrict__ mc)
{
    extern __shared__ __align__(16) char smem[];
    const uint32_t sb = smem_u32(smem);
    const int tid = threadIdx.x;
    const int lane = tid & 31;
    const int wid = tid >> 5;
    const int m0 = blockIdx.y * 128;
    const int n0 = blockIdx.x * 128;
    const int wm = (wid & 1) * 64;
    const int wn = (wid >> 1) * 32;

    float acc[4][4][4] = {};

    auto loadStage = [&](int c, int s) {
        const uint32_t base = sb + s * G1_STAGE;
        const int k0 = c * 32;
#pragma unroll
        for (int rep = 0; rep < 4; rep++) {
            const int idx = rep * 256 + tid;
            const int half = idx >> 9, r = (idx >> 2) & 127, ch = idx & 3;
            const __nv_bfloat16* src =
                (half ? Al : Ah) + (size_t)(m0 + r) * DD + k0 + ch * 8;
            cpa16(base + half * A_TILE + r * LDA + ch * 16, src);
        }
#pragma unroll
        for (int rep = 0; rep < 4; rep++) {
            const int idx = rep * 256 + tid;
            const int half = idx >> 9, r = (idx >> 4) & 31, ch = idx & 15;
            const __nv_bfloat16* src =
                (half ? Bl : Bh) + (size_t)(k0 + r) * DD + n0 + ch * 8;
            cpa16(base + 2 * A_TILE + half * B_TILE + r * LDB + ch * 16, src);
        }
        CP_COMMIT();
    };

    const int NC = DD / 32;
    loadStage(0, 0);

    for (int c = 0; c < NC; c++) {
        CP_WAIT0();
        __syncthreads();
        if (c + 1 < NC) loadStage(c + 1, (c + 1) & 1);
        const uint32_t st = sb + (c & 1) * G1_STAGE;

#pragma unroll
        for (int ks = 0; ks < 2; ks++) {
            uint32_t ah[4][4], al[4][4];
            const uint32_t abase = st + (lane & 15) * LDA + ks * 32 + (lane >> 4) * 16;
#pragma unroll
            for (int mt = 0; mt < 4; mt++) {
                ldsm4(ah[mt], abase + (wm + mt * 16) * LDA);
                ldsm4(al[mt], abase + A_TILE + (wm + mt * 16) * LDA);
            }
            const uint32_t brow = ks * 16 + (lane & 7) + ((lane >> 3) & 1) * 8;
            const uint32_t bbase = st + 2 * A_TILE + brow * LDB + wn * 2 + (lane >> 4) * 16;
            uint32_t bh[2][4], bl[2][4];
            ldsm4t(bh[0], bbase);
            ldsm4t(bh[1], bbase + 32);
            ldsm4t(bl[0], bbase + B_TILE);
            ldsm4t(bl[1], bbase + B_TILE + 32);

#pragma unroll
            for (int mt = 0; mt < 4; mt++)
#pragma unroll
                for (int nt = 0; nt < 4; nt++) {
                    const uint32_t* ph = &bh[nt >> 1][(nt & 1) * 2];
                    const uint32_t* pl = &bl[nt >> 1][(nt & 1) * 2];
                    mma_bf16(acc[mt][nt], ah[mt], ph);
                    mma_bf16(acc[mt][nt], ah[mt], pl);
                    mma_bf16(acc[mt][nt], al[mt], ph);
                }
        }
    }

    const int g = lane >> 2, t4 = lane & 3;
#pragma unroll
    for (int mt = 0; mt < 4; mt++) {
        const int r0 = m0 + wm + mt * 16 + g;
#pragma unroll
        for (int nt = 0; nt < 4; nt++) {
            const int cc = n0 + wn + nt * 8 + 2 * t4;
            float v0 = acc[mt][nt][0], v1 = acc[mt][nt][1];
            float v2 = acc[mt][nt][2], v3 = acc[mt][nt][3];
            if (MC) {
                const float2 m2 = *(const float2*)&mc[cc];
                v0 -= m2.x; v1 -= m2.y; v2 -= m2.x; v3 -= m2.y;
            }
            *(float2*)&Cf32[(size_t)r0 * DD + cc] = make_float2(v0, v1);
            *(float2*)&Cf32[(size_t)(r0 + 8) * DD + cc] = make_float2(v2, v3);
            if (!LAST) {
                store_split2(Ch, Cl, (size_t)r0 * DD + cc, v0, v1);
                store_split2(Ch, Cl, (size_t)(r0 + 8) * DD + cc, v2, v3);
            }
        }
    }
}

// ---------------------------------------------------------------------------
// Input Gram split-K (upper-triangle tiles) — run ONCE on x
// ---------------------------------------------------------------------------
#define CV_STAGE (4 * B_TILE)      // 34816
#define CV_SMEM (2 * CV_STAGE)     // 69632

__global__ void __launch_bounds__(256)
hcov(const __nv_bfloat16* __restrict__ Hh, const __nv_bfloat16* __restrict__ Hl,
     float* __restrict__ Cp)
{
    extern __shared__ __align__(16) char smem[];
    const uint32_t sb = smem_u32(smem);
    const int tid = threadIdx.x;
    const int lane = tid & 31;
    const int wid = tid >> 5;
    const int bx = blockIdx.x;
    const int bi = (bx < 4) ? 0 : (bx < 7) ? 1 : (bx < 9) ? 2 : 3;
    const int bj = bx - ((bi == 0) ? 0 : (bi == 1) ? 3 : (bi == 2) ? 5 : 6);
    const int i0 = bi * 128;
    const int j0 = bj * 128;
    const int z  = blockIdx.z;
    const int wm = (wid & 1) * 64;
    const int wn = (wid >> 1) * 32;

    float acc[4][4][4] = {};

    auto loadStage = [&](int c, int s) {
        const uint32_t base = sb + s * CV_STAGE;
        const int nbase = z * KCHUNK + c * 32;
#pragma unroll
        for (int rep = 0; rep < 8; rep++) {
            const int idx = rep * 256 + tid;
            const int tile = idx >> 9;
            const int r = (idx >> 4) & 31, ch = idx & 15;
            const __nv_bfloat16* basep = (tile & 1) ? Hl : Hh;
            const int coff = (tile < 2) ? i0 : j0;
            const __nv_bfloat16* src = basep + (size_t)(nbase + r) * DD + coff + ch * 8;
            cpa16(base + tile * B_TILE + r * LDB + ch * 16, src);
        }
        CP_COMMIT();
    };

    const int NC = KCHUNK / 32;
    loadStage(0, 0);

    for (int c = 0; c < NC; c++) {
        CP_WAIT0();
        __syncthreads();
        if (c + 1 < NC) loadStage(c + 1, (c + 1) & 1);
        const uint32_t st = sb + (c & 1) * CV_STAGE;

#pragma unroll
        for (int ks = 0; ks < 2; ks++) {
            const uint32_t arow = ks * 16 + (lane & 7) + ((lane >> 4) & 1) * 8;
            const uint32_t abase = st + arow * LDB + wm * 2 + ((lane >> 3) & 1) * 16;
            uint32_t ah[4][4], al[4][4];
#pragma unroll
            for (int mt = 0; mt < 4; mt++) {
                ldsm4t(ah[mt], abase + mt * 32);
                ldsm4t(al[mt], abase + B_TILE + mt * 32);
            }
            const uint32_t brow = ks * 16 + (lane & 7) + ((lane >> 3) & 1) * 8;
            const uint32_t bbase = st + 2 * B_TILE + brow * LDB + wn * 2 + (lane >> 4) * 16;
            uint32_t bh[2][4], bl[2][4];
            ldsm4t(bh[0], bbase);
            ldsm4t(bh[1], bbase + 32);
            ldsm4t(bl[0], bbase + B_TILE);
            ldsm4t(bl[1], bbase + B_TILE + 32);

#pragma unroll
            for (int mt = 0; mt < 4; mt++)
#pragma unroll
                for (int nt = 0; nt < 4; nt++) {
                    const uint32_t* ph = &bh[nt >> 1][(nt & 1) * 2];
                    const uint32_t* pl = &bl[nt >> 1][(nt & 1) * 2];
                    mma_bf16(acc[mt][nt], ah[mt], ph);
                    mma_bf16(acc[mt][nt], ah[mt], pl);
                    mma_bf16(acc[mt][nt], al[mt], ph);
                }
        }
    }

    float* out = Cp + (size_t)z * DD * DD;
    const int g = lane >> 2, t4 = lane & 3;
#pragma unroll
    for (int mt = 0; mt < 4; mt++) {
        const int r0 = i0 + wm + mt * 16 + g;
#pragma unroll
        for (int nt = 0; nt < 4; nt++) {
            const int cc = j0 + wn + nt * 8 + 2 * t4;
            float2 v0 = {acc[mt][nt][0], acc[mt][nt][1]};
            float2 v1 = {acc[mt][nt][2], acc[mt][nt][3]};
            *(float2*)&out[(size_t)r0 * DD + cc] = v0;
            *(float2*)&out[(size_t)(r0 + 8) * DD + cc] = v1;
        }
    }
}

__global__ void reduce_cov_sym(const float* __restrict__ Cp, float* __restrict__ G)
{
    const int i = blockIdx.x, j = threadIdx.x;
    if (j < i) return;
    float s = 0.0f;
#pragma unroll 8
    for (int zz = 0; zz < KSPLIT; zz++)
        s += Cp[(size_t)zz * DD * DD + i * DD + j];
    G[i * DD + j] = s;
    G[j * DD + i] = s;
}

// ---------------------------------------------------------------------------
// Small GEMM core: 64x64 tile, 256 threads, intra-block split-K (2 halves)
// ---------------------------------------------------------------------------
#define NS_LDA 80
#define NS_AT  (64 * NS_LDA)
#define NS_LDB 144
#define NS_BT  (32 * NS_LDB)
#define NS_STAGE (2 * NS_AT + 2 * NS_BT)     // 19456
#define NS_SMEM4 (4 * NS_STAGE)              // 77824 (2 halves x 2 stages)

struct NsAcc { float a[2][4][4]; };

__device__ __forceinline__ void ns_tri(int bx, int& ti, int& tj) {
    int t = 0, rem = bx;
    while (rem >= 8 - t) { rem -= 8 - t; t++; }
    ti = t; tj = t + rem;
}

// 256-thread core. On exit, warps 0-3 (wid<4) hold the full-K accumulators
// for their (wm, wn) = ((wid&1)*32, ((wid>>1)&1)*32) subtile.
__device__ __forceinline__ void ns_core256(
    const __nv_bfloat16* __restrict__ Ah, const __nv_bfloat16* __restrict__ Al,
    const __nv_bfloat16* __restrict__ Bh, const __nv_bfloat16* __restrict__ Bl,
    int m0, int n0, char* smem, NsAcc& A)
{
    const uint32_t sb = smem_u32(smem);
    const int tid = threadIdx.x;
    const int lane = tid & 31;
    const int wid = tid >> 5;          // 0..7
    const int khalf = wid >> 2;        // 0/1 K-slice
    const int ltid = tid & 127;
    const int w4 = wid & 3;
    const int wm = (w4 & 1) * 32;
    const int wn = (w4 >> 1) * 32;
    const uint32_t hbase = sb + khalf * (2 * NS_STAGE);

    auto loadStage = [&](int cc, int s) {
        const uint32_t base = hbase + s * NS_STAGE;
        const int k0 = (khalf * 8 + cc) * 32;
#pragma unroll
        for (int rep = 0; rep < 8; rep++) {
            const int idx = rep * 128 + ltid;
            if (idx < 512) {
                const int half = idx >> 8, r = (idx >> 2) & 63, ch = idx & 3;
                const __nv_bfloat16* src =
                    (half ? Al : Ah) + (size_t)(m0 + r) * DD + k0 + ch * 8;
                cpa16(base + half * NS_AT + r * NS_LDA + ch * 16, src);
            } else {
                const int j = idx - 512;
                const int half = j >> 8, r = (j >> 3) & 31, ch = j & 7;
                const __nv_bfloat16* src =
                    (half ? Bl : Bh) + (size_t)(k0 + r) * DD + n0 + ch * 8;
                cpa16(base + 2 * NS_AT + half * NS_BT + r * NS_LDB + ch * 16, src);
            }
        }
        CP_COMMIT();
    };

    loadStage(0, 0);

    for (int cc = 0; cc < 8; cc++) {
        CP_WAIT0();
        __syncthreads();
        if (cc + 1 < 8) loadStage(cc + 1, (cc + 1) & 1);
        const uint32_t st = hbase + (cc & 1) * NS_STAGE;

#pragma unroll
        for (int ks = 0; ks < 2; ks++) {
            uint32_t ah[2][4], al[2][4];
            const uint32_t abase = st + (lane & 15) * NS_LDA + ks * 32 + (lane >> 4) * 16;
#pragma unroll
            for (int mt = 0; mt < 2; mt++) {
                ldsm4(ah[mt], abase + (wm + mt * 16) * NS_LDA);
                ldsm4(al[mt], abase + NS_AT + (wm + mt * 16) * NS_LDA);
            }
            const uint32_t brow = ks * 16 + (lane & 7) + ((lane >> 3) & 1) * 8;
            const uint32_t bbase = st + 2 * NS_AT + brow * NS_LDB + wn * 2 + (lane >> 4) * 16;
            uint32_t bh[2][4], bl[2][4];
            ldsm4t(bh[0], bbase);
            ldsm4t(bh[1], bbase + 32);
            ldsm4t(bl[0], bbase + NS_BT);
            ldsm4t(bl[1], bbase + NS_BT + 32);

#pragma unroll
            for (int mt = 0; mt < 2; mt++)
#pragma unroll
                for (int nt = 0; nt < 4; nt++) {
                    const uint32_t* ph = &bh[nt >> 1][(nt & 1) * 2];
                    const uint32_t* pl = &bl[nt >> 1][(nt & 1) * 2];
                    mma_bf16(A.a[mt][nt], ah[mt], ph);
                    mma_bf16(A.a[mt][nt], ah[mt], pl);
                    mma_bf16(A.a[mt][nt], al[mt], ph);
                }
        }
    }

    // cross-half reduce (deterministic): khalf=1 -> smem -> khalf=0 adds
    __syncthreads();
    float* red = (float*)smem;
    if (khalf == 1) {
        float* dst = red + ((size_t)(w4 * 32 + lane)) * 32;
#pragma unroll
        for (int mt = 0; mt < 2; mt++)
#pragma unroll
            for (int nt = 0; nt < 4; nt++)
#pragma unroll
                for (int q = 0; q < 4; q++)
                    dst[mt * 16 + nt * 4 + q] = A.a[mt][nt][q];
    }
    __syncthreads();
    if (khalf == 0) {
        const float* src = red + ((size_t)(w4 * 32 + lane)) * 32;
#pragma unroll
        for (int mt = 0; mt < 2; mt++)
#pragma unroll
            for (int nt = 0; nt < 4; nt++)
#pragma unroll
                for (int q = 0; q < 4; q++)
                    A.a[mt][nt][q] += src[mt * 16 + nt * 4 + q];
    }
}

// Generic small GEMM: C = scale * (A @ B), grid (8,8), 256 threads.
// SCALE: 0 -> 1.0 ; 1 -> scalars[2]^2 ; 2 -> scalars[2]
template<int SCALE, int OF32, int OSPLIT>
__global__ void __launch_bounds__(256)
sg(const __nv_bfloat16* __restrict__ Ah, const __nv_bfloat16* __restrict__ Al,
   const __nv_bfloat16* __restrict__ Bh, const __nv_bfloat16* __restrict__ Bl,
   float* __restrict__ Cf32,
   __nv_bfloat16* __restrict__ Ch, __nv_bfloat16* __restrict__ Cl,
   const float* __restrict__ scalars)
{
    extern __shared__ __align__(16) char smem[];
    const int m0 = blockIdx.y * 64;
    const int n0 = blockIdx.x * 64;

    NsAcc A = {};
    ns_core256(Ah, Al, Bh, Bl, m0, n0, smem, A);

    const int wid = threadIdx.x >> 5;
    if (wid >= 4) return;
    const int lane = threadIdx.x & 31;
    const int wm = (wid & 1) * 32;
    const int wn = (wid >> 1) * 32;

    float sc = 1.0f;
    if (SCALE == 1) sc = scalars[2] * scalars[2];
    if (SCALE == 2) sc = scalars[2];
    const int g = lane >> 2, t4 = lane & 3;
#pragma unroll
    for (int mt = 0; mt < 2; mt++) {
        const int r0 = m0 + wm + mt * 16 + g;
#pragma unroll
        for (int nt = 0; nt < 4; nt++) {
            const int cc = n0 + wn + nt * 8 + 2 * t4;
#pragma unroll
            for (int half = 0; half < 2; half++) {
                const size_t idx = (size_t)(r0 + half * 8) * DD + cc;
                const float v0 = A.a[mt][nt][half * 2 + 0] * sc;
                const float v1 = A.a[mt][nt][half * 2 + 1] * sc;
                if (OF32) *(float2*)&Cf32[idx] = make_float2(v0, v1);
                if (OSPLIT) store_split2(Ch, Cl, idx, v0, v1);
            }
        }
    }
}

// grid (36,1,2): z=0 -> T1 = P @ S ; z=1 -> T2 = P @ P ; symmetric, mirrored
__global__ void __launch_bounds__(256)
ns_pair(const __nv_bfloat16* __restrict__ Pah, const __nv_bfloat16* __restrict__ Pal,
        const __nv_bfloat16* __restrict__ Sh,  const __nv_bfloat16* __restrict__ Sl,
        __nv_bfloat16* __restrict__ T1h, __nv_bfloat16* __restrict__ T1l,
        __nv_bfloat16* __restrict__ T2h, __nv_bfloat16* __restrict__ T2l)
{
    extern __shared__ __align__(16) char smem[];
    int ti, tj;
    ns_tri(blockIdx.x, ti, tj);
    const int m0 = ti * 64;
    const int n0 = tj * 64;

    NsAcc A = {};
    const __nv_bfloat16* Bh = blockIdx.z ? Pah : Sh;
    const __nv_bfloat16* Bl = blockIdx.z ? Pal : Sl;
    ns_core256(Pah, Pal, Bh, Bl, m0, n0, smem, A);

    const int wid = threadIdx.x >> 5;
    if (wid >= 4) return;
    const int lane = threadIdx.x & 31;
    const int wm = (wid & 1) * 32;
    const int wn = (wid >> 1) * 32;

    __nv_bfloat16* Oh = blockIdx.z ? T2h : T1h;
    __nv_bfloat16* Ol = blockIdx.z ? T2l : T1l;
    const int g = lane >> 2, t4 = lane & 3;
    const bool mir = (ti != tj);
#pragma unroll
    for (int mt = 0; mt < 2; mt++) {
        const int r0 = m0 + wm + mt * 16 + g;
#pragma unroll
        for (int nt = 0; nt < 4; nt++) {
            const int cc = n0 + wn + nt * 8 + 2 * t4;
            const float v0 = A.a[mt][nt][0], v1 = A.a[mt][nt][1];
            const float v2 = A.a[mt][nt][2], v3 = A.a[mt][nt][3];
            store_split2(Oh, Ol, (size_t)r0 * DD + cc, v0, v1);
            store_split2(Oh, Ol, (size_t)(r0 + 8) * DD + cc, v2, v3);
            if (mir) {
                store_split1(Oh, Ol, (size_t)cc * DD + r0, v0);
                store_split1(Oh, Ol, (size_t)(cc + 1) * DD + r0, v1);
                store_split1(Oh, Ol, (size_t)cc * DD + r0 + 8, v2);
                store_split1(Oh, Ol, (size_t)(cc + 1) * DD + r0 + 8, v3);
            }
        }
    }
}

// grid (36): Pb = 1.5*Pold - 0.5*(T2 @ T1); symmetric, mirrored; fp32 + splits
__global__ void __launch_bounds__(256)
ns_update(const __nv_bfloat16* __restrict__ T2h, const __nv_bfloat16* __restrict__ T2l,
          const __nv_bfloat16* __restrict__ T1h, const __nv_bfloat16* __restrict__ T1l,
          const float* __restrict__ Pold, float* __restrict__ Pnew,
          __nv_bfloat16* __restrict__ Pnh, __nv_bfloat16* __restrict__ Pnl)
{
    extern __shared__ __align__(16) char smem[];
    int ti, tj;
    ns_tri(blockIdx.x, ti, tj);
    const int m0 = ti * 64;
    const int n0 = tj * 64;

    NsAcc A = {};
    ns_core256(T2h, T2l, T1h, T1l, m0, n0, smem, A);

    const int wid = threadIdx.x >> 5;
    if (wid >= 4) return;
    const int lane = threadIdx.x & 31;
    const int wm = (wid & 1) * 32;
    const int wn = (wid >> 1) * 32;

    const int g = lane >> 2, t4 = lane & 3;
    const bool mir = (ti != tj);
#pragma unroll
    for (int mt = 0; mt < 2; mt++) {
        const int r0 = m0 + wm + mt * 16 + g;
#pragma unroll
        for (int nt = 0; nt < 4; nt++) {
            const int cc = n0 + wn + nt * 8 + 2 * t4;
#pragma unroll
            for (int half = 0; half < 2; half++) {
                const int r = r0 + half * 8;
                const size_t idx = (size_t)r * DD + cc;
                const float2 po = *(const float2*)&Pold[idx];
                const float v0 = 1.5f * po.x - 0.5f * A.a[mt][nt][half * 2 + 0];
                const float v1 = 1.5f * po.y - 0.5f * A.a[mt][nt][half * 2 + 1];
                *(float2*)&Pnew[idx] = make_float2(v0, v1);
                store_split2(Pnh, Pnl, idx, v0, v1);
                if (mir) {
                    Pnew[(size_t)cc * DD + r] = v0;
                    Pnew[(size_t)(cc + 1) * DD + r] = v1;
                    store_split1(Pnh, Pnl, (size_t)cc * DD + r, v0);
                    store_split1(Pnh, Pnl, (size_t)(cc + 1) * DD + r, v1);
                }
            }
        }
    }
}

// ---------------------------------------------------------------------------
// trace / fused S+P1 / vector helpers
// ---------------------------------------------------------------------------
__global__ void mean_finalize(const float* __restrict__ colp, float* __restrict__ mean)
{
    __shared__ float sm[128];
    const int j = blockIdx.x;
    const int t = threadIdx.x;
    const float4 v = *(const float4*)(colp + (size_t)j * 512 + t * 4);
    sm[t] = v.x + v.y + v.z + v.w;
    __syncthreads();
    for (int s = 64; s > 0; s >>= 1) {
        if (t < s) sm[t] += sm[t + s];
        __syncthreads();
    }
    if (t == 0) mean[j] = sm[0] * (1.0f / (float)NROWS);
}

__global__ void trace_kernel(const float* __restrict__ G,
                             const float* __restrict__ mH,
                             float* __restrict__ scalars)
{
    __shared__ float sm[512];
    const int i = threadIdx.x;
    const float m = mH ? mH[i] : 0.0f;
    sm[i] = G[i * DD + i] * (1.0f / (float)NROWS) - m * m + INV_TEMP;
    __syncthreads();
    for (int s = 256; s > 0; s >>= 1) {
        if (i < s) sm[i] += sm[i + s];
        __syncthreads();
    }
    if (i == 0) {
        const float tr = sm[0];
        scalars[0] = tr;
        scalars[1] = 1.0f / tr;
        scalars[2] = rsqrtf(tr);
    }
}

// fused: S splits + P1 = 1.5 I - 0.5 S (fp32 + splits)
__global__ void s_kernel(const float* __restrict__ G,
                         const float* __restrict__ mH,
                         const float* __restrict__ scalars,
                         __nv_bfloat16* __restrict__ Sh, __nv_bfloat16* __restrict__ Sl,
                         float* __restrict__ P,
                         __nv_bfloat16* __restrict__ Ph, __nv_bfloat16* __restrict__ Pl)
{
    const int i = blockIdx.x, j = threadIdx.x;
    const float invtr = scalars[1];
    float v = G[i * DD + j] * (1.0f / (float)NROWS);
    if (mH) v -= mH[i] * mH[j];
    if (i == j) v += INV_TEMP;
    v *= invtr;
    split1(v, Sh[i * DD + j], Sl[i * DD + j]);
    const float p = ((i == j) ? 1.5f : 0.0f) - 0.5f * v;
    P[i * DD + j] = p;
    split1(p, Ph[i * DD + j], Pl[i * DD + j]);
}

// mH = mean_prev @ W
__global__ void meanW(const float* __restrict__ mp, const float* __restrict__ W,
                      float* __restrict__ mH)
{
    const int j = blockIdx.x * 128 + threadIdx.x;
    float s = 0.0f;
#pragma unroll 8
    for (int k = 0; k < DD; k++)
        s += mp[k] * W[(size_t)k * DD + j];
    mH[j] = s;
}

// mc = s2 * mH @ P
__global__ void mc_kernel(const float* __restrict__ mH, const float* __restrict__ P,
                          const float* __restrict__ scalars, float* __restrict__ mc)
{
    const int j = blockIdx.x * 128 + threadIdx.x;
    float s = 0.0f;
#pragma unroll 8
    for (int k = 0; k < DD; k++)
        s += mH[k] * P[(size_t)k * DD + j];
    mc[j] = s * scalars[2];
}

// ---------------------------------------------------------------------------
// Host orchestration
// ---------------------------------------------------------------------------
static void run_layer(const float* W, float* out,
                      __nv_bfloat16* inh, __nv_bfloat16* inl,
                      __nv_bfloat16* outh, __nv_bfloat16* outl,
                      int first, int last)
{
    float *G, *P, *Pn, *mean, *mH, *mc, *scal;
    __nv_bfloat16 *Wh, *Wl, *Sh, *Sl;
    __nv_bfloat16 *Pah, *Pal, *Pbh, *Pbl, *T1h, *T1l, *T2h, *T2l;
    __nv_bfloat16 *Uh, *Ul, *GOh, *GOl, *Gch, *Gcl;
    cudaGetSymbolAddress((void**)&G,    g_G);
    cudaGetSymbolAddress((void**)&P,    g_P);
    cudaGetSymbolAddress((void**)&Pn,   g_Pn);
    cudaGetSymbolAddress((void**)&mean, g_mean);
    cudaGetSymbolAddress((void**)&mH,   g_mH);
    cudaGetSymbolAddress((void**)&mc,   g_mc);
    cudaGetSymbolAddress((void**)&scal, g_scalars);
    cudaGetSymbolAddress((void**)&Wh,   g_Wh);
    cudaGetSymbolAddress((void**)&Wl,   g_Wl);
    cudaGetSymbolAddress((void**)&Sh,   g_Sh);
    cudaGetSymbolAddress((void**)&Sl,   g_Sl);
    cudaGetSymbolAddress((void**)&Pah,  g_Pah);
    cudaGetSymbolAddress((void**)&Pal,  g_Pal);
    cudaGetSymbolAddress((void**)&Pbh,  g_Pbh);
    cudaGetSymbolAddress((void**)&Pbl,  g_Pbl);
    cudaGetSymbolAddress((void**)&T1h,  g_T1h);
    cudaGetSymbolAddress((void**)&T1l,  g_T1l);
    cudaGetSymbolAddress((void**)&T2h,  g_T2h);
    cudaGetSymbolAddress((void**)&T2l,  g_T2l);
    cudaGetSymbolAddress((void**)&Uh,   g_Uh);
    cudaGetSymbolAddress((void**)&Ul,   g_Ul);
    cudaGetSymbolAddress((void**)&GOh,  g_GOh);
    cudaGetSymbolAddress((void**)&GOl,  g_GOl);
    cudaGetSymbolAddress((void**)&Gch,  g_Gch);
    cudaGetSymbolAddress((void**)&Gcl,  g_Gcl);

    const int wBlocks = (DD * DD) / (256 * 4);

    // W splits (+ mean_H for the first layer)
    split_f32<<<wBlocks, 256>>>(W, Wh, Wl);
    if (first) meanW<<<4, 128>>>(mean, W, mH);
    const float* mHp = first ? mH : nullptr;

    // G_H = W^T @ G_in @ W  (G_in splits in GOh/GOl)
    tsplit<<<dim3(16, 16), dim3(32, 32)>>>(W, Uh, Ul);
    sg<0, 0, 1><<<dim3(8, 8), 256, NS_SMEM4>>>(Uh, Ul, GOh, GOl, nullptr, T1h, T1l, scal);
    sg<0, 1, 0><<<dim3(8, 8), 256, NS_SMEM4>>>(T1h, T1l, Wh, Wl, G, nullptr, nullptr, scal);

    trace_kernel<<<1, 512>>>(G, mHp, scal);
    s_kernel<<<512, 512>>>(G, mHp, scal, Sh, Sl, P, Pah, Pal);

    // Newton-Schulz (iteration 1 fused into s_kernel)
    float* Pf = P; float* Pg = Pn;
    __nv_bfloat16 *ah = Pah, *al = Pal, *bh = Pbh, *bl = Pbl;
    for (int t = 1; t < NS_ITERS; t++) {
        ns_pair<<<dim3(36, 1, 2), 256, NS_SMEM4>>>(ah, al, Sh, Sl, T1h, T1l, T2h, T2l);
        ns_update<<<dim3(36), 256, NS_SMEM4>>>(T2h, T2l, T1h, T1l, Pf, Pg, bh, bl);
        { float* t0 = Pf; Pf = Pg; Pg = t0; }
        { __nv_bfloat16* t1 = ah; ah = bh; bh = t1; }
        { __nv_bfloat16* t2 = al; al = bl; bl = t2; }
    }

    // G_out = s2^2 * P @ Gc @ P  (input Gram for the next layer)
    if (!last) {
        gc_split<<<512, 512>>>(G, mHp, Gch, Gcl);
        sg<0, 0, 1><<<dim3(8, 8), 256, NS_SMEM4>>>(ah, al, Gch, Gcl, nullptr, T1h, T1l, scal);
        sg<1, 0, 1><<<dim3(8, 8), 256, NS_SMEM4>>>(T1h, T1l, ah, al, nullptr, GOh, GOl, scal);
    }

    // Weff = s2 * W @ P ; (mc only for the first layer)
    sg<2, 0, 1><<<dim3(8, 8), 256, NS_SMEM4>>>(Wh, Wl, ah, al, nullptr, Uh, Ul, scal);
    if (first) mc_kernel<<<4, 128>>>(mH, Pf, scal, mc);

    // out = in @ Weff (- mc)
    if (first)
        hgemm_out<1, 0><<<dim3(4, 512), 256, G1_SMEM>>>(inh, inl, Uh, Ul,
                                                        out, outh, outl, mc);
    else if (last)
        hgemm_out<0, 1><<<dim3(4, 512), 256, G1_SMEM>>>(inh, inl, Uh, Ul,
                                                        out, outh, outl, nullptr);
    else
        hgemm_out<0, 0><<<dim3(4, 512), 256, G1_SMEM>>>(inh, inl, Uh, Ul,
                                                        out, outh, outl, nullptr);
}

extern "C" void kernel_launch(void* const* d_in, const int* in_sizes, int n_in,
                              void* d_out, int out_size)
{
    (void)in_sizes; (void)n_in; (void)out_size;
    const float* x  = (const float*)d_in[0];
    const float* W0 = (const float*)d_in[1];
    const float* W1 = (const float*)d_in[2];
    const float* W2 = (const float*)d_in[3];
    float* out = (float*)d_out;

    cudaFuncSetAttribute(hgemm_out<1, 0>, cudaFuncAttributeMaxDynamicSharedMemorySize, G1_SMEM);
    cudaFuncSetAttribute(hgemm_out<0, 0>, cudaFuncAttributeMaxDynamicSharedMemorySize, G1_SMEM);
    cudaFuncSetAttribute(hgemm_out<0, 1>, cudaFuncAttributeMaxDynamicSharedMemorySize, G1_SMEM);
    cudaFuncSetAttribute(hcov, cudaFuncAttributeMaxDynamicSharedMemorySize, CV_SMEM);
    cudaFuncSetAttribute(ns_pair,   cudaFuncAttributeMaxDynamicSharedMemorySize, NS_SMEM4);
    cudaFuncSetAttribute(ns_update, cudaFuncAttributeMaxDynamicSharedMemorySize, NS_SMEM4);
    cudaFuncSetAttribute((const void*)sg<0, 0, 1>, cudaFuncAttributeMaxDynamicSharedMemorySize, NS_SMEM4);
    cudaFuncSetAttribute((const void*)sg<0, 1, 0>, cudaFuncAttributeMaxDynamicSharedMemorySize, NS_SMEM4);
    cudaFuncSetAttribute((const void*)sg<1, 0, 1>, cudaFuncAttributeMaxDynamicSharedMemorySize, NS_SMEM4);
    cudaFuncSetAttribute((const void*)sg<2, 0, 1>, cudaFuncAttributeMaxDynamicSharedMemorySize, NS_SMEM4);

    float *covp, *G, *colp, *mean;
    __nv_bfloat16 *Ah, *Al, *Hh, *Hl, *GOh, *GOl;
    cudaGetSymbolAddress((void**)&covp, g_covp);
    cudaGetSymbolAddress((void**)&G,    g_G);
    cudaGetSymbolAddress((void**)&colp, g_colp);
    cudaGetSymbolAddress((void**)&mean, g_mean);
    cudaGetSymbolAddress((void**)&Ah,   g_Ah);
    cudaGetSymbolAddress((void**)&Al,   g_Al);
    cudaGetSymbolAddress((void**)&Hh,   g_Hh);
    cudaGetSymbolAddress((void**)&Hl,   g_Hl);
    cudaGetSymbolAddress((void**)&GOh,  g_GOh);
    cudaGetSymbolAddress((void**)&GOl,  g_GOl);

    // input preprocessing: splits, mean, Gram (the only big Gram in the run)
    split_f32<<<(NROWS * DD) / (256 * 4), 256>>>(x, Ah, Al);
    colsum_x<<<dim3(4, 512), 128>>>(x, colp);
    mean_finalize<<<512, 128>>>(colp, mean);
    hcov<<<dim3(10, 1, KSPLIT), 256, CV_SMEM>>>(Ah, Al, covp);
    reduce_cov_sym<<<512, 512>>>(covp, G);
    gsplit<<<512, 512>>>(G, GOh, GOl);

    float* o0 = out;
    float* o1 = out + (size_t)NROWS * DD;
    float* o2 = out + (size_t)2 * NROWS * DD;

    run_layer(W0, o0, Ah, Al, Hh, Hl, 1, 0);
    run_layer(W1, o1, Hh, Hl, Ah, Al, 0, 0);
    run_layer(W2, o2, Ah, Al, Hh, Hl, 0, 1);
}

// round 11
// speedup vs baseline: 1.7884x; 1.0219x over previous
#include <cuda_runtime.h>
#include <cuda_bf16.h>
#include <cstdint>
#include <math.h>

#define NROWS 65536
#define DD    512
#define KSPLIT 64
#define KCHUNK (NROWS / KSPLIT)   // 1024
#define NS_ITERS 10
#define INV_TEMP 0.1f

// ---------------------------------------------------------------------------
// Static device scratch
// ---------------------------------------------------------------------------
__device__ float g_covp[(size_t)KSPLIT * DD * DD];   // 64 MB (input Gram only)
__device__ float g_G[DD * DD];
__device__ float g_P[DD * DD];
__device__ float g_Pn[DD * DD];
__device__ float g_colp[DD * 512];
__device__ float g_mean[DD];                          // mean of x
__device__ float g_mH[DD];                            // mean of H0 (analytic)
__device__ float g_bvec[3][DD];                       // affine offsets per layer
__device__ float g_scalars[4];
__device__ __nv_bfloat16 g_Ah[(size_t)NROWS * DD];   // x splits (read-only after pre)
__device__ __nv_bfloat16 g_Al[(size_t)NROWS * DD];
__device__ __nv_bfloat16 g_Wh[DD * DD];
__device__ __nv_bfloat16 g_Wl[DD * DD];
__device__ __nv_bfloat16 g_Sh[DD * DD], g_Sl[DD * DD];
__device__ __nv_bfloat16 g_Pah[DD * DD], g_Pal[DD * DD];
__device__ __nv_bfloat16 g_Pbh[DD * DD], g_Pbl[DD * DD];
__device__ __nv_bfloat16 g_T1h[DD * DD], g_T1l[DD * DD];
__device__ __nv_bfloat16 g_T2h[DD * DD], g_T2l[DD * DD];
__device__ __nv_bfloat16 g_Uh[DD * DD],  g_Ul[DD * DD];   // W^T splits
__device__ __nv_bfloat16 g_Weh[DD * DD], g_Wel[DD * DD];  // Weff temp splits
__device__ __nv_bfloat16 g_GOh[DD * DD], g_GOl[DD * DD];  // Gram chain splits
__device__ __nv_bfloat16 g_Gch[DD * DD], g_Gcl[DD * DD];
__device__ __nv_bfloat16 g_M0h[DD * DD], g_M0l[DD * DD];  // composed maps
__device__ __nv_bfloat16 g_M1h[DD * DD], g_M1l[DD * DD];
__device__ __nv_bfloat16 g_M2h[DD * DD], g_M2l[DD * DD];

// ---------------------------------------------------------------------------
// PTX helpers
// ---------------------------------------------------------------------------
__device__ __forceinline__ uint32_t smem_u32(const void* p) {
    uint32_t a;
    asm("{ .reg .u64 t; cvta.to.shared.u64 t, %1; cvt.u32.u64 %0, t; }"
        : "=r"(a) : "l"(p));
    return a;
}
__device__ __forceinline__ void cpa16(uint32_t dst, const void* src) {
    asm volatile("cp.async.cg.shared.global [%0], [%1], 16;"
                 :: "r"(dst), "l"(src) : "memory");
}
#define CP_COMMIT() asm volatile("cp.async.commit_group;" ::: "memory")
#define CP_WAIT0()  asm volatile("cp.async.wait_group 0;" ::: "memory")

__device__ __forceinline__ void ldsm4(uint32_t* r, uint32_t a) {
    asm volatile("ldmatrix.sync.aligned.m8n8.x4.shared.b16 {%0,%1,%2,%3}, [%4];"
        : "=r"(r[0]), "=r"(r[1]), "=r"(r[2]), "=r"(r[3]) : "r"(a));
}
__device__ __forceinline__ void ldsm4t(uint32_t* r, uint32_t a) {
    asm volatile("ldmatrix.sync.aligned.m8n8.x4.trans.shared.b16 {%0,%1,%2,%3}, [%4];"
        : "=r"(r[0]), "=r"(r[1]), "=r"(r[2]), "=r"(r[3]) : "r"(a));
}
__device__ __forceinline__ void mma_bf16(float* d, const uint32_t* a, const uint32_t* b) {
    asm volatile("mma.sync.aligned.m16n8k16.row.col.f32.bf16.bf16.f32 "
        "{%0,%1,%2,%3}, {%4,%5,%6,%7}, {%8,%9}, {%0,%1,%2,%3};"
        : "+f"(d[0]), "+f"(d[1]), "+f"(d[2]), "+f"(d[3])
        : "r"(a[0]), "r"(a[1]), "r"(a[2]), "r"(a[3]), "r"(b[0]), "r"(b[1]));
}

__device__ __forceinline__ void split1(float v, __nv_bfloat16& h, __nv_bfloat16& l) {
    h = __float2bfloat16_rn(v);
    l = __float2bfloat16_rn(v - __bfloat162float(h));
}
__device__ __forceinline__ void store_split1(__nv_bfloat16* Xh, __nv_bfloat16* Xl,
                                             size_t off, float v) {
    split1(v, Xh[off], Xl[off]);
}
__device__ __forceinline__ void store_split2(__nv_bfloat16* Xh, __nv_bfloat16* Xl,
                                             size_t off, float a, float b) {
    __nv_bfloat16 ha, la, hb, lb;
    split1(a, ha, la);
    split1(b, hb, lb);
    *(uint32_t*)(Xh + off) =
        ((uint32_t)__bfloat16_as_ushort(hb) << 16) | __bfloat16_as_ushort(ha);
    *(uint32_t*)(Xl + off) =
        ((uint32_t)__bfloat16_as_ushort(lb) << 16) | __bfloat16_as_ushort(la);
}

__global__ void split_f32(const float* __restrict__ X,
                          __nv_bfloat16* __restrict__ Xh, __nv_bfloat16* __restrict__ Xl)
{
    const size_t i = ((size_t)blockIdx.x * blockDim.x + threadIdx.x) * 4;
    float4 v = *(const float4*)(X + i);
    __nv_bfloat16 h[4], l[4];
    split1(v.x, h[0], l[0]); split1(v.y, h[1], l[1]);
    split1(v.z, h[2], l[2]); split1(v.w, h[3], l[3]);
    *(uint64_t*)(Xh + i) = *(const uint64_t*)h;
    *(uint64_t*)(Xl + i) = *(const uint64_t*)l;
}

__global__ void tsplit(const float* __restrict__ W,
                       __nv_bfloat16* __restrict__ Uh, __nv_bfloat16* __restrict__ Ul)
{
    __shared__ float t[32][33];
    const int bx = blockIdx.x * 32;
    const int by = blockIdx.y * 32;
    const int tx = threadIdx.x, ty = threadIdx.y;
    t[ty][tx] = W[(size_t)(by + ty) * DD + bx + tx];
    __syncthreads();
    const float v = t[tx][ty];
    const size_t o = (size_t)(bx + ty) * DD + by + tx;
    split1(v, Uh[o], Ul[o]);
}

__global__ void gsplit(const float* __restrict__ G,
                       __nv_bfloat16* __restrict__ Gh, __nv_bfloat16* __restrict__ Gl)
{
    const int i = blockIdx.x, j = threadIdx.x;
    split1(G[i * DD + j], Gh[i * DD + j], Gl[i * DD + j]);
}

__global__ void gc_split(const float* __restrict__ G, const float* __restrict__ mH,
                         __nv_bfloat16* __restrict__ Gch, __nv_bfloat16* __restrict__ Gcl)
{
    const int i = blockIdx.x, j = threadIdx.x;
    float v = G[i * DD + j];
    if (mH) v -= (float)NROWS * mH[i] * mH[j];
    split1(v, Gch[i * DD + j], Gcl[i * DD + j]);
}

__global__ void colsum_x(const float* __restrict__ X, float* __restrict__ colp)
{
    const int c0 = blockIdx.x * 128;
    const int r0 = blockIdx.y * 128;
    const int t = threadIdx.x;
    float s = 0.0f;
    for (int r = 0; r < 128; r++)
        s += X[(size_t)(r0 + r) * DD + c0 + t];
    colp[(size_t)(c0 + t) * 512 + blockIdx.y] = s;
}

// ---------------------------------------------------------------------------
// Big affine GEMM: out = x @ M + 1*b^T   (fp32 output only)
// ---------------------------------------------------------------------------
#define LDA 80
#define LDB 272
#define A_TILE (128 * LDA)
#define B_TILE (32 * LDB)
#define G1_STAGE (2 * A_TILE + 2 * B_TILE)   // 37888
#define G1_SMEM (2 * G1_STAGE)               // 75776

__global__ void __launch_bounds__(256)
hgemm_aff(const __nv_bfloat16* __restrict__ Ah, const __nv_bfloat16* __restrict__ Al,
          const __nv_bfloat16* __restrict__ Bh, const __nv_bfloat16* __restrict__ Bl,
          float* __restrict__ Cf32, const float* __restrict__ bvec)
{
    extern __shared__ __align__(16) char smem[];
    const uint32_t sb = smem_u32(smem);
    const int tid = threadIdx.x;
    const int lane = tid & 31;
    const int wid = tid >> 5;
    const int m0 = blockIdx.y * 128;
    const int n0 = blockIdx.x * 128;
    const int wm = (wid & 1) * 64;
    const int wn = (wid >> 1) * 32;

    float acc[4][4][4] = {};

    auto loadStage = [&](int c, int s) {
        const uint32_t base = sb + s * G1_STAGE;
        const int k0 = c * 32;
#pragma unroll
        for (int rep = 0; rep < 4; rep++) {
            const int idx = rep * 256 + tid;
            const int half = idx >> 9, r = (idx >> 2) & 127, ch = idx & 3;
            const __nv_bfloat16* src =
                (half ? Al : Ah) + (size_t)(m0 + r) * DD + k0 + ch * 8;
            cpa16(base + half * A_TILE + r * LDA + ch * 16, src);
        }
#pragma unroll
        for (int rep = 0; rep < 4; rep++) {
            const int idx = rep * 256 + tid;
            const int half = idx >> 9, r = (idx >> 4) & 31, ch = idx & 15;
            const __nv_bfloat16* src =
                (half ? Bl : Bh) + (size_t)(k0 + r) * DD + n0 + ch * 8;
            cpa16(base + 2 * A_TILE + half * B_TILE + r * LDB + ch * 16, src);
        }
        CP_COMMIT();
    };

    const int NC = DD / 32;
    loadStage(0, 0);

    for (int c = 0; c < NC; c++) {
        CP_WAIT0();
        __syncthreads();
        if (c + 1 < NC) loadStage(c + 1, (c + 1) & 1);
        const uint32_t st = sb + (c & 1) * G1_STAGE;

#pragma unroll
        for (int ks = 0; ks < 2; ks++) {
            uint32_t ah[4][4], al[4][4];
            const uint32_t abase = st + (lane & 15) * LDA + ks * 32 + (lane >> 4) * 16;
#pragma unroll
            for (int mt = 0; mt < 4; mt++) {
                ldsm4(ah[mt], abase + (wm + mt * 16) * LDA);
                ldsm4(al[mt], abase + A_TILE + (wm + mt * 16) * LDA);
            }
            const uint32_t brow = ks * 16 + (lane & 7) + ((lane >> 3) & 1) * 8;
            const uint32_t bbase = st + 2 * A_TILE + brow * LDB + wn * 2 + (lane >> 4) * 16;
            uint32_t bh[2][4], bl[2][4];
            ldsm4t(bh[0], bbase);
            ldsm4t(bh[1], bbase + 32);
            ldsm4t(bl[0], bbase + B_TILE);
            ldsm4t(bl[1], bbase + B_TILE + 32);

#pragma unroll
            for (int mt = 0; mt < 4; mt++)
#pragma unroll
                for (int nt = 0; nt < 4; nt++) {
                    const uint32_t* ph = &bh[nt >> 1][(nt & 1) * 2];
                    const uint32_t* pl = &bl[nt >> 1][(nt & 1) * 2];
                    mma_bf16(acc[mt][nt], ah[mt], ph);
                    mma_bf16(acc[mt][nt], ah[mt], pl);
                    mma_bf16(acc[mt][nt], al[mt], ph);
                }
        }
    }

    const int g = lane >> 2, t4 = lane & 3;
#pragma unroll
    for (int mt = 0; mt < 4; mt++) {
        const int r0 = m0 + wm + mt * 16 + g;
#pragma unroll
        for (int nt = 0; nt < 4; nt++) {
            const int cc = n0 + wn + nt * 8 + 2 * t4;
            const float2 b2 = *(const float2*)&bvec[cc];
            *(float2*)&Cf32[(size_t)r0 * DD + cc] =
                make_float2(acc[mt][nt][0] + b2.x, acc[mt][nt][1] + b2.y);
            *(float2*)&Cf32[(size_t)(r0 + 8) * DD + cc] =
                make_float2(acc[mt][nt][2] + b2.x, acc[mt][nt][3] + b2.y);
        }
    }
}

// ---------------------------------------------------------------------------
// Input Gram split-K (upper-triangle tiles) — run ONCE on x
// ---------------------------------------------------------------------------
#define CV_STAGE (4 * B_TILE)
#define CV_SMEM (2 * CV_STAGE)

__global__ void __launch_bounds__(256)
hcov(const __nv_bfloat16* __restrict__ Hh, const __nv_bfloat16* __restrict__ Hl,
     float* __restrict__ Cp)
{
    extern __shared__ __align__(16) char smem[];
    const uint32_t sb = smem_u32(smem);
    const int tid = threadIdx.x;
    const int lane = tid & 31;
    const int wid = tid >> 5;
    const int bx = blockIdx.x;
    const int bi = (bx < 4) ? 0 : (bx < 7) ? 1 : (bx < 9) ? 2 : 3;
    const int bj = bx - ((bi == 0) ? 0 : (bi == 1) ? 3 : (bi == 2) ? 5 : 6);
    const int i0 = bi * 128;
    const int j0 = bj * 128;
    const int z  = blockIdx.z;
    const int wm = (wid & 1) * 64;
    const int wn = (wid >> 1) * 32;

    float acc[4][4][4] = {};

    auto loadStage = [&](int c, int s) {
        const uint32_t base = sb + s * CV_STAGE;
        const int nbase = z * KCHUNK + c * 32;
#pragma unroll
        for (int rep = 0; rep < 8; rep++) {
            const int idx = rep * 256 + tid;
            const int tile = idx >> 9;
            const int r = (idx >> 4) & 31, ch = idx & 15;
            const __nv_bfloat16* basep = (tile & 1) ? Hl : Hh;
            const int coff = (tile < 2) ? i0 : j0;
            const __nv_bfloat16* src = basep + (size_t)(nbase + r) * DD + coff + ch * 8;
            cpa16(base + tile * B_TILE + r * LDB + ch * 16, src);
        }
        CP_COMMIT();
    };

    const int NC = KCHUNK / 32;
    loadStage(0, 0);

    for (int c = 0; c < NC; c++) {
        CP_WAIT0();
        __syncthreads();
        if (c + 1 < NC) loadStage(c + 1, (c + 1) & 1);
        const uint32_t st = sb + (c & 1) * CV_STAGE;

#pragma unroll
        for (int ks = 0; ks < 2; ks++) {
            const uint32_t arow = ks * 16 + (lane & 7) + ((lane >> 4) & 1) * 8;
            const uint32_t abase = st + arow * LDB + wm * 2 + ((lane >> 3) & 1) * 16;
            uint32_t ah[4][4], al[4][4];
#pragma unroll
            for (int mt = 0; mt < 4; mt++) {
                ldsm4t(ah[mt], abase + mt * 32);
                ldsm4t(al[mt], abase + B_TILE + mt * 32);
            }
            const uint32_t brow = ks * 16 + (lane & 7) + ((lane >> 3) & 1) * 8;
            const uint32_t bbase = st + 2 * B_TILE + brow * LDB + wn * 2 + (lane >> 4) * 16;
            uint32_t bh[2][4], bl[2][4];
            ldsm4t(bh[0], bbase);
            ldsm4t(bh[1], bbase + 32);
            ldsm4t(bl[0], bbase + B_TILE);
            ldsm4t(bl[1], bbase + B_TILE + 32);

#pragma unroll
            for (int mt = 0; mt < 4; mt++)
#pragma unroll
                for (int nt = 0; nt < 4; nt++) {
                    const uint32_t* ph = &bh[nt >> 1][(nt & 1) * 2];
                    const uint32_t* pl = &bl[nt >> 1][(nt & 1) * 2];
                    mma_bf16(acc[mt][nt], ah[mt], ph);
                    mma_bf16(acc[mt][nt], ah[mt], pl);
                    mma_bf16(acc[mt][nt], al[mt], ph);
                }
        }
    }

    float* out = Cp + (size_t)z * DD * DD;
    const int g = lane >> 2, t4 = lane & 3;
#pragma unroll
    for (int mt = 0; mt < 4; mt++) {
        const int r0 = i0 + wm + mt * 16 + g;
#pragma unroll
        for (int nt = 0; nt < 4; nt++) {
            const int cc = j0 + wn + nt * 8 + 2 * t4;
            float2 v0 = {acc[mt][nt][0], acc[mt][nt][1]};
            float2 v1 = {acc[mt][nt][2], acc[mt][nt][3]};
            *(float2*)&out[(size_t)r0 * DD + cc] = v0;
            *(float2*)&out[(size_t)(r0 + 8) * DD + cc] = v1;
        }
    }
}

__global__ void reduce_cov_sym(const float* __restrict__ Cp, float* __restrict__ G)
{
    const int i = blockIdx.x, j = threadIdx.x;
    if (j < i) return;
    float s = 0.0f;
#pragma unroll 8
    for (int zz = 0; zz < KSPLIT; zz++)
        s += Cp[(size_t)zz * DD * DD + i * DD + j];
    G[i * DD + j] = s;
    G[j * DD + i] = s;
}

// ---------------------------------------------------------------------------
// Small GEMM core: 64x64 tile, 256 threads, intra-block split-K
// ---------------------------------------------------------------------------
#define NS_LDA 80
#define NS_AT  (64 * NS_LDA)
#define NS_LDB 144
#define NS_BT  (32 * NS_LDB)
#define NS_STAGE (2 * NS_AT + 2 * NS_BT)
#define NS_SMEM4 (4 * NS_STAGE)

struct NsAcc { float a[2][4][4]; };

__device__ __forceinline__ void ns_tri(int bx, int& ti, int& tj) {
    int t = 0, rem = bx;
    while (rem >= 8 - t) { rem -= 8 - t; t++; }
    ti = t; tj = t + rem;
}

__device__ __forceinline__ void ns_core256(
    const __nv_bfloat16* __restrict__ Ah, const __nv_bfloat16* __restrict__ Al,
    const __nv_bfloat16* __restrict__ Bh, const __nv_bfloat16* __restrict__ Bl,
    int m0, int n0, char* smem, NsAcc& A)
{
    const uint32_t sb = smem_u32(smem);
    const int tid = threadIdx.x;
    const int lane = tid & 31;
    const int wid = tid >> 5;
    const int khalf = wid >> 2;
    const int ltid = tid & 127;
    const int w4 = wid & 3;
    const int wm = (w4 & 1) * 32;
    const int wn = (w4 >> 1) * 32;
    const uint32_t hbase = sb + khalf * (2 * NS_STAGE);

    auto loadStage = [&](int cc, int s) {
        const uint32_t base = hbase + s * NS_STAGE;
        const int k0 = (khalf * 8 + cc) * 32;
#pragma unroll
        for (int rep = 0; rep < 8; rep++) {
            const int idx = rep * 128 + ltid;
            if (idx < 512) {
                const int half = idx >> 8, r = (idx >> 2) & 63, ch = idx & 3;
                const __nv_bfloat16* src =
                    (half ? Al : Ah) + (size_t)(m0 + r) * DD + k0 + ch * 8;
                cpa16(base + half * NS_AT + r * NS_LDA + ch * 16, src);
            } else {
                const int j = idx - 512;
                const int half = j >> 8, r = (j >> 3) & 31, ch = j & 7;
                const __nv_bfloat16* src =
                    (half ? Bl : Bh) + (size_t)(k0 + r) * DD + n0 + ch * 8;
                cpa16(base + 2 * NS_AT + half * NS_BT + r * NS_LDB + ch * 16, src);
            }
        }
        CP_COMMIT();
    };

    loadStage(0, 0);

    for (int cc = 0; cc < 8; cc++) {
        CP_WAIT0();
        __syncthreads();
        if (cc + 1 < 8) loadStage(cc + 1, (cc + 1) & 1);
        const uint32_t st = hbase + (cc & 1) * NS_STAGE;

#pragma unroll
        for (int ks = 0; ks < 2; ks++) {
            uint32_t ah[2][4], al[2][4];
            const uint32_t abase = st + (lane & 15) * NS_LDA + ks * 32 + (lane >> 4) * 16;
#pragma unroll
            for (int mt = 0; mt < 2; mt++) {
                ldsm4(ah[mt], abase + (wm + mt * 16) * NS_LDA);
                ldsm4(al[mt], abase + NS_AT + (wm + mt * 16) * NS_LDA);
            }
            const uint32_t brow = ks * 16 + (lane & 7) + ((lane >> 3) & 1) * 8;
            const uint32_t bbase = st + 2 * NS_AT + brow * NS_LDB + wn * 2 + (lane >> 4) * 16;
            uint32_t bh[2][4], bl[2][4];
            ldsm4t(bh[0], bbase);
            ldsm4t(bh[1], bbase + 32);
            ldsm4t(bl[0], bbase + NS_BT);
            ldsm4t(bl[1], bbase + NS_BT + 32);

#pragma unroll
            for (int mt = 0; mt < 2; mt++)
#pragma unroll
                for (int nt = 0; nt < 4; nt++) {
                    const uint32_t* ph = &bh[nt >> 1][(nt & 1) * 2];
                    const uint32_t* pl = &bl[nt >> 1][(nt & 1) * 2];
                    mma_bf16(A.a[mt][nt], ah[mt], ph);
                    mma_bf16(A.a[mt][nt], ah[mt], pl);
                    mma_bf16(A.a[mt][nt], al[mt], ph);
                }
        }
    }

    __syncthreads();
    float* red = (float*)smem;
    if (khalf == 1) {
        float* dst = red + ((size_t)(w4 * 32 + lane)) * 32;
#pragma unroll
        for (int mt = 0; mt < 2; mt++)
#pragma unroll
            for (int nt = 0; nt < 4; nt++)
#pragma unroll
                for (int q = 0; q < 4; q++)
                    dst[mt * 16 + nt * 4 + q] = A.a[mt][nt][q];
    }
    __syncthreads();
    if (khalf == 0) {
        const float* src = red + ((size_t)(w4 * 32 + lane)) * 32;
#pragma unroll
        for (int mt = 0; mt < 2; mt++)
#pragma unroll
            for (int nt = 0; nt < 4; nt++)
#pragma unroll
                for (int q = 0; q < 4; q++)
                    A.a[mt][nt][q] += src[mt * 16 + nt * 4 + q];
    }
}

// Generic small GEMM: C = scale * (A @ B), grid (8,8), 256 threads.
template<int SCALE, int OF32, int OSPLIT>
__global__ void __launch_bounds__(256)
sg(const __nv_bfloat16* __restrict__ Ah, const __nv_bfloat16* __restrict__ Al,
   const __nv_bfloat16* __restrict__ Bh, const __nv_bfloat16* __restrict__ Bl,
   float* __restrict__ Cf32,
   __nv_bfloat16* __restrict__ Ch, __nv_bfloat16* __restrict__ Cl,
   const float* __restrict__ scalars)
{
    extern __shared__ __align__(16) char smem[];
    const int m0 = blockIdx.y * 64;
    const int n0 = blockIdx.x * 64;

    NsAcc A = {};
    ns_core256(Ah, Al, Bh, Bl, m0, n0, smem, A);

    const int wid = threadIdx.x >> 5;
    if (wid >= 4) return;
    const int lane = threadIdx.x & 31;
    const int wm = (wid & 1) * 32;
    const int wn = (wid >> 1) * 32;

    float sc = 1.0f;
    if (SCALE == 1) sc = scalars[2] * scalars[2];
    if (SCALE == 2) sc = scalars[2];
    const int g = lane >> 2, t4 = lane & 3;
#pragma unroll
    for (int mt = 0; mt < 2; mt++) {
        const int r0 = m0 + wm + mt * 16 + g;
#pragma unroll
        for (int nt = 0; nt < 4; nt++) {
            const int cc = n0 + wn + nt * 8 + 2 * t4;
#pragma unroll
            for (int half = 0; half < 2; half++) {
                const size_t idx = (size_t)(r0 + half * 8) * DD + cc;
                const float v0 = A.a[mt][nt][half * 2 + 0] * sc;
                const float v1 = A.a[mt][nt][half * 2 + 1] * sc;
                if (OF32) *(float2*)&Cf32[idx] = make_float2(v0, v1);
                if (OSPLIT) store_split2(Ch, Cl, idx, v0, v1);
            }
        }
    }
}

// grid (36,1,2): z=0 -> T1 = P @ S ; z=1 -> T2 = P @ P
__global__ void __launch_bounds__(256)
ns_pair(const __nv_bfloat16* __restrict__ Pah, const __nv_bfloat16* __restrict__ Pal,
        const __nv_bfloat16* __restrict__ Sh,  const __nv_bfloat16* __restrict__ Sl,
        __nv_bfloat16* __restrict__ T1h, __nv_bfloat16* __restrict__ T1l,
        __nv_bfloat16* __restrict__ T2h, __nv_bfloat16* __restrict__ T2l)
{
    extern __shared__ __align__(16) char smem[];
    int ti, tj;
    ns_tri(blockIdx.x, ti, tj);
    const int m0 = ti * 64;
    const int n0 = tj * 64;

    NsAcc A = {};
    const __nv_bfloat16* Bh = blockIdx.z ? Pah : Sh;
    const __nv_bfloat16* Bl = blockIdx.z ? Pal : Sl;
    ns_core256(Pah, Pal, Bh, Bl, m0, n0, smem, A);

    const int wid = threadIdx.x >> 5;
    if (wid >= 4) return;
    const int lane = threadIdx.x & 31;
    const int wm = (wid & 1) * 32;
    const int wn = (wid >> 1) * 32;

    __nv_bfloat16* Oh = blockIdx.z ? T2h : T1h;
    __nv_bfloat16* Ol = blockIdx.z ? T2l : T1l;
    const int g = lane >> 2, t4 = lane & 3;
    const bool mir = (ti != tj);
#pragma unroll
    for (int mt = 0; mt < 2; mt++) {
        const int r0 = m0 + wm + mt * 16 + g;
#pragma unroll
        for (int nt = 0; nt < 4; nt++) {
            const int cc = n0 + wn + nt * 8 + 2 * t4;
            const float v0 = A.a[mt][nt][0], v1 = A.a[mt][nt][1];
            const float v2 = A.a[mt][nt][2], v3 = A.a[mt][nt][3];
            store_split2(Oh, Ol, (size_t)r0 * DD + cc, v0, v1);
            store_split2(Oh, Ol, (size_t)(r0 + 8) * DD + cc, v2, v3);
            if (mir) {
                store_split1(Oh, Ol, (size_t)cc * DD + r0, v0);
                store_split1(Oh, Ol, (size_t)(cc + 1) * DD + r0, v1);
                store_split1(Oh, Ol, (size_t)cc * DD + r0 + 8, v2);
                store_split1(Oh, Ol, (size_t)(cc + 1) * DD + r0 + 8, v3);
            }
        }
    }
}

// grid (36): Pb = 1.5*Pold - 0.5*(T2 @ T1)
__global__ void __launch_bounds__(256)
ns_update(const __nv_bfloat16* __restrict__ T2h, const __nv_bfloat16* __restrict__ T2l,
          const __nv_bfloat16* __restrict__ T1h, const __nv_bfloat16* __restrict__ T1l,
          const float* __restrict__ Pold, float* __restrict__ Pnew,
          __nv_bfloat16* __restrict__ Pnh, __nv_bfloat16* __restrict__ Pnl)
{
    extern __shared__ __align__(16) char smem[];
    int ti, tj;
    ns_tri(blockIdx.x, ti, tj);
    const int m0 = ti * 64;
    const int n0 = tj * 64;

    NsAcc A = {};
    ns_core256(T2h, T2l, T1h, T1l, m0, n0, smem, A);

    const int wid = threadIdx.x >> 5;
    if (wid >= 4) return;
    const int lane = threadIdx.x & 31;
    const int wm = (wid & 1) * 32;
    const int wn = (wid >> 1) * 32;

    const int g = lane >> 2, t4 = lane & 3;
    const bool mir = (ti != tj);
#pragma unroll
    for (int mt = 0; mt < 2; mt++) {
        const int r0 = m0 + wm + mt * 16 + g;
#pragma unroll
        for (int nt = 0; nt < 4; nt++) {
            const int cc = n0 + wn + nt * 8 + 2 * t4;
#pragma unroll
            for (int half = 0; half < 2; half++) {
                const int r = r0 + half * 8;
                const size_t idx = (size_t)r * DD + cc;
                const float2 po = *(const float2*)&Pold[idx];
                const float v0 = 1.5f * po.x - 0.5f * A.a[mt][nt][half * 2 + 0];
                const float v1 = 1.5f * po.y - 0.5f * A.a[mt][nt][half * 2 + 1];
                *(float2*)&Pnew[idx] = make_float2(v0, v1);
                store_split2(Pnh, Pnl, idx, v0, v1);
                if (mir) {
                    Pnew[(size_t)cc * DD + r] = v0;
                    Pnew[(size_t)(cc + 1) * DD + r] = v1;
                    store_split1(Pnh, Pnl, (size_t)cc * DD + r, v0);
                    store_split1(Pnh, Pnl, (size_t)(cc + 1) * DD + r, v1);
                }
            }
        }
    }
}

// ---------------------------------------------------------------------------
// trace / fused S+P1 / vector helpers
// ---------------------------------------------------------------------------
__global__ void mean_finalize(const float* __restrict__ colp, float* __restrict__ mean)
{
    __shared__ float sm[128];
    const int j = blockIdx.x;
    const int t = threadIdx.x;
    const float4 v = *(const float4*)(colp + (size_t)j * 512 + t * 4);
    sm[t] = v.x + v.y + v.z + v.w;
    __syncthreads();
    for (int s = 64; s > 0; s >>= 1) {
        if (t < s) sm[t] += sm[t + s];
        __syncthreads();
    }
    if (t == 0) mean[j] = sm[0] * (1.0f / (float)NROWS);
}

__global__ void trace_kernel(const float* __restrict__ G,
                             const float* __restrict__ mH,
                             float* __restrict__ scalars)
{
    __shared__ float sm[512];
    const int i = threadIdx.x;
    const float m = mH ? mH[i] : 0.0f;
    sm[i] = G[i * DD + i] * (1.0f / (float)NROWS) - m * m + INV_TEMP;
    __syncthreads();
    for (int s = 256; s > 0; s >>= 1) {
        if (i < s) sm[i] += sm[i + s];
        __syncthreads();
    }
    if (i == 0) {
        const float tr = sm[0];
        scalars[0] = tr;
        scalars[1] = 1.0f / tr;
        scalars[2] = rsqrtf(tr);
    }
}

__global__ void s_kernel(const float* __restrict__ G,
                         const float* __restrict__ mH,
                         const float* __restrict__ scalars,
                         __nv_bfloat16* __restrict__ Sh, __nv_bfloat16* __restrict__ Sl,
                         float* __restrict__ P,
                         __nv_bfloat16* __restrict__ Ph, __nv_bfloat16* __restrict__ Pl)
{
    const int i = blockIdx.x, j = threadIdx.x;
    const float invtr = scalars[1];
    float v = G[i * DD + j] * (1.0f / (float)NROWS);
    if (mH) v -= mH[i] * mH[j];
    if (i == j) v += INV_TEMP;
    v *= invtr;
    split1(v, Sh[i * DD + j], Sl[i * DD + j]);
    const float p = ((i == j) ? 1.5f : 0.0f) - 0.5f * v;
    P[i * DD + j] = p;
    split1(p, Ph[i * DD + j], Pl[i * DD + j]);
}

__global__ void meanW(const float* __restrict__ mp, const float* __restrict__ W,
                      float* __restrict__ mH)
{
    const int j = blockIdx.x * 128 + threadIdx.x;
    float s = 0.0f;
#pragma unroll 8
    for (int k = 0; k < DD; k++)
        s += mp[k] * W[(size_t)k * DD + j];
    mH[j] = s;
}

// b0 = -s2 * mH @ P
__global__ void b0_kernel(const float* __restrict__ mH, const float* __restrict__ P,
                          const float* __restrict__ scalars, float* __restrict__ b)
{
    const int j = blockIdx.x * 128 + threadIdx.x;
    float s = 0.0f;
#pragma unroll 8
    for (int k = 0; k < DD; k++)
        s += mH[k] * P[(size_t)k * DD + j];
    b[j] = -s * scalars[2];
}

// bnew = bold @ Weff  (Weff from splits, hi+lo)
__global__ void bcomp(const float* __restrict__ bold,
                      const __nv_bfloat16* __restrict__ Weh,
                      const __nv_bfloat16* __restrict__ Wel,
                      float* __restrict__ bnew)
{
    const int j = blockIdx.x * 128 + threadIdx.x;
    float s = 0.0f;
#pragma unroll 8
    for (int k = 0; k < DD; k++)
        s += bold[k] * (__bfloat162float(Weh[(size_t)k * DD + j]) +
                        __bfloat162float(Wel[(size_t)k * DD + j]));
    bnew[j] = s;
}

// ---------------------------------------------------------------------------
// Host orchestration: affine collapse + fork/join streams
// ---------------------------------------------------------------------------
extern "C" void kernel_launch(void* const* d_in, const int* in_sizes, int n_in,
                              void* d_out, int out_size)
{
    (void)in_sizes; (void)n_in; (void)out_size;
    const float* x = (const float*)d_in[0];
    const float* Ws[3] = {(const float*)d_in[1], (const float*)d_in[2],
                          (const float*)d_in[3]};
    float* out = (float*)d_out;

    cudaFuncSetAttribute(hgemm_aff, cudaFuncAttributeMaxDynamicSharedMemorySize, G1_SMEM);
    cudaFuncSetAttribute(hcov, cudaFuncAttributeMaxDynamicSharedMemorySize, CV_SMEM);
    cudaFuncSetAttribute(ns_pair,   cudaFuncAttributeMaxDynamicSharedMemorySize, NS_SMEM4);
    cudaFuncSetAttribute(ns_update, cudaFuncAttributeMaxDynamicSharedMemorySize, NS_SMEM4);
    cudaFuncSetAttribute((const void*)sg<0, 0, 1>, cudaFuncAttributeMaxDynamicSharedMemorySize, NS_SMEM4);
    cudaFuncSetAttribute((const void*)sg<0, 1, 0>, cudaFuncAttributeMaxDynamicSharedMemorySize, NS_SMEM4);
    cudaFuncSetAttribute((const void*)sg<1, 0, 1>, cudaFuncAttributeMaxDynamicSharedMemorySize, NS_SMEM4);
    cudaFuncSetAttribute((const void*)sg<2, 0, 1>, cudaFuncAttributeMaxDynamicSharedMemorySize, NS_SMEM4);

    float *covp, *G, *P, *Pn, *colp, *mean, *mH, *bvec, *scal;
    __nv_bfloat16 *Ah, *Al, *Wh, *Wl, *Sh, *Sl;
    __nv_bfloat16 *Pah, *Pal, *Pbh, *Pbl, *T1h, *T1l, *T2h, *T2l;
    __nv_bfloat16 *Uh, *Ul, *Weh, *Wel, *GOh, *GOl, *Gch, *Gcl;
    __nv_bfloat16 *Mh[3], *Ml[3];
    cudaGetSymbolAddress((void**)&covp, g_covp);
    cudaGetSymbolAddress((void**)&G,    g_G);
    cudaGetSymbolAddress((void**)&P,    g_P);
    cudaGetSymbolAddress((void**)&Pn,   g_Pn);
    cudaGetSymbolAddress((void**)&colp, g_colp);
    cudaGetSymbolAddress((void**)&mean, g_mean);
    cudaGetSymbolAddress((void**)&mH,   g_mH);
    cudaGetSymbolAddress((void**)&bvec, g_bvec);
    cudaGetSymbolAddress((void**)&scal, g_scalars);
    cudaGetSymbolAddress((void**)&Ah,   g_Ah);
    cudaGetSymbolAddress((void**)&Al,   g_Al);
    cudaGetSymbolAddress((void**)&Wh,   g_Wh);
    cudaGetSymbolAddress((void**)&Wl,   g_Wl);
    cudaGetSymbolAddress((void**)&Sh,   g_Sh);
    cudaGetSymbolAddress((void**)&Sl,   g_Sl);
    cudaGetSymbolAddress((void**)&Pah,  g_Pah);
    cudaGetSymbolAddress((void**)&Pal,  g_Pal);
    cudaGetSymbolAddress((void**)&Pbh,  g_Pbh);
    cudaGetSymbolAddress((void**)&Pbl,  g_Pbl);
    cudaGetSymbolAddress((void**)&T1h,  g_T1h);
    cudaGetSymbolAddress((void**)&T1l,  g_T1l);
    cudaGetSymbolAddress((void**)&T2h,  g_T2h);
    cudaGetSymbolAddress((void**)&T2l,  g_T2l);
    cudaGetSymbolAddress((void**)&Uh,   g_Uh);
    cudaGetSymbolAddress((void**)&Ul,   g_Ul);
    cudaGetSymbolAddress((void**)&Weh,  g_Weh);
    cudaGetSymbolAddress((void**)&Wel,  g_Wel);
    cudaGetSymbolAddress((void**)&GOh,  g_GOh);
    cudaGetSymbolAddress((void**)&GOl,  g_GOl);
    cudaGetSymbolAddress((void**)&Gch,  g_Gch);
    cudaGetSymbolAddress((void**)&Gcl,  g_Gcl);
    cudaGetSymbolAddress((void**)&Mh[0], g_M0h);
    cudaGetSymbolAddress((void**)&Ml[0], g_M0l);
    cudaGetSymbolAddress((void**)&Mh[1], g_M1h);
    cudaGetSymbolAddress((void**)&Ml[1], g_M1l);
    cudaGetSymbolAddress((void**)&Mh[2], g_M2h);
    cudaGetSymbolAddress((void**)&Ml[2], g_M2l);

    // second stream + events (host-side resources; created per call, <=3 calls)
    cudaStream_t s2;
    cudaStreamCreateWithFlags(&s2, cudaStreamNonBlocking);
    cudaEvent_t evM[3], evJoin;
    for (int i = 0; i < 3; i++)
        cudaEventCreateWithFlags(&evM[i], cudaEventDisableTiming);
    cudaEventCreateWithFlags(&evJoin, cudaEventDisableTiming);

    const int wBlocks = (DD * DD) / (256 * 4);

    // ---- preprocessing on default stream ----
    split_f32<<<(NROWS * DD) / (256 * 4), 256>>>(x, Ah, Al);
    colsum_x<<<dim3(4, 512), 128>>>(x, colp);
    mean_finalize<<<512, 128>>>(colp, mean);
    hcov<<<dim3(10, 1, KSPLIT), 256, CV_SMEM>>>(Ah, Al, covp);
    reduce_cov_sym<<<512, 512>>>(covp, G);
    gsplit<<<512, 512>>>(G, GOh, GOl);

    // ---- per-layer small chains on default stream; big GEMMs forked to s2 ----
    for (int l = 0; l < 3; l++) {
        const float* W = Ws[l];
        const int first = (l == 0);
        const int last  = (l == 2);

        split_f32<<<wBlocks, 256>>>(W, Wh, Wl);
        if (first) meanW<<<4, 128>>>(mean, W, mH);
        const float* mHp = first ? mH : nullptr;

        tsplit<<<dim3(16, 16), dim3(32, 32)>>>(W, Uh, Ul);
        sg<0, 0, 1><<<dim3(8, 8), 256, NS_SMEM4>>>(Uh, Ul, GOh, GOl,
                                                   nullptr, T1h, T1l, scal);
        sg<0, 1, 0><<<dim3(8, 8), 256, NS_SMEM4>>>(T1h, T1l, Wh, Wl,
                                                   G, nullptr, nullptr, scal);
        trace_kernel<<<1, 512>>>(G, mHp, scal);
        s_kernel<<<512, 512>>>(G, mHp, scal, Sh, Sl, P, Pah, Pal);

        float* Pf = P; float* Pg = Pn;
        __nv_bfloat16 *ah = Pah, *al = Pal, *bh = Pbh, *bl = Pbl;
        for (int t = 1; t < NS_ITERS; t++) {
            ns_pair<<<dim3(36, 1, 2), 256, NS_SMEM4>>>(ah, al, Sh, Sl,
                                                       T1h, T1l, T2h, T2l);
            ns_update<<<dim3(36), 256, NS_SMEM4>>>(T2h, T2l, T1h, T1l,
                                                   Pf, Pg, bh, bl);
            { float* t0 = Pf; Pf = Pg; Pg = t0; }
            { __nv_bfloat16* t1 = ah; ah = bh; bh = t1; }
            { __nv_bfloat16* t2 = al; al = bl; bl = t2; }
        }

        if (!last) {
            gc_split<<<512, 512>>>(G, mHp, Gch, Gcl);
            sg<0, 0, 1><<<dim3(8, 8), 256, NS_SMEM4>>>(ah, al, Gch, Gcl,
                                                       nullptr, T1h, T1l, scal);
            sg<1, 0, 1><<<dim3(8, 8), 256, NS_SMEM4>>>(T1h, T1l, ah, al,
                                                       nullptr, GOh, GOl, scal);
        }

        // M_l and b_l
        if (first) {
            sg<2, 0, 1><<<dim3(8, 8), 256, NS_SMEM4>>>(Wh, Wl, ah, al,
                                                       nullptr, Mh[0], Ml[0], scal);
            b0_kernel<<<4, 128>>>(mH, Pf, scal, bvec);
        } else {
            sg<2, 0, 1><<<dim3(8, 8), 256, NS_SMEM4>>>(Wh, Wl, ah, al,
                                                       nullptr, Weh, Wel, scal);
            sg<0, 0, 1><<<dim3(8, 8), 256, NS_SMEM4>>>(Mh[l - 1], Ml[l - 1], Weh, Wel,
                                                       nullptr, Mh[l], Ml[l], scal);
            bcomp<<<4, 128>>>(bvec + (l - 1) * DD, Weh, Wel, bvec + l * DD);
        }

        // fork: big affine GEMM for this layer on s2
        cudaEventRecord(evM[l], 0);
        cudaStreamWaitEvent(s2, evM[l], 0);
        hgemm_aff<<<dim3(4, 512), 256, G1_SMEM, s2>>>(
            Ah, Al, Mh[l], Ml[l], out + (size_t)l * NROWS * DD, bvec + l * DD);
    }

    // join s2 back into the default stream
    cudaEventRecord(evJoin, s2);
    cudaStreamWaitEvent(0, evJoin, 0);
}